// round 6
// baseline (speedup 1.0000x reference)
#include <cuda_runtime.h>
#include <math.h>
#include <stdint.h>

#define BB 8
#define TT 4096
#define DD 256
#define MM 1024
#define CTX 7
#define LL (TT - 1 + CTX)      /* 4102 */
#define LLP 4104               /* padded stride, 16B-aligned rows */
#define NN (BB*TT)             /* 32768 */
#define QSIZE (NN*DD)          /* 8388608 */

// ---------------- scratch (static device globals; no runtime alloc) ----------
__device__ __align__(16) float g_xt[BB*DD*TT];          // x transposed [b][d][t]
__device__ __align__(16) float g_noisy[BB*DD*LLP];      // noisy ctx input, exact fp32
__device__ __align__(16) float g_wcsh[DD*DD*CTX];       // w_ctx exact, A-frag shuffled
__device__ __align__(16) float g_w2sh[DD*DD];           // w_f2[:,256:] exact, A-frag shuffled
__device__ __align__(16) float g_ctxout[BB*DD*TT];      // conv output [b][o][t]
__device__ __align__(16) float g_cur[(size_t)NN*DD];    // fuse1 out [n][c], exact fp32
__device__ __align__(16) float g_G[(size_t)NN*MM];      // cur . E^T   [n][m]
__device__ __align__(16) float g_ET[DD*MM];             // E transposed [c][m]
__device__ __align__(16) float g_w1T[2*DD*DD];          // w_f1 transposed [k][o]
__device__ __align__(16) float g_w2T[2*DD*DD];          // w_f2 transposed [k][o]
__device__ __align__(16) float g_W2E[MM*DD];            // E . w_f2a^T  [m][o]
__device__ __align__(16) float g_esq[MM];
__device__ float g_scale[BB];
__device__ int   g_idx[NN];
__device__ unsigned int g_hist[MM];
__device__ float g_avgp[MM];

__device__ __forceinline__ float tf32_hi(float v) {
    uint32_t b;
    asm("cvt.rna.tf32.f32 %0, %1;" : "=r"(b) : "f"(v));
    return __uint_as_float(b);
}

#define MMA8(d, a0,a1,a2,a3, b0,b1) \
    asm volatile("mma.sync.aligned.m16n8k8.row.col.f32.tf32.tf32.f32 " \
        "{%0,%1,%2,%3}, {%4,%5,%6,%7}, {%8,%9}, {%0,%1,%2,%3};" \
        : "+f"((d)[0]), "+f"((d)[1]), "+f"((d)[2]), "+f"((d)[3]) \
        : "r"(a0), "r"(a1), "r"(a2), "r"(a3), "r"(b0), "r"(b1))

// split exact -> (hi, lo) tf32 pair in registers
#define SPLIT2(vh, vl, v) do { float _h = tf32_hi(v); (vh) = __float_as_uint(_h); \
                               (vl) = __float_as_uint(tf32_hi((v) - _h)); } while (0)

// ---------------- small utility kernels -------------------------------------
__global__ void k_zero() {
    int i = blockIdx.x*blockDim.x + threadIdx.x;
    if (i < MM) { g_hist[i] = 0u; g_avgp[i] = 0.f; }
}

// dst[c][r] = src[r][c];  which: 0 -> g_ET, 1 -> g_w1T, 2 -> g_w2T
__global__ void k_transp(const float* __restrict__ src, int rows, int cols, int which) {
    __shared__ float s[32][33];
    float* dst = (which == 0) ? g_ET : (which == 1) ? g_w1T : g_w2T;
    int c0 = blockIdx.x*32, r0 = blockIdx.y*32;
    int tx = threadIdx.x, ty = threadIdx.y;
    #pragma unroll
    for (int j = 0; j < 4; j++) {
        int r = r0 + ty + j*8, c = c0 + tx;
        s[ty + j*8][tx] = (r < rows && c < cols) ? src[(size_t)r*cols + c] : 0.f;
    }
    __syncthreads();
    #pragma unroll
    for (int j = 0; j < 4; j++) {
        int c = c0 + ty + j*8, r = r0 + tx;
        if (c < cols && r < rows) dst[(size_t)c*rows + r] = s[tx][ty + j*8];
    }
}

__global__ void k_esq(const float* __restrict__ E) {
    int warp = threadIdx.x >> 5, lane = threadIdx.x & 31;
    int m = blockIdx.x*8 + warp;
    const float* row = E + (size_t)m*DD;
    float s = 0.f;
    for (int c = lane; c < DD; c += 32) { float v = row[c]; s += v*v; }
    #pragma unroll
    for (int o = 16; o > 0; o >>= 1) s += __shfl_down_sync(0xffffffffu, s, o);
    if (lane == 0) g_esq[m] = s;
}

// w_ctx -> A-fragment-shuffled exact layout
// dest[((ic*7+kk)*16 + otile)*128 + lane*4 + reg]
__global__ void k_shufw(const float* __restrict__ wctx) {
    int idx = blockIdx.x*256 + threadIdx.x;       // grid 1792
    int o = idx / (DD*CTX);
    int rem = idx - o*(DD*CTX);
    int i = rem / CTX, kk = rem - i*CTX;
    int ic = i >> 3, il = i & 7;
    int otile = o >> 4, oloc = o & 15;
    int lane = (oloc & 7)*4 + (il & 3);
    int reg = (oloc >> 3) + 2*(il >> 2);
    g_wcsh[((ic*7 + kk)*16 + otile)*128 + lane*4 + reg] = wctx[idx];
}

// w_f2[:,256:512] -> A-fragment-shuffled exact layout
__global__ void k_shufw2(const float* __restrict__ wf2) {
    int idx = blockIdx.x*256 + threadIdx.x;       // grid 256
    int o = idx >> 8, k = idx & 255;
    int ic = k >> 3, il = k & 7;
    int otile = o >> 4, oloc = o & 15;
    int lane = (oloc & 7)*4 + (il & 3);
    int reg = (oloc >> 3) + 2*(il >> 2);
    g_w2sh[(ic*16 + otile)*128 + lane*4 + reg] = wf2[o*2*DD + DD + k];
}

// scale[b] = 0.5 * sqrt(mean(ctx_in^2)) * 0.5^(epo/10)
__global__ void k_scale(const float* __restrict__ x, const int* __restrict__ epo_p) {
    int b = blockIdx.x;
    const float* xb = x + (size_t)b*TT*DD;
    float s = 0.f;
    int tot = (TT-1)*DD;
    for (int i = threadIdx.x; i < tot; i += blockDim.x) { float v = xb[i]; s += v*v; }
    __shared__ float sm[8];
    #pragma unroll
    for (int o = 16; o > 0; o >>= 1) s += __shfl_down_sync(0xffffffffu, s, o);
    if ((threadIdx.x & 31) == 0) sm[threadIdx.x >> 5] = s;
    __syncthreads();
    if (threadIdx.x == 0) {
        float t = 0.f;
        for (int w = 0; w < 8; w++) t += sm[w];
        int iv = epo_p[0];
        float ef = (iv >= 0 && iv < 100000) ? (float)iv : __int_as_float(iv);
        float sc = sqrtf(t / (float)(DD*LL));
        g_scale[b] = 0.5f * sc * exp2f(-ef * 0.1f);
    }
}

// g_xt[b][d][t] = x[b][t][d]
__global__ void k_xt(const float* __restrict__ x) {
    __shared__ float s[32][33];
    int b = blockIdx.z, t0 = blockIdx.x*32, d0 = blockIdx.y*32;
    int tx = threadIdx.x, ty = threadIdx.y;
    #pragma unroll
    for (int j = 0; j < 4; j++) {
        int t = t0 + ty + j*8;
        s[ty + j*8][tx] = x[((size_t)b*TT + t)*DD + d0 + tx];
    }
    __syncthreads();
    #pragma unroll
    for (int j = 0; j < 4; j++) {
        int d = d0 + ty + j*8;
        g_xt[((size_t)b*DD + d)*TT + t0 + tx] = s[tx][ty + j*8];
    }
}

// noisy[b][i][l] = pad(x) + coef*noise, exact fp32 (stride LLP)
__global__ void k_noisy(const float* __restrict__ x, const float* __restrict__ noise) {
    __shared__ float s[32][33];
    int b = blockIdx.z, l0 = blockIdx.x*32, i0 = blockIdx.y*32;
    int tx = threadIdx.x, ty = threadIdx.y;
    float coef = g_scale[b];
    #pragma unroll
    for (int j = 0; j < 4; j++) {
        int row = ty + j*8;
        int t = l0 + row - CTX;
        float v = (t >= 0 && t < TT-1) ? x[((size_t)b*TT + t)*DD + i0 + tx] : 0.f;
        s[row][tx] = v;
    }
    __syncthreads();
    #pragma unroll
    for (int j = 0; j < 4; j++) {
        int i = i0 + ty + j*8, l = l0 + tx;
        if (l < LL)
            g_noisy[((size_t)b*DD + i)*LLP + l] =
                s[tx][ty + j*8] + coef * noise[((size_t)b*DD + i)*LL + l];
    }
}

// ---------------- conv on tensor cores (3xTF32, split-on-load) ---------------
#define CV_STG 4672  /* floats per stage: X 1088 + W 3584 */
#define CV_SMEMB (2*CV_STG*4)

__global__ void __launch_bounds__(256, 2) k_conv_tc(int obase) {
    extern __shared__ float cs[];
    int tid = threadIdx.x, lane = tid & 31, warp = tid >> 5;
    int warpM = warp >> 2, warpN = warp & 3;
    int t0 = blockIdx.x*128, o0 = obase + blockIdx.y*64, b = blockIdx.z;
    int ot0 = o0 >> 4;

    uint32_t sbase;
    asm("{ .reg .u64 t; cvta.to.shared.u64 t, %1; cvt.u32.u64 %0, t; }" : "=r"(sbase) : "l"(cs));

    auto issue = [&](int ic, int s) {
        const float* xp = g_noisy + ((size_t)(b*DD + ic*8))*LLP + t0;
        uint32_t xd = sbase + (uint32_t)((s*CV_STG)*4);
        for (int idx = tid; idx < 272; idx += 256) {
            int row = idx / 34, q = idx - row*34;
            asm volatile("cp.async.cg.shared.global [%0], [%1], 16;"
                :: "r"(xd + (uint32_t)((row*136 + q*4)*4)), "l"(xp + (size_t)row*LLP + q*4));
        }
        const float* wp = g_wcsh + ((size_t)(ic*7)*16 + ot0)*128;
        uint32_t wd = sbase + (uint32_t)((s*CV_STG + 1088)*4);
        for (int idx = tid; idx < 896; idx += 256) {
            int kk = idx >> 7, q = idx & 127;
            asm volatile("cp.async.cg.shared.global [%0], [%1], 16;"
                :: "r"(wd + (uint32_t)((kk*512 + q*4)*4)), "l"(wp + kk*2048 + q*4));
        }
        asm volatile("cp.async.commit_group;");
    };

    float c[2][4][4] = {};
    issue(0, 0);
    issue(1, 1);

    for (int ic = 0; ic < 32; ic++) {
        int s = ic & 1;
        if (ic < 31) { asm volatile("cp.async.wait_group 1;"); }
        else         { asm volatile("cp.async.wait_group 0;"); }
        __syncthreads();
        const float* XE = cs + s*CV_STG;
        const float* WE = XE + 1088;
        int i0v = lane & 3, trow = lane >> 2;

        #pragma unroll
        for (int kk = 0; kk < 7; kk++) {
            uint32_t ah[2][4], al[2][4];
            #pragma unroll
            for (int mf = 0; mf < 2; mf++) {
                float4 vw = *(const float4*)&WE[kk*512 + (warpM*2 + mf)*128 + lane*4];
                SPLIT2(ah[mf][0], al[mf][0], vw.x);
                SPLIT2(ah[mf][1], al[mf][1], vw.y);
                SPLIT2(ah[mf][2], al[mf][2], vw.z);
                SPLIT2(ah[mf][3], al[mf][3], vw.w);
            }
            uint32_t bh[4][2], bl[4][2];
            #pragma unroll
            for (int nf = 0; nf < 4; nf++) {
                int toff = warpN*32 + nf*8 + trow + kk;
                float b0 = XE[i0v*136 + toff];
                float b1 = XE[(i0v + 4)*136 + toff];
                SPLIT2(bh[nf][0], bl[nf][0], b0);
                SPLIT2(bh[nf][1], bl[nf][1], b1);
            }
            #pragma unroll
            for (int mf = 0; mf < 2; mf++) {
                #pragma unroll
                for (int nf = 0; nf < 4; nf++) {
                    MMA8(c[mf][nf], ah[mf][0], ah[mf][1], ah[mf][2], ah[mf][3], bh[nf][0], bh[nf][1]);
                    MMA8(c[mf][nf], ah[mf][0], ah[mf][1], ah[mf][2], ah[mf][3], bl[nf][0], bl[nf][1]);
                    MMA8(c[mf][nf], al[mf][0], al[mf][1], al[mf][2], al[mf][3], bh[nf][0], bh[nf][1]);
                }
            }
        }
        __syncthreads();
        if (ic + 2 < 32) issue(ic + 2, s);
    }

    #pragma unroll
    for (int mf = 0; mf < 2; mf++) {
        int r = o0 + warpM*32 + mf*16 + (lane >> 2);
        #pragma unroll
        for (int nf = 0; nf < 4; nf++) {
            int tg = t0 + warpN*32 + nf*8 + (lane & 3)*2;
            *(float2*)&g_ctxout[((size_t)b*DD + r)*TT + tg]     = make_float2(c[mf][nf][0], c[mf][nf][1]);
            *(float2*)&g_ctxout[((size_t)b*DD + r + 8)*TT + tg] = make_float2(c[mf][nf][2], c[mf][nf][3]);
        }
    }
}

// ---------------- fuse1 (SIMT, exact): cur[n][o] = prelu(...) ----------------
__global__ void __launch_bounds__(256) k_f1(const float* __restrict__ a1p) {
    __shared__ float sA[16][68];
    __shared__ float sB[16][68];
    int b = blockIdx.z, t0 = blockIdx.x*64, o0 = blockIdx.y*64;
    int tid = threadIdx.x;
    int tx = tid & 15, ty = tid >> 4;
    int kl = tid >> 4, nl4 = (tid & 15)*4;
    float acc[4][4] = {};
    for (int kc = 0; kc < 2*DD; kc += 16) {
        const float* Ap = (kc < DD) ? (g_xt + ((size_t)b*DD + kc)*TT)
                                    : (g_ctxout + ((size_t)b*DD + (kc - DD))*TT);
        *(float4*)&sA[kl][nl4] = *(const float4*)(Ap + (size_t)kl*TT + t0 + nl4);
        *(float4*)&sB[kl][nl4] = *(const float4*)(g_w1T + (size_t)(kc + kl)*DD + o0 + nl4);
        __syncthreads();
        #pragma unroll
        for (int k = 0; k < 16; k++) {
            float4 av = *(const float4*)&sA[k][4*tx];
            float4 bv = *(const float4*)&sB[k][4*ty];
            float ar[4] = {av.x, av.y, av.z, av.w};
            float br[4] = {bv.x, bv.y, bv.z, bv.w};
            #pragma unroll
            for (int a = 0; a < 4; a++)
                #pragma unroll
                for (int c = 0; c < 4; c++)
                    acc[a][c] += br[a] * ar[c];
        }
        __syncthreads();
    }
    float a1 = *a1p;
    #pragma unroll
    for (int c = 0; c < 4; c++) {
        size_t n = (size_t)b*TT + t0 + 4*tx + c;
        float4 ve;
        float u;
        u = acc[0][c]; ve.x = (u >= 0.f) ? u : a1*u;
        u = acc[1][c]; ve.y = (u >= 0.f) ? u : a1*u;
        u = acc[2][c]; ve.z = (u >= 0.f) ? u : a1*u;
        u = acc[3][c]; ve.w = (u >= 0.f) ? u : a1*u;
        *(float4*)&g_cur[n*DD + o0 + 4*ty] = ve;
    }
}

// ---------------- W2E GEMM (small): C[m][o] = sum_c ET[c][m] w2T[c][o]
__global__ void __launch_bounds__(256) k_gemm_w2e() {
    __shared__ float sA[16][68];
    __shared__ float sB[16][68];
    int i0 = blockIdx.x*64, j0 = blockIdx.y*64;
    int tid = threadIdx.x;
    int tx = tid & 15, ty = tid >> 4;
    int kl = tid >> 4, nl4 = (tid & 15)*4;
    float acc[4][4] = {};
    for (int kc = 0; kc < DD; kc += 16) {
        *(float4*)&sA[kl][nl4] = *(const float4*)(g_ET  + (size_t)(kc + kl)*MM + i0 + nl4);
        *(float4*)&sB[kl][nl4] = *(const float4*)(g_w2T + (size_t)(kc + kl)*DD + j0 + nl4);
        __syncthreads();
        #pragma unroll
        for (int k = 0; k < 16; k++) {
            float4 av = *(const float4*)&sA[k][4*tx];
            float4 bv = *(const float4*)&sB[k][4*ty];
            float ar[4] = {av.x, av.y, av.z, av.w};
            float br[4] = {bv.x, bv.y, bv.z, bv.w};
            #pragma unroll
            for (int a = 0; a < 4; a++)
                #pragma unroll
                for (int c = 0; c < 4; c++)
                    acc[a][c] += br[a] * ar[c];
        }
        __syncthreads();
    }
    #pragma unroll
    for (int c = 0; c < 4; c++) {
        int i = i0 + 4*tx + c;
        float4 v = make_float4(acc[0][c], acc[1][c], acc[2][c], acc[3][c]);
        *(float4*)&g_W2E[(size_t)i*DD + j0 + 4*ty] = v;
    }
}

// ---------------- dist GEMM via mma.sync tf32 (3xTF32, split-on-load) --------
#define D_ARRF 4096
#define D_SMEMB (2*2*D_ARRF*4)   /* 65536 */

__device__ __forceinline__ int swz(int r, int c) {
    return r*32 + ((((c >> 2) ^ (r & 7)) << 2) | (c & 3));
}

__global__ void __launch_bounds__(256, 2) k_dist_mma(const float* __restrict__ emb) {
    extern __shared__ float sm[];
    int tid = threadIdx.x, lane = tid & 31, warp = tid >> 5;
    int warpM = warp >> 2, warpN = warp & 3;
    int n0 = blockIdx.x*128, m0 = blockIdx.y*128;

    uint32_t sbase;
    asm("{ .reg .u64 t; cvta.to.shared.u64 t, %1; cvt.u32.u64 %0, t; }" : "=r"(sbase) : "l"(sm));

    const float* srcs[2] = { g_cur + (size_t)n0*DD, emb + (size_t)m0*DD };
    int lr = tid >> 3, c4 = tid & 7;

    auto issue = [&](int kc, int s) {
        #pragma unroll
        for (int a = 0; a < 2; a++) {
            const float* srcb = srcs[a] + kc + c4*4;
            uint32_t dstb = sbase + (uint32_t)(((s*2 + a)*D_ARRF)*4);
            #pragma unroll
            for (int j = 0; j < 4; j++) {
                int row = lr + 32*j;
                uint32_t dst = dstb + (uint32_t)((row*32 + ((c4 ^ (row & 7)) << 2))*4);
                asm volatile("cp.async.cg.shared.global [%0], [%1], 16;"
                             :: "r"(dst), "l"(srcb + (size_t)row*DD));
            }
        }
        asm volatile("cp.async.commit_group;");
    };

    float c[4][4][4] = {};
    issue(0, 0);

    for (int it = 0; it < 8; it++) {
        int s = it & 1;
        if (it + 1 < 8) issue((it + 1)*32, s ^ 1);
        if (it + 1 < 8) { asm volatile("cp.async.wait_group 1;"); }
        else            { asm volatile("cp.async.wait_group 0;"); }
        __syncthreads();

        const float* sA = sm + (s*2 + 0)*D_ARRF;
        const float* sB = sm + (s*2 + 1)*D_ARRF;

        #pragma unroll
        for (int ks = 0; ks < 4; ks++) {
            int ca = ks*8 + (lane & 3);
            uint32_t Ah[16], Al[16], Bh[8], Bl[8];
            #pragma unroll
            for (int mf = 0; mf < 4; mf++) {
                int r1 = warpM*64 + mf*16 + (lane >> 2), r2 = r1 + 8;
                SPLIT2(Ah[mf*4+0], Al[mf*4+0], sA[swz(r1, ca)]);
                SPLIT2(Ah[mf*4+1], Al[mf*4+1], sA[swz(r2, ca)]);
                SPLIT2(Ah[mf*4+2], Al[mf*4+2], sA[swz(r1, ca + 4)]);
                SPLIT2(Ah[mf*4+3], Al[mf*4+3], sA[swz(r2, ca + 4)]);
            }
            #pragma unroll
            for (int nf = 0; nf < 4; nf++) {
                int rm = warpN*32 + nf*8 + (lane >> 2);
                SPLIT2(Bh[nf*2+0], Bl[nf*2+0], sB[swz(rm, ca)]);
                SPLIT2(Bh[nf*2+1], Bl[nf*2+1], sB[swz(rm, ca + 4)]);
            }
            #pragma unroll
            for (int mf = 0; mf < 4; mf++) {
                #pragma unroll
                for (int nf = 0; nf < 4; nf++) {
                    MMA8(c[mf][nf], Ah[mf*4+0], Ah[mf*4+1], Ah[mf*4+2], Ah[mf*4+3],
                         Bh[nf*2+0], Bh[nf*2+1]);
                    MMA8(c[mf][nf], Ah[mf*4+0], Ah[mf*4+1], Ah[mf*4+2], Ah[mf*4+3],
                         Bl[nf*2+0], Bl[nf*2+1]);
                    MMA8(c[mf][nf], Al[mf*4+0], Al[mf*4+1], Al[mf*4+2], Al[mf*4+3],
                         Bh[nf*2+0], Bh[nf*2+1]);
                }
            }
        }
        __syncthreads();
    }

    #pragma unroll
    for (int mf = 0; mf < 4; mf++) {
        int r1 = n0 + warpM*64 + mf*16 + (lane >> 2);
        #pragma unroll
        for (int nf = 0; nf < 4; nf++) {
            int gc = m0 + warpN*32 + nf*8 + (lane & 3)*2;
            *(float2*)&g_G[(size_t)r1*MM + gc]       = make_float2(c[mf][nf][0], c[mf][nf][1]);
            *(float2*)&g_G[(size_t)(r1 + 8)*MM + gc] = make_float2(c[mf][nf][2], c[mf][nf][3]);
        }
    }
}

// ---------------- per-row stats with exact top-2 refinement -----------------
__device__ __forceinline__ float gumbel_of(float u) {
    u = fminf(fmaxf(u, 1e-10f), 1.f - 1e-7f);
    return -logf(-logf(u));
}

__global__ void __launch_bounds__(256) k_rowstats(const float* __restrict__ gum,
                                                  const float* __restrict__ emb,
                                                  float* __restrict__ out) {
    __shared__ float sAcc[MM];
    int tid = threadIdx.x, wid = tid >> 5, lane = tid & 31;
    for (int i = tid; i < MM; i += 256) sAcc[i] = 0.f;
    __syncthreads();

    float esq_r[8][4];
    #pragma unroll
    for (int ch = 0; ch < 8; ch++) {
        float4 v = *(const float4*)&g_esq[ch*128 + lane*4];
        esq_r[ch][0] = v.x; esq_r[ch][1] = v.y; esq_r[ch][2] = v.z; esq_r[ch][3] = v.w;
    }
    float pAcc[8][4] = {};
    int nbase = blockIdx.x*128 + wid*16;

    for (int r = 0; r < 16; r++) {
        int n = nbase + r;
        const float* Gr = g_G + (size_t)n*MM;
        const float* Ur = gum + (size_t)n*MM;
        float dm[8][4];
        float h1v = -3.4e38f, h2v = -3.4e38f; int h1i = 0x7fffffff, h2i = 0x7fffffff;
        float s1v = -3.4e38f, s2v = -3.4e38f; int s1i = 0x7fffffff, s2i = 0x7fffffff;
        #pragma unroll
        for (int ch = 0; ch < 8; ch++) {
            float4 g4 = *(const float4*)&Gr[ch*128 + lane*4];
            float4 u4 = *(const float4*)&Ur[ch*128 + lane*4];
            float gg[4] = {g4.x, g4.y, g4.z, g4.w};
            float uu[4] = {u4.x, u4.y, u4.z, u4.w};
            #pragma unroll
            for (int j = 0; j < 4; j++) {
                int m = ch*128 + lane*4 + j;
                float d = 2.f*gg[j] - esq_r[ch][j];
                dm[ch][j] = d;
                if (d > h1v || (d == h1v && m < h1i)) { h2v = h1v; h2i = h1i; h1v = d; h1i = m; }
                else if (d > h2v || (d == h2v && m < h2i)) { h2v = d; h2i = m; }
                float sc = d + gumbel_of(uu[j]);
                if (sc > s1v || (sc == s1v && m < s1i)) { s2v = s1v; s2i = s1i; s1v = sc; s1i = m; }
                else if (sc > s2v || (sc == s2v && m < s2i)) { s2v = sc; s2i = m; }
            }
        }
        #pragma unroll
        for (int o = 16; o > 0; o >>= 1) {
            float ov1 = __shfl_xor_sync(0xffffffffu, h1v, o);
            int   oi1 = __shfl_xor_sync(0xffffffffu, h1i, o);
            float ov2 = __shfl_xor_sync(0xffffffffu, h2v, o);
            int   oi2 = __shfl_xor_sync(0xffffffffu, h2i, o);
            if (ov1 > h1v || (ov1 == h1v && oi1 < h1i)) {
                float t1v = h1v; int t1i = h1i;
                h1v = ov1; h1i = oi1;
                if (t1v > ov2 || (t1v == ov2 && t1i < oi2)) { h2v = t1v; h2i = t1i; }
                else { h2v = ov2; h2i = oi2; }
            } else {
                if (ov1 > h2v || (ov1 == h2v && oi1 < h2i)) { h2v = ov1; h2i = oi1; }
            }
            float pv1 = __shfl_xor_sync(0xffffffffu, s1v, o);
            int   pi1 = __shfl_xor_sync(0xffffffffu, s1i, o);
            float pv2 = __shfl_xor_sync(0xffffffffu, s2v, o);
            int   pi2 = __shfl_xor_sync(0xffffffffu, s2i, o);
            if (pv1 > s1v || (pv1 == s1v && pi1 < s1i)) {
                float t1v = s1v; int t1i = s1i;
                s1v = pv1; s1i = pi1;
                if (t1v > pv2 || (t1v == pv2 && t1i < pi2)) { s2v = t1v; s2i = t1i; }
                else { s2v = pv2; s2i = pi2; }
            } else {
                if (pv1 > s2v || (pv1 == s2v && pi1 < s2i)) { s2v = pv1; s2i = pi1; }
            }
        }

        int cands[4] = {h1i, h2i, s1i, s2i};
        float ex[4];
        const float* curp = g_cur + (size_t)n*DD + lane*8;
        #pragma unroll
        for (int t = 0; t < 4; t++) {
            const float* Ep = emb + (size_t)cands[t]*DD + lane*8;
            float s = 0.f;
            #pragma unroll
            for (int j = 0; j < 8; j++) s += curp[j]*Ep[j];
            #pragma unroll
            for (int o = 16; o > 0; o >>= 1) s += __shfl_xor_sync(0xffffffffu, s, o);
            ex[t] = 2.f*s - g_esq[cands[t]];
        }

        float ssum = 0.f;
        #pragma unroll
        for (int ch = 0; ch < 8; ch++)
            #pragma unroll
            for (int j = 0; j < 4; j++) { float e = expf(dm[ch][j] - h1v); dm[ch][j] = e; ssum += e; }
        #pragma unroll
        for (int o = 16; o > 0; o >>= 1) ssum += __shfl_xor_sync(0xffffffffu, ssum, o);
        float inv = 1.f / ssum;
        #pragma unroll
        for (int ch = 0; ch < 8; ch++)
            #pragma unroll
            for (int j = 0; j < 4; j++) pAcc[ch][j] += dm[ch][j] * inv;

        if (lane == 0) {
            int kH = h1i; float vH = ex[0];
            if (ex[1] > vH || (ex[1] == vH && h2i < kH)) { kH = h2i; vH = ex[1]; }
            atomicAdd(&g_hist[kH], 1u);
            float sc0 = ex[2] + gumbel_of(Ur[s1i]);
            float sc1 = ex[3] + gumbel_of(Ur[s2i]);
            int kS = s1i;
            if (sc1 > sc0 || (sc1 == sc0 && s2i < s1i)) kS = s2i;
            g_idx[n] = kS;
            out[QSIZE + 2 + n] = (float)kS;
        }
    }
    #pragma unroll
    for (int ch = 0; ch < 8; ch++)
        #pragma unroll
        for (int j = 0; j < 4; j++) atomicAdd(&sAcc[ch*128 + lane*4 + j], pAcc[ch][j]);
    __syncthreads();
    for (int i = tid; i < MM; i += 256) atomicAdd(&g_avgp[i], sAcc[i]);
}

__global__ void k_finalize(float* __restrict__ out) {
    __shared__ float s1[MM];
    __shared__ float s2[MM];
    int m = threadIdx.x;
    float hp = (float)g_hist[m] * (1.f/(float)NN);
    float ap = g_avgp[m] * (1.f/(float)NN);
    s1[m] = -hp * log2f(hp + 1e-10f);
    s2[m] = -ap * log2f(ap + 1e-10f);
    __syncthreads();
    for (int s = 512; s > 0; s >>= 1) {
        if (m < s) { s1[m] += s1[m + s]; s2[m] += s2[m + s]; }
        __syncthreads();
    }
    if (m == 0) { out[QSIZE] = s1[0]; out[QSIZE + 1] = s2[0]; }
}

// ---------------- fuse2 on tensor cores (3xTF32, split-on-load) --------------
// out[n][o] = prelu( sum_k w2b[o][k]*ctx[b][k][t]  +  W2E[idx[n]][o], a2 )
#define F2_STG 1600   /* X 1088 + W 512 */
#define F2_SMEMB (64*130*4)   /* transpose buffer dominates: 33280 */

__global__ void __launch_bounds__(256) k_f2_tc(const float* __restrict__ a2p,
                                               float* __restrict__ out) {
    extern __shared__ float fs[];
    int tid = threadIdx.x, lane = tid & 31, warp = tid >> 5;
    int warpM = warp >> 2, warpN = warp & 3;
    int t0 = blockIdx.x*128, o0 = blockIdx.y*64, b = blockIdx.z;
    int ot0 = o0 >> 4;

    uint32_t sbase;
    asm("{ .reg .u64 t; cvta.to.shared.u64 t, %1; cvt.u32.u64 %0, t; }" : "=r"(sbase) : "l"(fs));

    auto issue = [&](int ic, int s) {
        const float* xp = g_ctxout + ((size_t)(b*DD + ic*8))*TT + t0;
        uint32_t xd = sbase + (uint32_t)((s*F2_STG)*4);
        {
            int row = tid >> 5, q = tid & 31;   // 256 = 8 rows x 32 chunks
            asm volatile("cp.async.cg.shared.global [%0], [%1], 16;"
                :: "r"(xd + (uint32_t)((row*136 + q*4)*4)), "l"(xp + (size_t)row*TT + q*4));
        }
        if (tid < 128) {
            const float* wp = g_w2sh + ((size_t)ic*16 + ot0)*128;
            uint32_t wd = sbase + (uint32_t)((s*F2_STG + 1088)*4);
            asm volatile("cp.async.cg.shared.global [%0], [%1], 16;"
                :: "r"(wd + (uint32_t)(tid*16)), "l"(wp + tid*4));
        }
        asm volatile("cp.async.commit_group;");
    };

    float c[2][4][4] = {};
    issue(0, 0);
    issue(1, 1);

    for (int ic = 0; ic < 32; ic++) {
        int s = ic & 1;
        if (ic < 31) { asm volatile("cp.async.wait_group 1;"); }
        else         { asm volatile("cp.async.wait_group 0;"); }
        __syncthreads();
        const float* XE = fs + s*F2_STG;
        const float* WE = XE + 1088;
        int i0v = lane & 3, trow = lane >> 2;

        uint32_t ah[2][4], al[2][4];
        #pragma unroll
        for (int mf = 0; mf < 2; mf++) {
            float4 vw = *(const float4*)&WE[(warpM*2 + mf)*128 + lane*4];
            SPLIT2(ah[mf][0], al[mf][0], vw.x);
            SPLIT2(ah[mf][1], al[mf][1], vw.y);
            SPLIT2(ah[mf][2], al[mf][2], vw.z);
            SPLIT2(ah[mf][3], al[mf][3], vw.w);
        }
        uint32_t bh[4][2], bl[4][2];
        #pragma unroll
        for (int nf = 0; nf < 4; nf++) {
            int toff = warpN*32 + nf*8 + trow;
            float b0 = XE[i0v*136 + toff];
            float b1 = XE[(i0v + 4)*136 + toff];
            SPLIT2(bh[nf][0], bl[nf][0], b0);
            SPLIT2(bh[nf][1], bl[nf][1], b1);
        }
        #pragma unroll
        for (int mf = 0; mf < 2; mf++) {
            #pragma unroll
            for (int nf = 0; nf < 4; nf++) {
                MMA8(c[mf][nf], ah[mf][0], ah[mf][1], ah[mf][2], ah[mf][3], bh[nf][0], bh[nf][1]);
                MMA8(c[mf][nf], ah[mf][0], ah[mf][1], ah[mf][2], ah[mf][3], bl[nf][0], bl[nf][1]);
                MMA8(c[mf][nf], al[mf][0], al[mf][1], al[mf][2], al[mf][3], bh[nf][0], bh[nf][1]);
            }
        }
        __syncthreads();
        if (ic + 2 < 32) issue(ic + 2, s);
    }

    // epilogue: smem transpose [o][t] -> [t][o], + W2E gather + prelu
    #pragma unroll
    for (int mf = 0; mf < 2; mf++) {
        int r = warpM*32 + mf*16 + (lane >> 2);
        #pragma unroll
        for (int nf = 0; nf < 4; nf++) {
            int tg = warpN*32 + nf*8 + (lane & 3)*2;
            *(float2*)&fs[r*130 + tg]       = make_float2(c[mf][nf][0], c[mf][nf][1]);
            *(float2*)&fs[(r + 8)*130 + tg] = make_float2(c[mf][nf][2], c[mf][nf][3]);
        }
    }
    __syncthreads();
    float a2v = *a2p;
    int nl = tid >> 1, half = tid & 1;
    size_t n = (size_t)b*TT + t0 + nl;
    int mi = g_idx[n];
    const float* w2e = g_W2E + (size_t)mi*DD + o0 + half*32;
    float* op = out + n*DD + o0 + half*32;
    #pragma unroll
    for (int j = 0; j < 8; j++) {
        float4 w4 = *(const float4*)&w2e[j*4];
        float4 v;
        float u;
        u = fs[(half*32 + j*4 + 0)*130 + nl] + w4.x; v.x = (u >= 0.f) ? u : a2v*u;
        u = fs[(half*32 + j*4 + 1)*130 + nl] + w4.y; v.y = (u >= 0.f) ? u : a2v*u;
        u = fs[(half*32 + j*4 + 2)*130 + nl] + w4.z; v.z = (u >= 0.f) ? u : a2v*u;
        u = fs[(half*32 + j*4 + 3)*130 + nl] + w4.w; v.w = (u >= 0.f) ? u : a2v*u;
        *(float4*)&op[j*4] = v;
    }
}

// ---------------- launch -----------------------------------------------------
extern "C" void kernel_launch(void* const* d_in, const int* in_sizes, int n_in,
                              void* d_out, int out_size) {
    const float* x     = (const float*)d_in[0];
    const float* noise = (const float*)d_in[1];
    const float* gum   = (const float*)d_in[2];
    const int*   epo   = (const int*)  d_in[3];
    const float* emb   = (const float*)d_in[4];
    const float* wctx  = (const float*)d_in[5];
    const float* wf1   = (const float*)d_in[6];
    const float* a1    = (const float*)d_in[7];
    const float* wf2   = (const float*)d_in[8];
    const float* a2    = (const float*)d_in[9];
    float* out = (float*)d_out;

    cudaFuncSetAttribute(k_conv_tc, cudaFuncAttributeMaxDynamicSharedMemorySize, CV_SMEMB);
    cudaFuncSetAttribute(k_dist_mma, cudaFuncAttributeMaxDynamicSharedMemorySize, D_SMEMB);
    cudaFuncSetAttribute(k_f2_tc, cudaFuncAttributeMaxDynamicSharedMemorySize, F2_SMEMB);

    dim3 tb32(32, 8);

    k_scale<<<BB, 256>>>(x, epo);                                   // 0
    k_noisy<<<dim3((LL + 31)/32, DD/32, BB), tb32>>>(x, noise);     // 1
    k_shufw<<<DD*DD*CTX/256, 256>>>(wctx);                          // 2
    k_conv_tc<<<dim3(TT/128, 2, BB), 256, CV_SMEMB>>>(0);           // 3 <- capture
    k_conv_tc<<<dim3(TT/128, 2, BB), 256, CV_SMEMB>>>(128);         // 4
    k_xt<<<dim3(TT/32, DD/32, BB), tb32>>>(x);                      // 5
    k_transp<<<dim3(2*DD/32, DD/32), tb32>>>(wf1, DD, 2*DD, 1);     // w1T
    k_f1<<<dim3(TT/64, DD/64, BB), 256>>>(a1);
    k_transp<<<dim3(DD/32, MM/32), tb32>>>(emb, MM, DD, 0);         // ET
    k_transp<<<dim3(2*DD/32, DD/32), tb32>>>(wf2, DD, 2*DD, 2);     // w2T
    k_esq<<<MM/8, 256>>>(emb);
    k_zero<<<4, 256>>>();
    k_shufw2<<<DD*DD/256, 256>>>(wf2);
    k_gemm_w2e<<<dim3(MM/64, DD/64), 256>>>();
    k_dist_mma<<<dim3(NN/128, MM/128), 256, D_SMEMB>>>(emb);
    k_rowstats<<<NN/128, 256>>>(gum, emb, out);
    k_finalize<<<1, MM>>>(out);
    k_f2_tc<<<dim3(TT/128, DD/64, BB), 256, F2_SMEMB>>>(a2, out);
}

// round 7
// speedup vs baseline: 1.1530x; 1.1530x over previous
#include <cuda_runtime.h>
#include <cuda_bf16.h>
#include <math.h>
#include <stdint.h>

#define BB 8
#define TT 4096
#define DD 256
#define MM 1024
#define CTX 7
#define LL (TT - 1 + CTX)      /* 4102 */
#define LLP 4104               /* padded stride, 16B-aligned rows */
#define NN (BB*TT)             /* 32768 */
#define QSIZE (NN*DD)          /* 8388608 */

// ---------------- scratch (static device globals; no runtime alloc) ----------
__device__ __align__(16) float g_xt[BB*DD*TT];          // x transposed [b][d][t]
__device__ __align__(16) float g_noisy_hi[BB*DD*LLP];   // noisy ctx, tf32-hi
__device__ __align__(16) float g_noisy_lo[BB*DD*LLP];   // residual (tf32)
__device__ __align__(16) float g_wch[DD*DD*CTX];        // w_ctx hi, A-frag shuffled
__device__ __align__(16) float g_wcl[DD*DD*CTX];        // w_ctx lo
__device__ __align__(16) float g_w2shh[DD*DD];          // w_f2[:,256:] hi, shuffled
__device__ __align__(16) float g_w2shl[DD*DD];          // lo
__device__ __align__(16) float g_ctxout[BB*DD*TT];      // conv output [b][o][t]
__device__ __align__(16) float g_cur[(size_t)NN*DD];    // fuse1 out, exact fp32
__device__ __align__(16) __nv_bfloat16 g_cur_bh[(size_t)NN*DD]; // bf16 hi
__device__ __align__(16) __nv_bfloat16 g_cur_bl[(size_t)NN*DD]; // bf16 lo
__device__ __align__(16) __nv_bfloat16 g_E_bh[MM*DD];
__device__ __align__(16) __nv_bfloat16 g_E_bl[MM*DD];
__device__ __align__(16) float g_G[(size_t)NN*MM];      // cur . E^T   [n][m]
__device__ __align__(16) float g_ET[DD*MM];             // E transposed
__device__ __align__(16) float g_w1T[2*DD*DD];
__device__ __align__(16) float g_w2T[2*DD*DD];
__device__ __align__(16) float g_W2E[MM*DD];            // E . w_f2a^T  [m][o]
__device__ __align__(16) float g_esq[MM];
__device__ float g_scale[BB];
__device__ int   g_idx[NN];
__device__ unsigned int g_hist[MM];
__device__ float g_avgp[MM];

__device__ __forceinline__ float tf32_hi(float v) {
    uint32_t b;
    asm("cvt.rna.tf32.f32 %0, %1;" : "=r"(b) : "f"(v));
    return __uint_as_float(b);
}

#define MMA8(d, a0,a1,a2,a3, b0,b1) \
    asm volatile("mma.sync.aligned.m16n8k8.row.col.f32.tf32.tf32.f32 " \
        "{%0,%1,%2,%3}, {%4,%5,%6,%7}, {%8,%9}, {%0,%1,%2,%3};" \
        : "+f"((d)[0]), "+f"((d)[1]), "+f"((d)[2]), "+f"((d)[3]) \
        : "r"(a0), "r"(a1), "r"(a2), "r"(a3), "r"(b0), "r"(b1))

#define MMA16B(d, a, b) \
    asm volatile("mma.sync.aligned.m16n8k16.row.col.f32.bf16.bf16.f32 " \
        "{%0,%1,%2,%3}, {%4,%5,%6,%7}, {%8,%9}, {%0,%1,%2,%3};" \
        : "+f"((d)[0]), "+f"((d)[1]), "+f"((d)[2]), "+f"((d)[3]) \
        : "r"((a)[0]), "r"((a)[1]), "r"((a)[2]), "r"((a)[3]), "r"((b)[0]), "r"((b)[1]))

// split exact -> (hi, lo) tf32 pair in registers (used in f2 B-side only)
#define SPLIT2(vh, vl, v) do { float _h = tf32_hi(v); (vh) = __float_as_uint(_h); \
                               (vl) = __float_as_uint(tf32_hi((v) - _h)); } while (0)

// ---------------- small utility kernels -------------------------------------
__global__ void k_zero() {
    int i = blockIdx.x*blockDim.x + threadIdx.x;
    if (i < MM) { g_hist[i] = 0u; g_avgp[i] = 0.f; }
}

__global__ void k_transp(const float* __restrict__ src, int rows, int cols, int which) {
    __shared__ float s[32][33];
    float* dst = (which == 0) ? g_ET : (which == 1) ? g_w1T : g_w2T;
    int c0 = blockIdx.x*32, r0 = blockIdx.y*32;
    int tx = threadIdx.x, ty = threadIdx.y;
    #pragma unroll
    for (int j = 0; j < 4; j++) {
        int r = r0 + ty + j*8, c = c0 + tx;
        s[ty + j*8][tx] = (r < rows && c < cols) ? src[(size_t)r*cols + c] : 0.f;
    }
    __syncthreads();
    #pragma unroll
    for (int j = 0; j < 4; j++) {
        int c = c0 + ty + j*8, r = r0 + tx;
        if (c < cols && r < rows) dst[(size_t)c*rows + r] = s[tx][ty + j*8];
    }
}

__global__ void k_esq(const float* __restrict__ E) {
    int warp = threadIdx.x >> 5, lane = threadIdx.x & 31;
    int m = blockIdx.x*8 + warp;
    const float* row = E + (size_t)m*DD;
    float s = 0.f;
    for (int c = lane; c < DD; c += 32) { float v = row[c]; s += v*v; }
    #pragma unroll
    for (int o = 16; o > 0; o >>= 1) s += __shfl_down_sync(0xffffffffu, s, o);
    if (lane == 0) g_esq[m] = s;
}

// E -> bf16 hi/lo
__global__ void k_split_eb(const float* __restrict__ E) {
    int i = blockIdx.x*256 + threadIdx.x;
    float v = E[i];
    __nv_bfloat16 h = __float2bfloat16(v);
    g_E_bh[i] = h;
    g_E_bl[i] = __float2bfloat16(v - __bfloat162float(h));
}

// w_ctx -> tf32 hi/lo, A-fragment-shuffled
__global__ void k_splitw(const float* __restrict__ wctx) {
    int idx = blockIdx.x*256 + threadIdx.x;       // grid 1792
    int o = idx / (DD*CTX);
    int rem = idx - o*(DD*CTX);
    int i = rem / CTX, kk = rem - i*CTX;
    float v = wctx[idx];
    float h = tf32_hi(v);
    int ic = i >> 3, il = i & 7;
    int otile = o >> 4, oloc = o & 15;
    int lane = (oloc & 7)*4 + (il & 3);
    int reg = (oloc >> 3) + 2*(il >> 2);
    int d = ((ic*7 + kk)*16 + otile)*128 + lane*4 + reg;
    g_wch[d] = h;
    g_wcl[d] = tf32_hi(v - h);
}

// w_f2[:,256:512] -> tf32 hi/lo, A-fragment-shuffled
__global__ void k_shufw2(const float* __restrict__ wf2) {
    int idx = blockIdx.x*256 + threadIdx.x;       // grid 256
    int o = idx >> 8, k = idx & 255;
    int ic = k >> 3, il = k & 7;
    int otile = o >> 4, oloc = o & 15;
    int lane = (oloc & 7)*4 + (il & 3);
    int reg = (oloc >> 3) + 2*(il >> 2);
    float v = wf2[o*2*DD + DD + k];
    float h = tf32_hi(v);
    int d = (ic*16 + otile)*128 + lane*4 + reg;
    g_w2shh[d] = h;
    g_w2shl[d] = tf32_hi(v - h);
}

__global__ void k_scale(const float* __restrict__ x, const int* __restrict__ epo_p) {
    int b = blockIdx.x;
    const float* xb = x + (size_t)b*TT*DD;
    float s = 0.f;
    int tot = (TT-1)*DD;
    for (int i = threadIdx.x; i < tot; i += blockDim.x) { float v = xb[i]; s += v*v; }
    __shared__ float sm[8];
    #pragma unroll
    for (int o = 16; o > 0; o >>= 1) s += __shfl_down_sync(0xffffffffu, s, o);
    if ((threadIdx.x & 31) == 0) sm[threadIdx.x >> 5] = s;
    __syncthreads();
    if (threadIdx.x == 0) {
        float t = 0.f;
        for (int w = 0; w < 8; w++) t += sm[w];
        int iv = epo_p[0];
        float ef = (iv >= 0 && iv < 100000) ? (float)iv : __int_as_float(iv);
        float sc = sqrtf(t / (float)(DD*LL));
        g_scale[b] = 0.5f * sc * exp2f(-ef * 0.1f);
    }
}

__global__ void k_xt(const float* __restrict__ x) {
    __shared__ float s[32][33];
    int b = blockIdx.z, t0 = blockIdx.x*32, d0 = blockIdx.y*32;
    int tx = threadIdx.x, ty = threadIdx.y;
    #pragma unroll
    for (int j = 0; j < 4; j++) {
        int t = t0 + ty + j*8;
        s[ty + j*8][tx] = x[((size_t)b*TT + t)*DD + d0 + tx];
    }
    __syncthreads();
    #pragma unroll
    for (int j = 0; j < 4; j++) {
        int d = d0 + ty + j*8;
        g_xt[((size_t)b*DD + d)*TT + t0 + tx] = s[tx][ty + j*8];
    }
}

// noisy = pad(x)+coef*noise, tf32 hi/lo materialized (stride LLP)
__global__ void k_noisy(const float* __restrict__ x, const float* __restrict__ noise) {
    __shared__ float s[32][33];
    int b = blockIdx.z, l0 = blockIdx.x*32, i0 = blockIdx.y*32;
    int tx = threadIdx.x, ty = threadIdx.y;
    float coef = g_scale[b];
    #pragma unroll
    for (int j = 0; j < 4; j++) {
        int row = ty + j*8;
        int t = l0 + row - CTX;
        float v = (t >= 0 && t < TT-1) ? x[((size_t)b*TT + t)*DD + i0 + tx] : 0.f;
        s[row][tx] = v;
    }
    __syncthreads();
    #pragma unroll
    for (int j = 0; j < 4; j++) {
        int i = i0 + ty + j*8, l = l0 + tx;
        if (l < LL) {
            float v = s[tx][ty + j*8] + coef * noise[((size_t)b*DD + i)*LL + l];
            float h = tf32_hi(v);
            size_t off = ((size_t)b*DD + i)*LLP + l;
            g_noisy_hi[off] = h;
            g_noisy_lo[off] = tf32_hi(v - h);
        }
    }
}

// ---------------- conv on tensor cores (3xTF32, materialized hi/lo) ----------
#define CV_STG 9344  /* floats per stage: X hi/lo 2*1088 + W hi/lo 2*3584 */
#define CV_SMEMB (2*CV_STG*4)

__global__ void __launch_bounds__(256, 2) k_conv_tc(int obase) {
    extern __shared__ float cs[];
    int tid = threadIdx.x, lane = tid & 31, warp = tid >> 5;
    int warpM = warp >> 2, warpN = warp & 3;
    int t0 = blockIdx.x*128, o0 = obase + blockIdx.y*64, b = blockIdx.z;
    int ot0 = o0 >> 4;

    uint32_t sbase;
    asm("{ .reg .u64 t; cvta.to.shared.u64 t, %1; cvt.u32.u64 %0, t; }" : "=r"(sbase) : "l"(cs));

    auto issue = [&](int ic, int s) {
        const float* xh = g_noisy_hi + ((size_t)(b*DD + ic*8))*LLP + t0;
        const float* xl = g_noisy_lo + ((size_t)(b*DD + ic*8))*LLP + t0;
        uint32_t xdh = sbase + (uint32_t)((s*CV_STG)*4);
        uint32_t xdl = xdh + 1088*4;
        for (int idx = tid; idx < 272; idx += 256) {
            int row = idx / 34, q = idx - row*34;
            asm volatile("cp.async.cg.shared.global [%0], [%1], 16;"
                :: "r"(xdh + (uint32_t)((row*136 + q*4)*4)), "l"(xh + (size_t)row*LLP + q*4));
            asm volatile("cp.async.cg.shared.global [%0], [%1], 16;"
                :: "r"(xdl + (uint32_t)((row*136 + q*4)*4)), "l"(xl + (size_t)row*LLP + q*4));
        }
        const float* wh = g_wch + ((size_t)(ic*7)*16 + ot0)*128;
        const float* wl = g_wcl + ((size_t)(ic*7)*16 + ot0)*128;
        uint32_t wdh = sbase + (uint32_t)((s*CV_STG + 2176)*4);
        uint32_t wdl = wdh + 3584*4;
        for (int idx = tid; idx < 896; idx += 256) {
            int kk = idx >> 7, q = idx & 127;
            asm volatile("cp.async.cg.shared.global [%0], [%1], 16;"
                :: "r"(wdh + (uint32_t)((kk*512 + q*4)*4)), "l"(wh + kk*2048 + q*4));
            asm volatile("cp.async.cg.shared.global [%0], [%1], 16;"
                :: "r"(wdl + (uint32_t)((kk*512 + q*4)*4)), "l"(wl + kk*2048 + q*4));
        }
        asm volatile("cp.async.commit_group;");
    };

    float c[2][4][4] = {};
    issue(0, 0);
    issue(1, 1);

    for (int ic = 0; ic < 32; ic++) {
        int s = ic & 1;
        if (ic < 31) { asm volatile("cp.async.wait_group 1;"); }
        else         { asm volatile("cp.async.wait_group 0;"); }
        __syncthreads();
        const float* XH = cs + s*CV_STG;
        const float* XL = XH + 1088;
        const float* WH = XH + 2176;
        const float* WL = XH + 5760;
        int i0v = lane & 3, trow = lane >> 2;

        #pragma unroll
        for (int kk = 0; kk < 7; kk++) {
            uint32_t ah[2][4], al[2][4];
            #pragma unroll
            for (int mf = 0; mf < 2; mf++) {
                float4 vh = *(const float4*)&WH[kk*512 + (warpM*2 + mf)*128 + lane*4];
                float4 vl = *(const float4*)&WL[kk*512 + (warpM*2 + mf)*128 + lane*4];
                ah[mf][0] = __float_as_uint(vh.x); ah[mf][1] = __float_as_uint(vh.y);
                ah[mf][2] = __float_as_uint(vh.z); ah[mf][3] = __float_as_uint(vh.w);
                al[mf][0] = __float_as_uint(vl.x); al[mf][1] = __float_as_uint(vl.y);
                al[mf][2] = __float_as_uint(vl.z); al[mf][3] = __float_as_uint(vl.w);
            }
            uint32_t bh[4][2], bl[4][2];
            #pragma unroll
            for (int nf = 0; nf < 4; nf++) {
                int toff = warpN*32 + nf*8 + trow + kk;
                bh[nf][0] = __float_as_uint(XH[i0v*136 + toff]);
                bh[nf][1] = __float_as_uint(XH[(i0v + 4)*136 + toff]);
                bl[nf][0] = __float_as_uint(XL[i0v*136 + toff]);
                bl[nf][1] = __float_as_uint(XL[(i0v + 4)*136 + toff]);
            }
            #pragma unroll
            for (int mf = 0; mf < 2; mf++) {
                #pragma unroll
                for (int nf = 0; nf < 4; nf++) {
                    MMA8(c[mf][nf], ah[mf][0], ah[mf][1], ah[mf][2], ah[mf][3], bh[nf][0], bh[nf][1]);
                    MMA8(c[mf][nf], ah[mf][0], ah[mf][1], ah[mf][2], ah[mf][3], bl[nf][0], bl[nf][1]);
                    MMA8(c[mf][nf], al[mf][0], al[mf][1], al[mf][2], al[mf][3], bh[nf][0], bh[nf][1]);
                }
            }
        }
        __syncthreads();
        if (ic + 2 < 32) issue(ic + 2, s);
    }

    #pragma unroll
    for (int mf = 0; mf < 2; mf++) {
        int r = o0 + warpM*32 + mf*16 + (lane >> 2);
        #pragma unroll
        for (int nf = 0; nf < 4; nf++) {
            int tg = t0 + warpN*32 + nf*8 + (lane & 3)*2;
            *(float2*)&g_ctxout[((size_t)b*DD + r)*TT + tg]     = make_float2(c[mf][nf][0], c[mf][nf][1]);
            *(float2*)&g_ctxout[((size_t)b*DD + r + 8)*TT + tg] = make_float2(c[mf][nf][2], c[mf][nf][3]);
        }
    }
}

// ---------------- fuse1 (SIMT, exact); writes cur + bf16 hi/lo ---------------
__global__ void __launch_bounds__(256) k_f1(const float* __restrict__ a1p) {
    __shared__ float sA[16][68];
    __shared__ float sB[16][68];
    int b = blockIdx.z, t0 = blockIdx.x*64, o0 = blockIdx.y*64;
    int tid = threadIdx.x;
    int tx = tid & 15, ty = tid >> 4;
    int kl = tid >> 4, nl4 = (tid & 15)*4;
    float acc[4][4] = {};
    for (int kc = 0; kc < 2*DD; kc += 16) {
        const float* Ap = (kc < DD) ? (g_xt + ((size_t)b*DD + kc)*TT)
                                    : (g_ctxout + ((size_t)b*DD + (kc - DD))*TT);
        *(float4*)&sA[kl][nl4] = *(const float4*)(Ap + (size_t)kl*TT + t0 + nl4);
        *(float4*)&sB[kl][nl4] = *(const float4*)(g_w1T + (size_t)(kc + kl)*DD + o0 + nl4);
        __syncthreads();
        #pragma unroll
        for (int k = 0; k < 16; k++) {
            float4 av = *(const float4*)&sA[k][4*tx];
            float4 bv = *(const float4*)&sB[k][4*ty];
            float ar[4] = {av.x, av.y, av.z, av.w};
            float br[4] = {bv.x, bv.y, bv.z, bv.w};
            #pragma unroll
            for (int a = 0; a < 4; a++)
                #pragma unroll
                for (int cc = 0; cc < 4; cc++)
                    acc[a][cc] += br[a] * ar[cc];
        }
        __syncthreads();
    }
    float a1 = *a1p;
    #pragma unroll
    for (int cc = 0; cc < 4; cc++) {
        size_t n = (size_t)b*TT + t0 + 4*tx + cc;
        float4 ve;
        __nv_bfloat16 bh[4], bl[4];
        float u;
        u = acc[0][cc]; u = (u >= 0.f) ? u : a1*u; ve.x = u;
        u = acc[1][cc]; u = (u >= 0.f) ? u : a1*u; ve.y = u;
        u = acc[2][cc]; u = (u >= 0.f) ? u : a1*u; ve.z = u;
        u = acc[3][cc]; u = (u >= 0.f) ? u : a1*u; ve.w = u;
        float vv[4] = {ve.x, ve.y, ve.z, ve.w};
        #pragma unroll
        for (int j = 0; j < 4; j++) {
            bh[j] = __float2bfloat16(vv[j]);
            bl[j] = __float2bfloat16(vv[j] - __bfloat162float(bh[j]));
        }
        *(float4*)&g_cur[n*DD + o0 + 4*ty] = ve;
        *(uint2*)&g_cur_bh[n*DD + o0 + 4*ty] = *(uint2*)bh;
        *(uint2*)&g_cur_bl[n*DD + o0 + 4*ty] = *(uint2*)bl;
    }
}

// ---------------- W2E GEMM (small) -------------------------------------------
__global__ void __launch_bounds__(256) k_gemm_w2e() {
    __shared__ float sA[16][68];
    __shared__ float sB[16][68];
    int i0 = blockIdx.x*64, j0 = blockIdx.y*64;
    int tid = threadIdx.x;
    int tx = tid & 15, ty = tid >> 4;
    int kl = tid >> 4, nl4 = (tid & 15)*4;
    float acc[4][4] = {};
    for (int kc = 0; kc < DD; kc += 16) {
        *(float4*)&sA[kl][nl4] = *(const float4*)(g_ET  + (size_t)(kc + kl)*MM + i0 + nl4);
        *(float4*)&sB[kl][nl4] = *(const float4*)(g_w2T + (size_t)(kc + kl)*DD + j0 + nl4);
        __syncthreads();
        #pragma unroll
        for (int k = 0; k < 16; k++) {
            float4 av = *(const float4*)&sA[k][4*tx];
            float4 bv = *(const float4*)&sB[k][4*ty];
            float ar[4] = {av.x, av.y, av.z, av.w};
            float br[4] = {bv.x, bv.y, bv.z, bv.w};
            #pragma unroll
            for (int a = 0; a < 4; a++)
                #pragma unroll
                for (int cc = 0; cc < 4; cc++)
                    acc[a][cc] += br[a] * ar[cc];
        }
        __syncthreads();
    }
    #pragma unroll
    for (int cc = 0; cc < 4; cc++) {
        int i = i0 + 4*tx + cc;
        float4 v = make_float4(acc[0][cc], acc[1][cc], acc[2][cc], acc[3][cc]);
        *(float4*)&g_W2E[(size_t)i*DD + j0 + 4*ty] = v;
    }
}

// ---------------- dist GEMM via mma.sync bf16 (3xBF16, k16) ------------------
// smem per stage: 4 arrays (Ah, Al, Bh, Bl), each 128 rows x 32 bf16, row
// stride 40 bf16 (20 words, conflict-free since gcd-cycle of 20 mod 32 covers).
#define DB_ROWW 20                   /* words per row */
#define DB_ARRW (128*DB_ROWW)        /* 2560 words per array */
#define DB_STGW (4*DB_ARRW)          /* 10240 words per stage */
#define DB_SMEMB (2*DB_STGW*4)       /* 81920 bytes */

__global__ void __launch_bounds__(256, 2) k_dist_b(const float* __restrict__ emb_unused) {
    extern __shared__ uint32_t dsm[];
    int tid = threadIdx.x, lane = tid & 31, warp = tid >> 5;
    int warpM = warp >> 2, warpN = warp & 3;
    int n0 = blockIdx.x*128, m0 = blockIdx.y*128;

    uint32_t sbase;
    asm("{ .reg .u64 t; cvta.to.shared.u64 t, %1; cvt.u32.u64 %0, t; }" : "=r"(sbase) : "l"(dsm));

    const __nv_bfloat16* srcs[4] = {
        g_cur_bh + (size_t)n0*DD, g_cur_bl + (size_t)n0*DD,
        g_E_bh   + (size_t)m0*DD, g_E_bl   + (size_t)m0*DD };

    auto issue = [&](int kc, int s) {
        #pragma unroll
        for (int a = 0; a < 4; a++) {
            uint32_t dstb = sbase + (uint32_t)((s*DB_STGW + a*DB_ARRW)*4);
            #pragma unroll
            for (int j = 0; j < 2; j++) {
                int cid = tid + j*256;              // 512 chunks
                int row = cid >> 2, q = cid & 3;
                uint32_t dst = dstb + (uint32_t)(row*80 + q*16);
                const __nv_bfloat16* src = srcs[a] + (size_t)row*DD + kc + q*8;
                asm volatile("cp.async.cg.shared.global [%0], [%1], 16;"
                             :: "r"(dst), "l"(src));
            }
        }
        asm volatile("cp.async.commit_group;");
    };

    float c[4][4][4] = {};
    issue(0, 0);

    int gr = lane >> 2, lc = lane & 3;
    for (int it = 0; it < 8; it++) {
        int s = it & 1;
        if (it + 1 < 8) issue((it + 1)*32, s ^ 1);
        if (it + 1 < 8) { asm volatile("cp.async.wait_group 1;"); }
        else            { asm volatile("cp.async.wait_group 0;"); }
        __syncthreads();

        const uint32_t* sAh = dsm + s*DB_STGW;
        const uint32_t* sAl = sAh + DB_ARRW;
        const uint32_t* sBh = sAh + 2*DB_ARRW;
        const uint32_t* sBl = sAh + 3*DB_ARRW;

        #pragma unroll
        for (int ks = 0; ks < 2; ks++) {
            int wb = ks*8 + lc;
            uint32_t ah[4][4], al[4][4], bh[4][2], bl[4][2];
            #pragma unroll
            for (int mf = 0; mf < 4; mf++) {
                int r1 = (warpM*64 + mf*16 + gr)*DB_ROWW, r2 = r1 + 8*DB_ROWW;
                ah[mf][0] = sAh[r1 + wb];     ah[mf][1] = sAh[r2 + wb];
                ah[mf][2] = sAh[r1 + wb + 4]; ah[mf][3] = sAh[r2 + wb + 4];
                al[mf][0] = sAl[r1 + wb];     al[mf][1] = sAl[r2 + wb];
                al[mf][2] = sAl[r1 + wb + 4]; al[mf][3] = sAl[r2 + wb + 4];
            }
            #pragma unroll
            for (int nf = 0; nf < 4; nf++) {
                int rn = (warpN*32 + nf*8 + gr)*DB_ROWW;
                bh[nf][0] = sBh[rn + wb]; bh[nf][1] = sBh[rn + wb + 4];
                bl[nf][0] = sBl[rn + wb]; bl[nf][1] = sBl[rn + wb + 4];
            }
            #pragma unroll
            for (int mf = 0; mf < 4; mf++) {
                #pragma unroll
                for (int nf = 0; nf < 4; nf++) {
                    MMA16B(c[mf][nf], ah[mf], bh[nf]);
                    MMA16B(c[mf][nf], ah[mf], bl[nf]);
                    MMA16B(c[mf][nf], al[mf], bh[nf]);
                }
            }
        }
        __syncthreads();
    }

    #pragma unroll
    for (int mf = 0; mf < 4; mf++) {
        int r1 = n0 + warpM*64 + mf*16 + gr;
        #pragma unroll
        for (int nf = 0; nf < 4; nf++) {
            int gc = m0 + warpN*32 + nf*8 + lc*2;
            *(float2*)&g_G[(size_t)r1*MM + gc]       = make_float2(c[mf][nf][0], c[mf][nf][1]);
            *(float2*)&g_G[(size_t)(r1 + 8)*MM + gc] = make_float2(c[mf][nf][2], c[mf][nf][3]);
        }
    }
}

// ---------------- per-row stats with exact top-2 refinement -----------------
__device__ __forceinline__ float gumbel_of(float u) {
    u = fminf(fmaxf(u, 1e-10f), 1.f - 1e-7f);
    return -logf(-logf(u));
}

__global__ void __launch_bounds__(256) k_rowstats(const float* __restrict__ gum,
                                                  const float* __restrict__ emb,
                                                  float* __restrict__ out) {
    __shared__ float sAcc[MM];
    int tid = threadIdx.x, wid = tid >> 5, lane = tid & 31;
    for (int i = tid; i < MM; i += 256) sAcc[i] = 0.f;
    __syncthreads();

    float esq_r[8][4];
    #pragma unroll
    for (int ch = 0; ch < 8; ch++) {
        float4 v = *(const float4*)&g_esq[ch*128 + lane*4];
        esq_r[ch][0] = v.x; esq_r[ch][1] = v.y; esq_r[ch][2] = v.z; esq_r[ch][3] = v.w;
    }
    float pAcc[8][4] = {};
    int nbase = blockIdx.x*128 + wid*16;

    for (int r = 0; r < 16; r++) {
        int n = nbase + r;
        const float* Gr = g_G + (size_t)n*MM;
        const float* Ur = gum + (size_t)n*MM;
        float dm[8][4];
        float h1v = -3.4e38f, h2v = -3.4e38f; int h1i = 0x7fffffff, h2i = 0x7fffffff;
        float s1v = -3.4e38f, s2v = -3.4e38f; int s1i = 0x7fffffff, s2i = 0x7fffffff;
        #pragma unroll
        for (int ch = 0; ch < 8; ch++) {
            float4 g4 = *(const float4*)&Gr[ch*128 + lane*4];
            float4 u4 = *(const float4*)&Ur[ch*128 + lane*4];
            float gg[4] = {g4.x, g4.y, g4.z, g4.w};
            float uu[4] = {u4.x, u4.y, u4.z, u4.w};
            #pragma unroll
            for (int j = 0; j < 4; j++) {
                int m = ch*128 + lane*4 + j;
                float d = 2.f*gg[j] - esq_r[ch][j];
                dm[ch][j] = d;
                if (d > h1v || (d == h1v && m < h1i)) { h2v = h1v; h2i = h1i; h1v = d; h1i = m; }
                else if (d > h2v || (d == h2v && m < h2i)) { h2v = d; h2i = m; }
                float sc = d + gumbel_of(uu[j]);
                if (sc > s1v || (sc == s1v && m < s1i)) { s2v = s1v; s2i = s1i; s1v = sc; s1i = m; }
                else if (sc > s2v || (sc == s2v && m < s2i)) { s2v = sc; s2i = m; }
            }
        }
        #pragma unroll
        for (int o = 16; o > 0; o >>= 1) {
            float ov1 = __shfl_xor_sync(0xffffffffu, h1v, o);
            int   oi1 = __shfl_xor_sync(0xffffffffu, h1i, o);
            float ov2 = __shfl_xor_sync(0xffffffffu, h2v, o);
            int   oi2 = __shfl_xor_sync(0xffffffffu, h2i, o);
            if (ov1 > h1v || (ov1 == h1v && oi1 < h1i)) {
                float t1v = h1v; int t1i = h1i;
                h1v = ov1; h1i = oi1;
                if (t1v > ov2 || (t1v == ov2 && t1i < oi2)) { h2v = t1v; h2i = t1i; }
                else { h2v = ov2; h2i = oi2; }
            } else {
                if (ov1 > h2v || (ov1 == h2v && oi1 < h2i)) { h2v = ov1; h2i = oi1; }
            }
            float pv1 = __shfl_xor_sync(0xffffffffu, s1v, o);
            int   pi1 = __shfl_xor_sync(0xffffffffu, s1i, o);
            float pv2 = __shfl_xor_sync(0xffffffffu, s2v, o);
            int   pi2 = __shfl_xor_sync(0xffffffffu, s2i, o);
            if (pv1 > s1v || (pv1 == s1v && pi1 < s1i)) {
                float t1v = s1v; int t1i = s1i;
                s1v = pv1; s1i = pi1;
                if (t1v > pv2 || (t1v == pv2 && t1i < pi2)) { s2v = t1v; s2i = t1i; }
                else { s2v = pv2; s2i = pi2; }
            } else {
                if (pv1 > s2v || (pv1 == s2v && pi1 < s2i)) { s2v = pv1; s2i = pi1; }
            }
        }

        int cands[4] = {h1i, h2i, s1i, s2i};
        float ex[4];
        const float* curp = g_cur + (size_t)n*DD + lane*8;
        #pragma unroll
        for (int t = 0; t < 4; t++) {
            const float* Ep = emb + (size_t)cands[t]*DD + lane*8;
            float s = 0.f;
            #pragma unroll
            for (int j = 0; j < 8; j++) s += curp[j]*Ep[j];
            #pragma unroll
            for (int o = 16; o > 0; o >>= 1) s += __shfl_xor_sync(0xffffffffu, s, o);
            ex[t] = 2.f*s - g_esq[cands[t]];
        }

        float ssum = 0.f;
        #pragma unroll
        for (int ch = 0; ch < 8; ch++)
            #pragma unroll
            for (int j = 0; j < 4; j++) { float e = expf(dm[ch][j] - h1v); dm[ch][j] = e; ssum += e; }
        #pragma unroll
        for (int o = 16; o > 0; o >>= 1) ssum += __shfl_xor_sync(0xffffffffu, ssum, o);
        float inv = 1.f / ssum;
        #pragma unroll
        for (int ch = 0; ch < 8; ch++)
            #pragma unroll
            for (int j = 0; j < 4; j++) pAcc[ch][j] += dm[ch][j] * inv;

        if (lane == 0) {
            int kH = h1i; float vH = ex[0];
            if (ex[1] > vH || (ex[1] == vH && h2i < kH)) { kH = h2i; vH = ex[1]; }
            atomicAdd(&g_hist[kH], 1u);
            float sc0 = ex[2] + gumbel_of(Ur[s1i]);
            float sc1 = ex[3] + gumbel_of(Ur[s2i]);
            int kS = s1i;
            if (sc1 > sc0 || (sc1 == sc0 && s2i < s1i)) kS = s2i;
            g_idx[n] = kS;
            out[QSIZE + 2 + n] = (float)kS;
        }
    }
    #pragma unroll
    for (int ch = 0; ch < 8; ch++)
        #pragma unroll
        for (int j = 0; j < 4; j++) atomicAdd(&sAcc[ch*128 + lane*4 + j], pAcc[ch][j]);
    __syncthreads();
    for (int i = tid; i < MM; i += 256) atomicAdd(&g_avgp[i], sAcc[i]);
}

__global__ void k_finalize(float* __restrict__ out) {
    __shared__ float s1[MM];
    __shared__ float s2[MM];
    int m = threadIdx.x;
    float hp = (float)g_hist[m] * (1.f/(float)NN);
    float ap = g_avgp[m] * (1.f/(float)NN);
    s1[m] = -hp * log2f(hp + 1e-10f);
    s2[m] = -ap * log2f(ap + 1e-10f);
    __syncthreads();
    for (int s = 512; s > 0; s >>= 1) {
        if (m < s) { s1[m] += s1[m + s]; s2[m] += s2[m + s]; }
        __syncthreads();
    }
    if (m == 0) { out[QSIZE] = s1[0]; out[QSIZE + 1] = s2[0]; }
}

// ---------------- fuse2 on tensor cores (3xTF32, W materialized hi/lo) -------
#define F2_STG 2112   /* X 1088 + Wh 512 + Wl 512 */
#define F2_SMEMB (64*130*4)   /* transpose buffer dominates: 33280 >= 2*F2_STG*4 */

__global__ void __launch_bounds__(256) k_f2_tc(const float* __restrict__ a2p,
                                               float* __restrict__ out) {
    extern __shared__ float fs[];
    int tid = threadIdx.x, lane = tid & 31, warp = tid >> 5;
    int warpM = warp >> 2, warpN = warp & 3;
    int t0 = blockIdx.x*128, o0 = blockIdx.y*64, b = blockIdx.z;
    int ot0 = o0 >> 4;

    uint32_t sbase;
    asm("{ .reg .u64 t; cvta.to.shared.u64 t, %1; cvt.u32.u64 %0, t; }" : "=r"(sbase) : "l"(fs));

    auto issue = [&](int ic, int s) {
        const float* xp = g_ctxout + ((size_t)(b*DD + ic*8))*TT + t0;
        uint32_t xd = sbase + (uint32_t)((s*F2_STG)*4);
        {
            int row = tid >> 5, q = tid & 31;
            asm volatile("cp.async.cg.shared.global [%0], [%1], 16;"
                :: "r"(xd + (uint32_t)((row*136 + q*4)*4)), "l"(xp + (size_t)row*TT + q*4));
        }
        if (tid < 128) {
            const float* wp = g_w2shh + ((size_t)ic*16 + ot0)*128;
            uint32_t wd = sbase + (uint32_t)((s*F2_STG + 1088)*4);
            asm volatile("cp.async.cg.shared.global [%0], [%1], 16;"
                :: "r"(wd + (uint32_t)(tid*16)), "l"(wp + tid*4));
        } else {
            int t2 = tid - 128;
            const float* wp = g_w2shl + ((size_t)ic*16 + ot0)*128;
            uint32_t wd = sbase + (uint32_t)((s*F2_STG + 1600)*4);
            asm volatile("cp.async.cg.shared.global [%0], [%1], 16;"
                :: "r"(wd + (uint32_t)(t2*16)), "l"(wp + t2*4));
        }
        asm volatile("cp.async.commit_group;");
    };

    float c[2][4][4] = {};
    issue(0, 0);
    issue(1, 1);

    for (int ic = 0; ic < 32; ic++) {
        int s = ic & 1;
        if (ic < 31) { asm volatile("cp.async.wait_group 1;"); }
        else         { asm volatile("cp.async.wait_group 0;"); }
        __syncthreads();
        const float* XE = fs + s*F2_STG;
        const float* WEh = XE + 1088;
        const float* WEl = XE + 1600;
        int i0v = lane & 3, trow = lane >> 2;

        uint32_t ah[2][4], al[2][4];
        #pragma unroll
        for (int mf = 0; mf < 2; mf++) {
            float4 vh = *(const float4*)&WEh[(warpM*2 + mf)*128 + lane*4];
            float4 vl = *(const float4*)&WEl[(warpM*2 + mf)*128 + lane*4];
            ah[mf][0] = __float_as_uint(vh.x); ah[mf][1] = __float_as_uint(vh.y);
            ah[mf][2] = __float_as_uint(vh.z); ah[mf][3] = __float_as_uint(vh.w);
            al[mf][0] = __float_as_uint(vl.x); al[mf][1] = __float_as_uint(vl.y);
            al[mf][2] = __float_as_uint(vl.z); al[mf][3] = __float_as_uint(vl.w);
        }
        uint32_t bh[4][2], bl[4][2];
        #pragma unroll
        for (int nf = 0; nf < 4; nf++) {
            int toff = warpN*32 + nf*8 + trow;
            float b0 = XE[i0v*136 + toff];
            float b1 = XE[(i0v + 4)*136 + toff];
            SPLIT2(bh[nf][0], bl[nf][0], b0);
            SPLIT2(bh[nf][1], bl[nf][1], b1);
        }
        #pragma unroll
        for (int mf = 0; mf < 2; mf++) {
            #pragma unroll
            for (int nf = 0; nf < 4; nf++) {
                MMA8(c[mf][nf], ah[mf][0], ah[mf][1], ah[mf][2], ah[mf][3], bh[nf][0], bh[nf][1]);
                MMA8(c[mf][nf], ah[mf][0], ah[mf][1], ah[mf][2], ah[mf][3], bl[nf][0], bl[nf][1]);
                MMA8(c[mf][nf], al[mf][0], al[mf][1], al[mf][2], al[mf][3], bh[nf][0], bh[nf][1]);
            }
        }
        __syncthreads();
        if (ic + 2 < 32) issue(ic + 2, s);
    }

    #pragma unroll
    for (int mf = 0; mf < 2; mf++) {
        int r = warpM*32 + mf*16 + (lane >> 2);
        #pragma unroll
        for (int nf = 0; nf < 4; nf++) {
            int tg = warpN*32 + nf*8 + (lane & 3)*2;
            *(float2*)&fs[r*130 + tg]       = make_float2(c[mf][nf][0], c[mf][nf][1]);
            *(float2*)&fs[(r + 8)*130 + tg] = make_float2(c[mf][nf][2], c[mf][nf][3]);
        }
    }
    __syncthreads();
    float a2v = *a2p;
    int nl = tid >> 1, half = tid & 1;
    size_t n = (size_t)b*TT + t0 + nl;
    int mi = g_idx[n];
    const float* w2e = g_W2E + (size_t)mi*DD + o0 + half*32;
    float* op = out + n*DD + o0 + half*32;
    #pragma unroll
    for (int j = 0; j < 8; j++) {
        float4 w4 = *(const float4*)&w2e[j*4];
        float4 v;
        float u;
        u = fs[(half*32 + j*4 + 0)*130 + nl] + w4.x; v.x = (u >= 0.f) ? u : a2v*u;
        u = fs[(half*32 + j*4 + 1)*130 + nl] + w4.y; v.y = (u >= 0.f) ? u : a2v*u;
        u = fs[(half*32 + j*4 + 2)*130 + nl] + w4.z; v.z = (u >= 0.f) ? u : a2v*u;
        u = fs[(half*32 + j*4 + 3)*130 + nl] + w4.w; v.w = (u >= 0.f) ? u : a2v*u;
        *(float4*)&op[j*4] = v;
    }
}

// ---------------- launch -----------------------------------------------------
extern "C" void kernel_launch(void* const* d_in, const int* in_sizes, int n_in,
                              void* d_out, int out_size) {
    const float* x     = (const float*)d_in[0];
    const float* noise = (const float*)d_in[1];
    const float* gum   = (const float*)d_in[2];
    const int*   epo   = (const int*)  d_in[3];
    const float* emb   = (const float*)d_in[4];
    const float* wctx  = (const float*)d_in[5];
    const float* wf1   = (const float*)d_in[6];
    const float* a1    = (const float*)d_in[7];
    const float* wf2   = (const float*)d_in[8];
    const float* a2    = (const float*)d_in[9];
    float* out = (float*)d_out;

    cudaFuncSetAttribute(k_conv_tc, cudaFuncAttributeMaxDynamicSharedMemorySize, CV_SMEMB);
    cudaFuncSetAttribute(k_dist_b, cudaFuncAttributeMaxDynamicSharedMemorySize, DB_SMEMB);
    cudaFuncSetAttribute(k_f2_tc, cudaFuncAttributeMaxDynamicSharedMemorySize, F2_SMEMB);

    dim3 tb32(32, 8);

    k_scale<<<BB, 256>>>(x, epo);                                   // 0
    k_noisy<<<dim3((LL + 31)/32, DD/32, BB), tb32>>>(x, noise);     // 1
    k_splitw<<<DD*DD*CTX/256, 256>>>(wctx);                         // 2
    k_conv_tc<<<dim3(TT/128, 2, BB), 256, CV_SMEMB>>>(0);           // 3 <- capture
    k_conv_tc<<<dim3(TT/128, 2, BB), 256, CV_SMEMB>>>(128);         // 4
    k_xt<<<dim3(TT/32, DD/32, BB), tb32>>>(x);
    k_transp<<<dim3(2*DD/32, DD/32), tb32>>>(wf1, DD, 2*DD, 1);     // w1T
    k_f1<<<dim3(TT/64, DD/64, BB), 256>>>(a1);
    k_transp<<<dim3(DD/32, MM/32), tb32>>>(emb, MM, DD, 0);         // ET
    k_transp<<<dim3(2*DD/32, DD/32), tb32>>>(wf2, DD, 2*DD, 2);     // w2T
    k_esq<<<MM/8, 256>>>(emb);
    k_zero<<<4, 256>>>();
    k_split_eb<<<MM*DD/256, 256>>>(emb);
    k_shufw2<<<DD*DD/256, 256>>>(wf2);
    k_gemm_w2e<<<dim3(MM/64, DD/64), 256>>>();
    k_dist_b<<<dim3(NN/128, MM/128), 256, DB_SMEMB>>>(emb);
    k_rowstats<<<NN/128, 256>>>(gum, emb, out);
    k_finalize<<<1, MM>>>(out);
    k_f2_tc<<<dim3(TT/128, DD/64, BB), 256, F2_SMEMB>>>(a2, out);
}

// round 8
// speedup vs baseline: 1.1928x; 1.0345x over previous
#include <cuda_runtime.h>
#include <cuda_bf16.h>
#include <math.h>
#include <stdint.h>

#define BB 8
#define TT 4096
#define DD 256
#define MM 1024
#define CTX 7
#define LL (TT - 1 + CTX)      /* 4102 */
#define LLP 4104               /* padded stride */
#define NN (BB*TT)             /* 32768 */
#define QSIZE (NN*DD)          /* 8388608 */

// ---------------- scratch ----------------------------------------------------
__device__ __align__(16) float g_xt_hi[BB*DD*TT];
__device__ __align__(16) float g_xt_lo[BB*DD*TT];
__device__ __align__(16) float g_noisy_hi[BB*DD*LLP];
__device__ __align__(16) float g_noisy_lo[BB*DD*LLP];
__device__ __align__(16) float g_wch[DD*DD*CTX];        // w_ctx hi, A-frag shuffled
__device__ __align__(16) float g_wcl[DD*DD*CTX];
__device__ __align__(16) float g_w1shh[2*DD*DD];        // w_f1 hi, A-frag shuffled
__device__ __align__(16) float g_w1shl[2*DD*DD];
__device__ __align__(16) float g_w2shh[DD*DD];          // w_f2[:,256:] hi, shuffled
__device__ __align__(16) float g_w2shl[DD*DD];
__device__ __align__(16) float g_ctx_hi[BB*DD*TT];      // conv out hi [b][o][t]
__device__ __align__(16) float g_ctx_lo[BB*DD*TT];
__device__ __align__(16) float g_cur[(size_t)NN*DD];    // fuse1 out, exact fp32
__device__ __align__(16) __nv_bfloat16 g_cur_bh[(size_t)NN*DD];
__device__ __align__(16) __nv_bfloat16 g_cur_bl[(size_t)NN*DD];
__device__ __align__(16) __nv_bfloat16 g_E_bh[MM*DD];
__device__ __align__(16) __nv_bfloat16 g_E_bl[MM*DD];
__device__ __align__(16) float g_G[(size_t)NN*MM];
__device__ __align__(16) float g_ET[DD*MM];
__device__ __align__(16) float g_w2T[2*DD*DD];
__device__ __align__(16) float g_W2E[MM*DD];
__device__ __align__(16) float g_esq[MM];
__device__ float g_scale[BB];
__device__ int   g_idx[NN];
__device__ unsigned int g_hist[MM];
__device__ float g_avgp[MM];

__device__ __forceinline__ float tf32_hi(float v) {
    uint32_t b;
    asm("cvt.rna.tf32.f32 %0, %1;" : "=r"(b) : "f"(v));
    return __uint_as_float(b);
}

#define MMA8(d, a0,a1,a2,a3, b0,b1) \
    asm volatile("mma.sync.aligned.m16n8k8.row.col.f32.tf32.tf32.f32 " \
        "{%0,%1,%2,%3}, {%4,%5,%6,%7}, {%8,%9}, {%0,%1,%2,%3};" \
        : "+f"((d)[0]), "+f"((d)[1]), "+f"((d)[2]), "+f"((d)[3]) \
        : "r"(a0), "r"(a1), "r"(a2), "r"(a3), "r"(b0), "r"(b1))

#define MMA16B(d, a, b) \
    asm volatile("mma.sync.aligned.m16n8k16.row.col.f32.bf16.bf16.f32 " \
        "{%0,%1,%2,%3}, {%4,%5,%6,%7}, {%8,%9}, {%0,%1,%2,%3};" \
        : "+f"((d)[0]), "+f"((d)[1]), "+f"((d)[2]), "+f"((d)[3]) \
        : "r"((a)[0]), "r"((a)[1]), "r"((a)[2]), "r"((a)[3]), "r"((b)[0]), "r"((b)[1]))

// ---------------- small utility kernels -------------------------------------
__global__ void k_zero() {
    int i = blockIdx.x*blockDim.x + threadIdx.x;
    if (i < MM) { g_hist[i] = 0u; g_avgp[i] = 0.f; }
}

__global__ void k_transp(const float* __restrict__ src, int rows, int cols, int which) {
    __shared__ float s[32][33];
    float* dst = (which == 0) ? g_ET : g_w2T;
    int c0 = blockIdx.x*32, r0 = blockIdx.y*32;
    int tx = threadIdx.x, ty = threadIdx.y;
    #pragma unroll
    for (int j = 0; j < 4; j++) {
        int r = r0 + ty + j*8, c = c0 + tx;
        s[ty + j*8][tx] = (r < rows && c < cols) ? src[(size_t)r*cols + c] : 0.f;
    }
    __syncthreads();
    #pragma unroll
    for (int j = 0; j < 4; j++) {
        int c = c0 + ty + j*8, r = r0 + tx;
        if (c < cols && r < rows) dst[(size_t)c*rows + r] = s[tx][ty + j*8];
    }
}

__global__ void k_esq(const float* __restrict__ E) {
    int warp = threadIdx.x >> 5, lane = threadIdx.x & 31;
    int m = blockIdx.x*8 + warp;
    const float* row = E + (size_t)m*DD;
    float s = 0.f;
    for (int c = lane; c < DD; c += 32) { float v = row[c]; s += v*v; }
    #pragma unroll
    for (int o = 16; o > 0; o >>= 1) s += __shfl_down_sync(0xffffffffu, s, o);
    if (lane == 0) g_esq[m] = s;
}

__global__ void k_split_eb(const float* __restrict__ E) {
    int i = blockIdx.x*256 + threadIdx.x;
    float v = E[i];
    __nv_bfloat16 h = __float2bfloat16(v);
    g_E_bh[i] = h;
    g_E_bl[i] = __float2bfloat16(v - __bfloat162float(h));
}

// w_ctx -> tf32 hi/lo, A-fragment-shuffled
__global__ void k_splitw(const float* __restrict__ wctx) {
    int idx = blockIdx.x*256 + threadIdx.x;       // grid 1792
    int o = idx / (DD*CTX);
    int rem = idx - o*(DD*CTX);
    int i = rem / CTX, kk = rem - i*CTX;
    float v = wctx[idx];
    float h = tf32_hi(v);
    int ic = i >> 3, il = i & 7;
    int otile = o >> 4, oloc = o & 15;
    int lane = (oloc & 7)*4 + (il & 3);
    int reg = (oloc >> 3) + 2*(il >> 2);
    int d = ((ic*7 + kk)*16 + otile)*128 + lane*4 + reg;
    g_wch[d] = h;
    g_wcl[d] = tf32_hi(v - h);
}

// w_f1 -> tf32 hi/lo, A-fragment-shuffled; w_f1[o][k], o<256, k<512
__global__ void k_splitw1(const float* __restrict__ wf1) {
    int idx = blockIdx.x*256 + threadIdx.x;       // grid 512
    int o = idx >> 9, k = idx & 511;
    float v = wf1[idx];
    float h = tf32_hi(v);
    int ks = k >> 3, il = k & 7;
    int otile = o >> 4, oloc = o & 15;
    int lane = (oloc & 7)*4 + (il & 3);
    int reg = (oloc >> 3) + 2*(il >> 2);
    int d = (ks*16 + otile)*128 + lane*4 + reg;
    g_w1shh[d] = h;
    g_w1shl[d] = tf32_hi(v - h);
}

// w_f2[:,256:512] -> tf32 hi/lo, shuffled
__global__ void k_shufw2(const float* __restrict__ wf2) {
    int idx = blockIdx.x*256 + threadIdx.x;       // grid 256
    int o = idx >> 8, k = idx & 255;
    int ic = k >> 3, il = k & 7;
    int otile = o >> 4, oloc = o & 15;
    int lane = (oloc & 7)*4 + (il & 3);
    int reg = (oloc >> 3) + 2*(il >> 2);
    float v = wf2[o*2*DD + DD + k];
    float h = tf32_hi(v);
    int d = (ic*16 + otile)*128 + lane*4 + reg;
    g_w2shh[d] = h;
    g_w2shl[d] = tf32_hi(v - h);
}

__global__ void k_scale(const float* __restrict__ x, const int* __restrict__ epo_p) {
    int b = blockIdx.x;
    const float* xb = x + (size_t)b*TT*DD;
    float s = 0.f;
    int tot = (TT-1)*DD;
    for (int i = threadIdx.x; i < tot; i += blockDim.x) { float v = xb[i]; s += v*v; }
    __shared__ float sm[8];
    #pragma unroll
    for (int o = 16; o > 0; o >>= 1) s += __shfl_down_sync(0xffffffffu, s, o);
    if ((threadIdx.x & 31) == 0) sm[threadIdx.x >> 5] = s;
    __syncthreads();
    if (threadIdx.x == 0) {
        float t = 0.f;
        for (int w = 0; w < 8; w++) t += sm[w];
        int iv = epo_p[0];
        float ef = (iv >= 0 && iv < 100000) ? (float)iv : __int_as_float(iv);
        float sc = sqrtf(t / (float)(DD*LL));
        g_scale[b] = 0.5f * sc * exp2f(-ef * 0.1f);
    }
}

// x -> xt hi/lo [b][d][t]
__global__ void k_xt(const float* __restrict__ x) {
    __shared__ float s[32][33];
    int b = blockIdx.z, t0 = blockIdx.x*32, d0 = blockIdx.y*32;
    int tx = threadIdx.x, ty = threadIdx.y;
    #pragma unroll
    for (int j = 0; j < 4; j++) {
        int t = t0 + ty + j*8;
        s[ty + j*8][tx] = x[((size_t)b*TT + t)*DD + d0 + tx];
    }
    __syncthreads();
    #pragma unroll
    for (int j = 0; j < 4; j++) {
        int d = d0 + ty + j*8;
        float v = s[tx][ty + j*8];
        float h = tf32_hi(v);
        size_t off = ((size_t)b*DD + d)*TT + t0 + tx;
        g_xt_hi[off] = h;
        g_xt_lo[off] = tf32_hi(v - h);
    }
}

__global__ void k_noisy(const float* __restrict__ x, const float* __restrict__ noise) {
    __shared__ float s[32][33];
    int b = blockIdx.z, l0 = blockIdx.x*32, i0 = blockIdx.y*32;
    int tx = threadIdx.x, ty = threadIdx.y;
    float coef = g_scale[b];
    #pragma unroll
    for (int j = 0; j < 4; j++) {
        int row = ty + j*8;
        int t = l0 + row - CTX;
        float v = (t >= 0 && t < TT-1) ? x[((size_t)b*TT + t)*DD + i0 + tx] : 0.f;
        s[row][tx] = v;
    }
    __syncthreads();
    #pragma unroll
    for (int j = 0; j < 4; j++) {
        int i = i0 + ty + j*8, l = l0 + tx;
        if (l < LL) {
            float v = s[tx][ty + j*8] + coef * noise[((size_t)b*DD + i)*LL + l];
            float h = tf32_hi(v);
            size_t off = ((size_t)b*DD + i)*LLP + l;
            g_noisy_hi[off] = h;
            g_noisy_lo[off] = tf32_hi(v - h);
        }
    }
}

// ---------------- conv (3xTF32, materialized hi/lo) --------------------------
#define CV_STG 9344
#define CV_SMEMB (2*CV_STG*4)

__global__ void __launch_bounds__(256, 2) k_conv_tc(int obase) {
    extern __shared__ float cs[];
    int tid = threadIdx.x, lane = tid & 31, warp = tid >> 5;
    int warpM = warp >> 2, warpN = warp & 3;
    int t0 = blockIdx.x*128, o0 = obase + blockIdx.y*64, b = blockIdx.z;
    int ot0 = o0 >> 4;

    uint32_t sbase;
    asm("{ .reg .u64 t; cvta.to.shared.u64 t, %1; cvt.u32.u64 %0, t; }" : "=r"(sbase) : "l"(cs));

    auto issue = [&](int ic, int s) {
        const float* xh = g_noisy_hi + ((size_t)(b*DD + ic*8))*LLP + t0;
        const float* xl = g_noisy_lo + ((size_t)(b*DD + ic*8))*LLP + t0;
        uint32_t xdh = sbase + (uint32_t)((s*CV_STG)*4);
        uint32_t xdl = xdh + 1088*4;
        for (int idx = tid; idx < 272; idx += 256) {
            int row = idx / 34, q = idx - row*34;
            asm volatile("cp.async.cg.shared.global [%0], [%1], 16;"
                :: "r"(xdh + (uint32_t)((row*136 + q*4)*4)), "l"(xh + (size_t)row*LLP + q*4));
            asm volatile("cp.async.cg.shared.global [%0], [%1], 16;"
                :: "r"(xdl + (uint32_t)((row*136 + q*4)*4)), "l"(xl + (size_t)row*LLP + q*4));
        }
        const float* wh = g_wch + ((size_t)(ic*7)*16 + ot0)*128;
        const float* wl = g_wcl + ((size_t)(ic*7)*16 + ot0)*128;
        uint32_t wdh = sbase + (uint32_t)((s*CV_STG + 2176)*4);
        uint32_t wdl = wdh + 3584*4;
        for (int idx = tid; idx < 896; idx += 256) {
            int kk = idx >> 7, q = idx & 127;
            asm volatile("cp.async.cg.shared.global [%0], [%1], 16;"
                :: "r"(wdh + (uint32_t)((kk*512 + q*4)*4)), "l"(wh + kk*2048 + q*4));
            asm volatile("cp.async.cg.shared.global [%0], [%1], 16;"
                :: "r"(wdl + (uint32_t)((kk*512 + q*4)*4)), "l"(wl + kk*2048 + q*4));
        }
        asm volatile("cp.async.commit_group;");
    };

    float c[2][4][4] = {};
    issue(0, 0);
    issue(1, 1);

    for (int ic = 0; ic < 32; ic++) {
        int s = ic & 1;
        if (ic < 31) { asm volatile("cp.async.wait_group 1;"); }
        else         { asm volatile("cp.async.wait_group 0;"); }
        __syncthreads();
        const float* XH = cs + s*CV_STG;
        const float* XL = XH + 1088;
        const float* WH = XH + 2176;
        const float* WL = XH + 5760;
        int i0v = lane & 3, trow = lane >> 2;

        #pragma unroll
        for (int kk = 0; kk < 7; kk++) {
            uint32_t ah[2][4], al[2][4];
            #pragma unroll
            for (int mf = 0; mf < 2; mf++) {
                float4 vh = *(const float4*)&WH[kk*512 + (warpM*2 + mf)*128 + lane*4];
                float4 vl = *(const float4*)&WL[kk*512 + (warpM*2 + mf)*128 + lane*4];
                ah[mf][0] = __float_as_uint(vh.x); ah[mf][1] = __float_as_uint(vh.y);
                ah[mf][2] = __float_as_uint(vh.z); ah[mf][3] = __float_as_uint(vh.w);
                al[mf][0] = __float_as_uint(vl.x); al[mf][1] = __float_as_uint(vl.y);
                al[mf][2] = __float_as_uint(vl.z); al[mf][3] = __float_as_uint(vl.w);
            }
            uint32_t bh[4][2], bl[4][2];
            #pragma unroll
            for (int nf = 0; nf < 4; nf++) {
                int toff = warpN*32 + nf*8 + trow + kk;
                bh[nf][0] = __float_as_uint(XH[i0v*136 + toff]);
                bh[nf][1] = __float_as_uint(XH[(i0v + 4)*136 + toff]);
                bl[nf][0] = __float_as_uint(XL[i0v*136 + toff]);
                bl[nf][1] = __float_as_uint(XL[(i0v + 4)*136 + toff]);
            }
            #pragma unroll
            for (int mf = 0; mf < 2; mf++) {
                #pragma unroll
                for (int nf = 0; nf < 4; nf++) {
                    MMA8(c[mf][nf], ah[mf][0], ah[mf][1], ah[mf][2], ah[mf][3], bh[nf][0], bh[nf][1]);
                    MMA8(c[mf][nf], ah[mf][0], ah[mf][1], ah[mf][2], ah[mf][3], bl[nf][0], bl[nf][1]);
                    MMA8(c[mf][nf], al[mf][0], al[mf][1], al[mf][2], al[mf][3], bh[nf][0], bh[nf][1]);
                }
            }
        }
        __syncthreads();
        if (ic + 2 < 32) issue(ic + 2, s);
    }

    // epilogue: write ctxout as tf32 hi/lo
    #pragma unroll
    for (int mf = 0; mf < 2; mf++) {
        int r = o0 + warpM*32 + mf*16 + (lane >> 2);
        #pragma unroll
        for (int nf = 0; nf < 4; nf++) {
            int tg = t0 + warpN*32 + nf*8 + (lane & 3)*2;
            float v0 = c[mf][nf][0], v1 = c[mf][nf][1];
            float v2 = c[mf][nf][2], v3 = c[mf][nf][3];
            float h0 = tf32_hi(v0), h1 = tf32_hi(v1), h2 = tf32_hi(v2), h3 = tf32_hi(v3);
            size_t o1 = ((size_t)b*DD + r)*TT + tg;
            size_t o2 = ((size_t)b*DD + r + 8)*TT + tg;
            *(float2*)&g_ctx_hi[o1] = make_float2(h0, h1);
            *(float2*)&g_ctx_lo[o1] = make_float2(tf32_hi(v0 - h0), tf32_hi(v1 - h1));
            *(float2*)&g_ctx_hi[o2] = make_float2(h2, h3);
            *(float2*)&g_ctx_lo[o2] = make_float2(tf32_hi(v2 - h2), tf32_hi(v3 - h3));
        }
    }
}

// ---------------- fuse1 on tensor cores (3xTF32) -----------------------------
// cur[t][o] = prelu(sum_k w1[o][k]*cat[k][t]); K=512, chunk 16 (2 k8 slices)
#define F1_STG 6400   /* XH 2176 + XL 2176 + WH 1024 + WL 1024 */
#define F1_SMEMB (2*F1_STG*4)   /* 51200 */

__global__ void __launch_bounds__(256, 2) k_f1_tc(const float* __restrict__ a1p) {
    extern __shared__ float fs[];
    int tid = threadIdx.x, lane = tid & 31, warp = tid >> 5;
    int warpM = warp >> 2, warpN = warp & 3;
    int t0 = blockIdx.x*128, o0 = blockIdx.y*64, b = blockIdx.z;
    int ot0 = o0 >> 4;

    uint32_t sbase;
    asm("{ .reg .u64 t; cvta.to.shared.u64 t, %1; cvt.u32.u64 %0, t; }" : "=r"(sbase) : "l"(fs));

    auto issue = [&](int cchunk, int s) {
        uint32_t xdh = sbase + (uint32_t)((s*F1_STG)*4);
        uint32_t xdl = xdh + 2176*4;
        #pragma unroll
        for (int j = 0; j < 2; j++) {
            int idx = tid + j*256;           // 512 chunks per array
            int row = idx >> 5, q = idx & 31;
            int d = cchunk*16 + row;
            const float* sh = (d < DD) ? (g_xt_hi + ((size_t)b*DD + d)*TT + t0)
                                       : (g_ctx_hi + ((size_t)b*DD + d - DD)*TT + t0);
            const float* sl = (d < DD) ? (g_xt_lo + ((size_t)b*DD + d)*TT + t0)
                                       : (g_ctx_lo + ((size_t)b*DD + d - DD)*TT + t0);
            asm volatile("cp.async.cg.shared.global [%0], [%1], 16;"
                :: "r"(xdh + (uint32_t)((row*136 + q*4)*4)), "l"(sh + q*4));
            asm volatile("cp.async.cg.shared.global [%0], [%1], 16;"
                :: "r"(xdl + (uint32_t)((row*136 + q*4)*4)), "l"(sl + q*4));
        }
        const float* wh = g_w1shh + ((size_t)(cchunk*2)*16 + ot0)*128;
        const float* wl = g_w1shl + ((size_t)(cchunk*2)*16 + ot0)*128;
        uint32_t wdh = sbase + (uint32_t)((s*F1_STG + 4352)*4);
        uint32_t wdl = wdh + 1024*4;
        {
            int sl8 = tid >> 7, q = tid & 127;
            asm volatile("cp.async.cg.shared.global [%0], [%1], 16;"
                :: "r"(wdh + (uint32_t)(tid*16)), "l"(wh + sl8*2048 + q*4));
            asm volatile("cp.async.cg.shared.global [%0], [%1], 16;"
                :: "r"(wdl + (uint32_t)(tid*16)), "l"(wl + sl8*2048 + q*4));
        }
        asm volatile("cp.async.commit_group;");
    };

    float c[2][4][4] = {};
    issue(0, 0);
    issue(1, 1);

    for (int cc = 0; cc < 32; cc++) {
        int s = cc & 1;
        if (cc < 31) { asm volatile("cp.async.wait_group 1;"); }
        else         { asm volatile("cp.async.wait_group 0;"); }
        __syncthreads();
        const float* XH = fs + s*F1_STG;
        const float* XL = XH + 2176;
        const float* WH = XH + 4352;
        const float* WL = XH + 5376;
        int i0v = lane & 3, trow = lane >> 2;

        #pragma unroll
        for (int sl8 = 0; sl8 < 2; sl8++) {
            uint32_t ah[2][4], al[2][4];
            #pragma unroll
            for (int mf = 0; mf < 2; mf++) {
                float4 vh = *(const float4*)&WH[sl8*512 + (warpM*2 + mf)*128 + lane*4];
                float4 vl = *(const float4*)&WL[sl8*512 + (warpM*2 + mf)*128 + lane*4];
                ah[mf][0] = __float_as_uint(vh.x); ah[mf][1] = __float_as_uint(vh.y);
                ah[mf][2] = __float_as_uint(vh.z); ah[mf][3] = __float_as_uint(vh.w);
                al[mf][0] = __float_as_uint(vl.x); al[mf][1] = __float_as_uint(vl.y);
                al[mf][2] = __float_as_uint(vl.z); al[mf][3] = __float_as_uint(vl.w);
            }
            uint32_t bh[4][2], bl[4][2];
            #pragma unroll
            for (int nf = 0; nf < 4; nf++) {
                int toff = warpN*32 + nf*8 + trow;
                int rbase = sl8*8 + i0v;
                bh[nf][0] = __float_as_uint(XH[rbase*136 + toff]);
                bh[nf][1] = __float_as_uint(XH[(rbase + 4)*136 + toff]);
                bl[nf][0] = __float_as_uint(XL[rbase*136 + toff]);
                bl[nf][1] = __float_as_uint(XL[(rbase + 4)*136 + toff]);
            }
            #pragma unroll
            for (int mf = 0; mf < 2; mf++) {
                #pragma unroll
                for (int nf = 0; nf < 4; nf++) {
                    MMA8(c[mf][nf], ah[mf][0], ah[mf][1], ah[mf][2], ah[mf][3], bh[nf][0], bh[nf][1]);
                    MMA8(c[mf][nf], ah[mf][0], ah[mf][1], ah[mf][2], ah[mf][3], bl[nf][0], bl[nf][1]);
                    MMA8(c[mf][nf], al[mf][0], al[mf][1], al[mf][2], al[mf][3], bh[nf][0], bh[nf][1]);
                }
            }
        }
        __syncthreads();
        if (cc + 2 < 32) issue(cc + 2, s);
    }

    // epilogue: prelu -> smem transpose -> write cur exact + bf16 hi/lo
    float a1 = *a1p;
    #pragma unroll
    for (int mf = 0; mf < 2; mf++) {
        int r = warpM*32 + mf*16 + (lane >> 2);
        #pragma unroll
        for (int nf = 0; nf < 4; nf++) {
            int tg = warpN*32 + nf*8 + (lane & 3)*2;
            float v0 = c[mf][nf][0]; v0 = (v0 >= 0.f) ? v0 : a1*v0;
            float v1 = c[mf][nf][1]; v1 = (v1 >= 0.f) ? v1 : a1*v1;
            float v2 = c[mf][nf][2]; v2 = (v2 >= 0.f) ? v2 : a1*v2;
            float v3 = c[mf][nf][3]; v3 = (v3 >= 0.f) ? v3 : a1*v3;
            *(float2*)&fs[r*130 + tg]       = make_float2(v0, v1);
            *(float2*)&fs[(r + 8)*130 + tg] = make_float2(v2, v3);
        }
    }
    __syncthreads();
    int nl = tid >> 1, half = tid & 1;
    size_t n = (size_t)b*TT + t0 + nl;
    float* cp = g_cur + n*DD + o0 + half*32;
    __nv_bfloat16* bhp = g_cur_bh + n*DD + o0 + half*32;
    __nv_bfloat16* blp = g_cur_bl + n*DD + o0 + half*32;
    #pragma unroll
    for (int j = 0; j < 8; j++) {
        float4 v;
        v.x = fs[(half*32 + j*4 + 0)*130 + nl];
        v.y = fs[(half*32 + j*4 + 1)*130 + nl];
        v.z = fs[(half*32 + j*4 + 2)*130 + nl];
        v.w = fs[(half*32 + j*4 + 3)*130 + nl];
        *(float4*)&cp[j*4] = v;
        float vv[4] = {v.x, v.y, v.z, v.w};
        __nv_bfloat16 bh4[4], bl4[4];
        #pragma unroll
        for (int q = 0; q < 4; q++) {
            bh4[q] = __float2bfloat16(vv[q]);
            bl4[q] = __float2bfloat16(vv[q] - __bfloat162float(bh4[q]));
        }
        *(uint2*)&bhp[j*4] = *(uint2*)bh4;
        *(uint2*)&blp[j*4] = *(uint2*)bl4;
    }
}

// ---------------- W2E GEMM (small) -------------------------------------------
__global__ void __launch_bounds__(256) k_gemm_w2e() {
    __shared__ float sA[16][68];
    __shared__ float sB[16][68];
    int i0 = blockIdx.x*64, j0 = blockIdx.y*64;
    int tid = threadIdx.x;
    int tx = tid & 15, ty = tid >> 4;
    int kl = tid >> 4, nl4 = (tid & 15)*4;
    float acc[4][4] = {};
    for (int kc = 0; kc < DD; kc += 16) {
        *(float4*)&sA[kl][nl4] = *(const float4*)(g_ET  + (size_t)(kc + kl)*MM + i0 + nl4);
        *(float4*)&sB[kl][nl4] = *(const float4*)(g_w2T + (size_t)(kc + kl)*DD + j0 + nl4);
        __syncthreads();
        #pragma unroll
        for (int k = 0; k < 16; k++) {
            float4 av = *(const float4*)&sA[k][4*tx];
            float4 bv = *(const float4*)&sB[k][4*ty];
            float ar[4] = {av.x, av.y, av.z, av.w};
            float br[4] = {bv.x, bv.y, bv.z, bv.w};
            #pragma unroll
            for (int a = 0; a < 4; a++)
                #pragma unroll
                for (int cc = 0; cc < 4; cc++)
                    acc[a][cc] += br[a] * ar[cc];
        }
        __syncthreads();
    }
    #pragma unroll
    for (int cc = 0; cc < 4; cc++) {
        int i = i0 + 4*tx + cc;
        float4 v = make_float4(acc[0][cc], acc[1][cc], acc[2][cc], acc[3][cc]);
        *(float4*)&g_W2E[(size_t)i*DD + j0 + 4*ty] = v;
    }
}

// ---------------- dist GEMM via mma.sync bf16 (3xBF16, k16) ------------------
#define DB_ROWW 20
#define DB_ARRW (128*DB_ROWW)
#define DB_STGW (4*DB_ARRW)
#define DB_SMEMB (2*DB_STGW*4)

__global__ void __launch_bounds__(256, 2) k_dist_b() {
    extern __shared__ uint32_t dsm[];
    int tid = threadIdx.x, lane = tid & 31, warp = tid >> 5;
    int warpM = warp >> 2, warpN = warp & 3;
    int n0 = blockIdx.x*128, m0 = blockIdx.y*128;

    uint32_t sbase;
    asm("{ .reg .u64 t; cvta.to.shared.u64 t, %1; cvt.u32.u64 %0, t; }" : "=r"(sbase) : "l"(dsm));

    const __nv_bfloat16* srcs[4] = {
        g_cur_bh + (size_t)n0*DD, g_cur_bl + (size_t)n0*DD,
        g_E_bh   + (size_t)m0*DD, g_E_bl   + (size_t)m0*DD };

    auto issue = [&](int kc, int s) {
        #pragma unroll
        for (int a = 0; a < 4; a++) {
            uint32_t dstb = sbase + (uint32_t)((s*DB_STGW + a*DB_ARRW)*4);
            #pragma unroll
            for (int j = 0; j < 2; j++) {
                int cid = tid + j*256;
                int row = cid >> 2, q = cid & 3;
                uint32_t dst = dstb + (uint32_t)(row*80 + q*16);
                const __nv_bfloat16* src = srcs[a] + (size_t)row*DD + kc + q*8;
                asm volatile("cp.async.cg.shared.global [%0], [%1], 16;"
                             :: "r"(dst), "l"(src));
            }
        }
        asm volatile("cp.async.commit_group;");
    };

    float c[4][4][4] = {};
    issue(0, 0);

    int gr = lane >> 2, lc = lane & 3;
    for (int it = 0; it < 8; it++) {
        int s = it & 1;
        if (it + 1 < 8) issue((it + 1)*32, s ^ 1);
        if (it + 1 < 8) { asm volatile("cp.async.wait_group 1;"); }
        else            { asm volatile("cp.async.wait_group 0;"); }
        __syncthreads();

        const uint32_t* sAh = dsm + s*DB_STGW;
        const uint32_t* sAl = sAh + DB_ARRW;
        const uint32_t* sBh = sAh + 2*DB_ARRW;
        const uint32_t* sBl = sAh + 3*DB_ARRW;

        #pragma unroll
        for (int ks = 0; ks < 2; ks++) {
            int wb = ks*8 + lc;
            uint32_t ah[4][4], al[4][4], bh[4][2], bl[4][2];
            #pragma unroll
            for (int mf = 0; mf < 4; mf++) {
                int r1 = (warpM*64 + mf*16 + gr)*DB_ROWW, r2 = r1 + 8*DB_ROWW;
                ah[mf][0] = sAh[r1 + wb];     ah[mf][1] = sAh[r2 + wb];
                ah[mf][2] = sAh[r1 + wb + 4]; ah[mf][3] = sAh[r2 + wb + 4];
                al[mf][0] = sAl[r1 + wb];     al[mf][1] = sAl[r2 + wb];
                al[mf][2] = sAl[r1 + wb + 4]; al[mf][3] = sAl[r2 + wb + 4];
            }
            #pragma unroll
            for (int nf = 0; nf < 4; nf++) {
                int rn = (warpN*32 + nf*8 + gr)*DB_ROWW;
                bh[nf][0] = sBh[rn + wb]; bh[nf][1] = sBh[rn + wb + 4];
                bl[nf][0] = sBl[rn + wb]; bl[nf][1] = sBl[rn + wb + 4];
            }
            #pragma unroll
            for (int mf = 0; mf < 4; mf++) {
                #pragma unroll
                for (int nf = 0; nf < 4; nf++) {
                    MMA16B(c[mf][nf], ah[mf], bh[nf]);
                    MMA16B(c[mf][nf], ah[mf], bl[nf]);
                    MMA16B(c[mf][nf], al[mf], bh[nf]);
                }
            }
        }
        __syncthreads();
    }

    #pragma unroll
    for (int mf = 0; mf < 4; mf++) {
        int r1 = n0 + warpM*64 + mf*16 + gr;
        #pragma unroll
        for (int nf = 0; nf < 4; nf++) {
            int gc = m0 + warpN*32 + nf*8 + lc*2;
            *(float2*)&g_G[(size_t)r1*MM + gc]       = make_float2(c[mf][nf][0], c[mf][nf][1]);
            *(float2*)&g_G[(size_t)(r1 + 8)*MM + gc] = make_float2(c[mf][nf][2], c[mf][nf][3]);
        }
    }
}

// ---------------- per-row stats with exact top-2 refinement -----------------
__device__ __forceinline__ float gumbel_of(float u) {
    u = fminf(fmaxf(u, 1e-10f), 1.f - 1e-7f);
    return -logf(-logf(u));
}

__global__ void __launch_bounds__(256) k_rowstats(const float* __restrict__ gum,
                                                  const float* __restrict__ emb,
                                                  float* __restrict__ out) {
    __shared__ float sAcc[MM];
    int tid = threadIdx.x, wid = tid >> 5, lane = tid & 31;
    for (int i = tid; i < MM; i += 256) sAcc[i] = 0.f;
    __syncthreads();

    float esq_r[8][4];
    #pragma unroll
    for (int ch = 0; ch < 8; ch++) {
        float4 v = *(const float4*)&g_esq[ch*128 + lane*4];
        esq_r[ch][0] = v.x; esq_r[ch][1] = v.y; esq_r[ch][2] = v.z; esq_r[ch][3] = v.w;
    }
    float pAcc[8][4] = {};
    int nbase = blockIdx.x*128 + wid*16;

    for (int r = 0; r < 16; r++) {
        int n = nbase + r;
        const float* Gr = g_G + (size_t)n*MM;
        const float* Ur = gum + (size_t)n*MM;
        float dm[8][4];
        float h1v = -3.4e38f, h2v = -3.4e38f; int h1i = 0x7fffffff, h2i = 0x7fffffff;
        float s1v = -3.4e38f, s2v = -3.4e38f; int s1i = 0x7fffffff, s2i = 0x7fffffff;
        #pragma unroll
        for (int ch = 0; ch < 8; ch++) {
            float4 g4 = *(const float4*)&Gr[ch*128 + lane*4];
            float4 u4 = *(const float4*)&Ur[ch*128 + lane*4];
            float gg[4] = {g4.x, g4.y, g4.z, g4.w};
            float uu[4] = {u4.x, u4.y, u4.z, u4.w};
            #pragma unroll
            for (int j = 0; j < 4; j++) {
                int m = ch*128 + lane*4 + j;
                float d = 2.f*gg[j] - esq_r[ch][j];
                dm[ch][j] = d;
                if (d > h1v || (d == h1v && m < h1i)) { h2v = h1v; h2i = h1i; h1v = d; h1i = m; }
                else if (d > h2v || (d == h2v && m < h2i)) { h2v = d; h2i = m; }
                float sc = d + gumbel_of(uu[j]);
                if (sc > s1v || (sc == s1v && m < s1i)) { s2v = s1v; s2i = s1i; s1v = sc; s1i = m; }
                else if (sc > s2v || (sc == s2v && m < s2i)) { s2v = sc; s2i = m; }
            }
        }
        #pragma unroll
        for (int o = 16; o > 0; o >>= 1) {
            float ov1 = __shfl_xor_sync(0xffffffffu, h1v, o);
            int   oi1 = __shfl_xor_sync(0xffffffffu, h1i, o);
            float ov2 = __shfl_xor_sync(0xffffffffu, h2v, o);
            int   oi2 = __shfl_xor_sync(0xffffffffu, h2i, o);
            if (ov1 > h1v || (ov1 == h1v && oi1 < h1i)) {
                float t1v = h1v; int t1i = h1i;
                h1v = ov1; h1i = oi1;
                if (t1v > ov2 || (t1v == ov2 && t1i < oi2)) { h2v = t1v; h2i = t1i; }
                else { h2v = ov2; h2i = oi2; }
            } else {
                if (ov1 > h2v || (ov1 == h2v && oi1 < h2i)) { h2v = ov1; h2i = oi1; }
            }
            float pv1 = __shfl_xor_sync(0xffffffffu, s1v, o);
            int   pi1 = __shfl_xor_sync(0xffffffffu, s1i, o);
            float pv2 = __shfl_xor_sync(0xffffffffu, s2v, o);
            int   pi2 = __shfl_xor_sync(0xffffffffu, s2i, o);
            if (pv1 > s1v || (pv1 == s1v && pi1 < s1i)) {
                float t1v = s1v; int t1i = s1i;
                s1v = pv1; s1i = pi1;
                if (t1v > pv2 || (t1v == pv2 && t1i < pi2)) { s2v = t1v; s2i = t1i; }
                else { s2v = pv2; s2i = pi2; }
            } else {
                if (pv1 > s2v || (pv1 == s2v && pi1 < s2i)) { s2v = pv1; s2i = pi1; }
            }
        }

        int cands[4] = {h1i, h2i, s1i, s2i};
        float ex[4];
        const float* curp = g_cur + (size_t)n*DD + lane*8;
        #pragma unroll
        for (int t = 0; t < 4; t++) {
            const float* Ep = emb + (size_t)cands[t]*DD + lane*8;
            float s = 0.f;
            #pragma unroll
            for (int j = 0; j < 8; j++) s += curp[j]*Ep[j];
            #pragma unroll
            for (int o = 16; o > 0; o >>= 1) s += __shfl_xor_sync(0xffffffffu, s, o);
            ex[t] = 2.f*s - g_esq[cands[t]];
        }

        float ssum = 0.f;
        #pragma unroll
        for (int ch = 0; ch < 8; ch++)
            #pragma unroll
            for (int j = 0; j < 4; j++) { float e = expf(dm[ch][j] - h1v); dm[ch][j] = e; ssum += e; }
        #pragma unroll
        for (int o = 16; o > 0; o >>= 1) ssum += __shfl_xor_sync(0xffffffffu, ssum, o);
        float inv = 1.f / ssum;
        #pragma unroll
        for (int ch = 0; ch < 8; ch++)
            #pragma unroll
            for (int j = 0; j < 4; j++) pAcc[ch][j] += dm[ch][j] * inv;

        if (lane == 0) {
            int kH = h1i; float vH = ex[0];
            if (ex[1] > vH || (ex[1] == vH && h2i < kH)) { kH = h2i; vH = ex[1]; }
            atomicAdd(&g_hist[kH], 1u);
            float sc0 = ex[2] + gumbel_of(Ur[s1i]);
            float sc1 = ex[3] + gumbel_of(Ur[s2i]);
            int kS = s1i;
            if (sc1 > sc0 || (sc1 == sc0 && s2i < s1i)) kS = s2i;
            g_idx[n] = kS;
            out[QSIZE + 2 + n] = (float)kS;
        }
    }
    #pragma unroll
    for (int ch = 0; ch < 8; ch++)
        #pragma unroll
        for (int j = 0; j < 4; j++) atomicAdd(&sAcc[ch*128 + lane*4 + j], pAcc[ch][j]);
    __syncthreads();
    for (int i = tid; i < MM; i += 256) atomicAdd(&g_avgp[i], sAcc[i]);
}

__global__ void k_finalize(float* __restrict__ out) {
    __shared__ float s1[MM];
    __shared__ float s2[MM];
    int m = threadIdx.x;
    float hp = (float)g_hist[m] * (1.f/(float)NN);
    float ap = g_avgp[m] * (1.f/(float)NN);
    s1[m] = -hp * log2f(hp + 1e-10f);
    s2[m] = -ap * log2f(ap + 1e-10f);
    __syncthreads();
    for (int s = 512; s > 0; s >>= 1) {
        if (m < s) { s1[m] += s1[m + s]; s2[m] += s2[m + s]; }
        __syncthreads();
    }
    if (m == 0) { out[QSIZE] = s1[0]; out[QSIZE + 1] = s2[0]; }
}

// ---------------- fuse2 on tensor cores (3xTF32, all operands materialized) --
#define F2_STG 3200   /* XH 1088 + XL 1088 + WH 512 + WL 512 */
#define F2_SMEMB (64*130*4)   /* transpose buffer 33280 >= 2*F2_STG*4=25600 */

__global__ void __launch_bounds__(256) k_f2_tc(const float* __restrict__ a2p,
                                               float* __restrict__ out) {
    extern __shared__ float fs[];
    int tid = threadIdx.x, lane = tid & 31, warp = tid >> 5;
    int warpM = warp >> 2, warpN = warp & 3;
    int t0 = blockIdx.x*128, o0 = blockIdx.y*64, b = blockIdx.z;
    int ot0 = o0 >> 4;

    uint32_t sbase;
    asm("{ .reg .u64 t; cvta.to.shared.u64 t, %1; cvt.u32.u64 %0, t; }" : "=r"(sbase) : "l"(fs));

    auto issue = [&](int ic, int s) {
        const float* xh = g_ctx_hi + ((size_t)(b*DD + ic*8))*TT + t0;
        const float* xl = g_ctx_lo + ((size_t)(b*DD + ic*8))*TT + t0;
        uint32_t xdh = sbase + (uint32_t)((s*F2_STG)*4);
        uint32_t xdl = xdh + 1088*4;
        {
            int row = tid >> 5, q = tid & 31;
            asm volatile("cp.async.cg.shared.global [%0], [%1], 16;"
                :: "r"(xdh + (uint32_t)((row*136 + q*4)*4)), "l"(xh + (size_t)row*TT + q*4));
            asm volatile("cp.async.cg.shared.global [%0], [%1], 16;"
                :: "r"(xdl + (uint32_t)((row*136 + q*4)*4)), "l"(xl + (size_t)row*TT + q*4));
        }
        if (tid < 128) {
            const float* wp = g_w2shh + ((size_t)ic*16 + ot0)*128;
            uint32_t wd = sbase + (uint32_t)((s*F2_STG + 2176)*4);
            asm volatile("cp.async.cg.shared.global [%0], [%1], 16;"
                :: "r"(wd + (uint32_t)(tid*16)), "l"(wp + tid*4));
        } else {
            int t2 = tid - 128;
            const float* wp = g_w2shl + ((size_t)ic*16 + ot0)*128;
            uint32_t wd = sbase + (uint32_t)((s*F2_STG + 2688)*4);
            asm volatile("cp.async.cg.shared.global [%0], [%1], 16;"
                :: "r"(wd + (uint32_t)(t2*16)), "l"(wp + t2*4));
        }
        asm volatile("cp.async.commit_group;");
    };

    float c[2][4][4] = {};
    issue(0, 0);
    issue(1, 1);

    for (int ic = 0; ic < 32; ic++) {
        int s = ic & 1;
        if (ic < 31) { asm volatile("cp.async.wait_group 1;"); }
        else         { asm volatile("cp.async.wait_group 0;"); }
        __syncthreads();
        const float* XH = fs + s*F2_STG;
        const float* XL = XH + 1088;
        const float* WH = XH + 2176;
        const float* WL = XH + 2688;
        int i0v = lane & 3, trow = lane >> 2;

        uint32_t ah[2][4], al[2][4];
        #pragma unroll
        for (int mf = 0; mf < 2; mf++) {
            float4 vh = *(const float4*)&WH[(warpM*2 + mf)*128 + lane*4];
            float4 vl = *(const float4*)&WL[(warpM*2 + mf)*128 + lane*4];
            ah[mf][0] = __float_as_uint(vh.x); ah[mf][1] = __float_as_uint(vh.y);
            ah[mf][2] = __float_as_uint(vh.z); ah[mf][3] = __float_as_uint(vh.w);
            al[mf][0] = __float_as_uint(vl.x); al[mf][1] = __float_as_uint(vl.y);
            al[mf][2] = __float_as_uint(vl.z); al[mf][3] = __float_as_uint(vl.w);
        }
        uint32_t bh[4][2], bl[4][2];
        #pragma unroll
        for (int nf = 0; nf < 4; nf++) {
            int toff = warpN*32 + nf*8 + trow;
            bh[nf][0] = __float_as_uint(XH[i0v*136 + toff]);
            bh[nf][1] = __float_as_uint(XH[(i0v + 4)*136 + toff]);
            bl[nf][0] = __float_as_uint(XL[i0v*136 + toff]);
            bl[nf][1] = __float_as_uint(XL[(i0v + 4)*136 + toff]);
        }
        #pragma unroll
        for (int mf = 0; mf < 2; mf++) {
            #pragma unroll
            for (int nf = 0; nf < 4; nf++) {
                MMA8(c[mf][nf], ah[mf][0], ah[mf][1], ah[mf][2], ah[mf][3], bh[nf][0], bh[nf][1]);
                MMA8(c[mf][nf], ah[mf][0], ah[mf][1], ah[mf][2], ah[mf][3], bl[nf][0], bl[nf][1]);
                MMA8(c[mf][nf], al[mf][0], al[mf][1], al[mf][2], al[mf][3], bh[nf][0], bh[nf][1]);
            }
        }
        __syncthreads();
        if (ic + 2 < 32) issue(ic + 2, s);
    }

    #pragma unroll
    for (int mf = 0; mf < 2; mf++) {
        int r = warpM*32 + mf*16 + (lane >> 2);
        #pragma unroll
        for (int nf = 0; nf < 4; nf++) {
            int tg = warpN*32 + nf*8 + (lane & 3)*2;
            *(float2*)&fs[r*130 + tg]       = make_float2(c[mf][nf][0], c[mf][nf][1]);
            *(float2*)&fs[(r + 8)*130 + tg] = make_float2(c[mf][nf][2], c[mf][nf][3]);
        }
    }
    __syncthreads();
    float a2v = *a2p;
    int nl = tid >> 1, half = tid & 1;
    size_t n = (size_t)b*TT + t0 + nl;
    int mi = g_idx[n];
    const float* w2e = g_W2E + (size_t)mi*DD + o0 + half*32;
    float* op = out + n*DD + o0 + half*32;
    #pragma unroll
    for (int j = 0; j < 8; j++) {
        float4 w4 = *(const float4*)&w2e[j*4];
        float4 v;
        float u;
        u = fs[(half*32 + j*4 + 0)*130 + nl] + w4.x; v.x = (u >= 0.f) ? u : a2v*u;
        u = fs[(half*32 + j*4 + 1)*130 + nl] + w4.y; v.y = (u >= 0.f) ? u : a2v*u;
        u = fs[(half*32 + j*4 + 2)*130 + nl] + w4.z; v.z = (u >= 0.f) ? u : a2v*u;
        u = fs[(half*32 + j*4 + 3)*130 + nl] + w4.w; v.w = (u >= 0.f) ? u : a2v*u;
        *(float4*)&op[j*4] = v;
    }
}

// ---------------- launch -----------------------------------------------------
extern "C" void kernel_launch(void* const* d_in, const int* in_sizes, int n_in,
                              void* d_out, int out_size) {
    const float* x     = (const float*)d_in[0];
    const float* noise = (const float*)d_in[1];
    const float* gum   = (const float*)d_in[2];
    const int*   epo   = (const int*)  d_in[3];
    const float* emb   = (const float*)d_in[4];
    const float* wctx  = (const float*)d_in[5];
    const float* wf1   = (const float*)d_in[6];
    const float* a1    = (const float*)d_in[7];
    const float* wf2   = (const float*)d_in[8];
    const float* a2    = (const float*)d_in[9];
    float* out = (float*)d_out;

    cudaFuncSetAttribute(k_conv_tc, cudaFuncAttributeMaxDynamicSharedMemorySize, CV_SMEMB);
    cudaFuncSetAttribute(k_f1_tc, cudaFuncAttributeMaxDynamicSharedMemorySize, F1_SMEMB);
    cudaFuncSetAttribute(k_dist_b, cudaFuncAttributeMaxDynamicSharedMemorySize, DB_SMEMB);
    cudaFuncSetAttribute(k_f2_tc, cudaFuncAttributeMaxDynamicSharedMemorySize, F2_SMEMB);

    dim3 tb32(32, 8);

    k_scale<<<BB, 256>>>(x, epo);                                   // 0
    k_noisy<<<dim3((LL + 31)/32, DD/32, BB), tb32>>>(x, noise);     // 1
    k_splitw<<<DD*DD*CTX/256, 256>>>(wctx);                         // 2
    k_conv_tc<<<dim3(TT/128, 2, BB), 256, CV_SMEMB>>>(0);           // 3 <- capture
    k_conv_tc<<<dim3(TT/128, 2, BB), 256, CV_SMEMB>>>(128);         // 4
    k_xt<<<dim3(TT/32, DD/32, BB), tb32>>>(x);
    k_splitw1<<<2*DD*DD/256, 256>>>(wf1);
    k_f1_tc<<<dim3(TT/128, DD/64, BB), 256, F1_SMEMB>>>(a1);
    k_transp<<<dim3(DD/32, MM/32), tb32>>>(emb, MM, DD, 0);         // ET
    k_transp<<<dim3(2*DD/32, DD/32), tb32>>>(wf2, DD, 2*DD, 1);     // w2T
    k_esq<<<MM/8, 256>>>(emb);
    k_zero<<<4, 256>>>();
    k_split_eb<<<MM*DD/256, 256>>>(emb);
    k_shufw2<<<DD*DD/256, 256>>>(wf2);
    k_gemm_w2e<<<dim3(MM/64, DD/64), 256>>>();
    k_dist_b<<<dim3(NN/128, MM/128), 256, DB_SMEMB>>>();
    k_rowstats<<<NN/128, 256>>>(gum, emb, out);
    k_finalize<<<1, MM>>>(out);
    k_f2_tc<<<dim3(TT/128, DD/64, BB), 256, F2_SMEMB>>>(a2, out);
}

// round 9
// speedup vs baseline: 1.2047x; 1.0100x over previous
#include <cuda_runtime.h>
#include <cuda_bf16.h>
#include <math.h>
#include <stdint.h>

#define BB 8
#define TT 4096
#define DD 256
#define MM 1024
#define CTX 7
#define LL (TT - 1 + CTX)      /* 4102 */
#define LLP 4104               /* padded stride */
#define NN (BB*TT)             /* 32768 */
#define QSIZE (NN*DD)          /* 8388608 */

// ---------------- scratch ----------------------------------------------------
__device__ __align__(16) float2 g_xt2[BB*DD*TT];        // x^T as (tf32hi, lo)
__device__ __align__(16) float2 g_noisy2[BB*DD*LLP];    // noisy ctx-in (hi, lo)
__device__ __align__(16) float2 g_ctx2[BB*DD*TT];       // conv out (hi, lo)
__device__ __align__(16) float g_wch[DD*DD*CTX];        // w_ctx hi, A-frag shuffled
__device__ __align__(16) float g_wcl[DD*DD*CTX];
__device__ __align__(16) float g_w1shh[2*DD*DD];
__device__ __align__(16) float g_w1shl[2*DD*DD];
__device__ __align__(16) float g_w2shh[DD*DD];
__device__ __align__(16) float g_w2shl[DD*DD];
__device__ __align__(16) float g_cur[(size_t)NN*DD];    // fuse1 out, exact fp32
__device__ __align__(16) __nv_bfloat16 g_cur_bh[(size_t)NN*DD];
__device__ __align__(16) __nv_bfloat16 g_cur_bl[(size_t)NN*DD];
__device__ __align__(16) __nv_bfloat16 g_E_bh[MM*DD];
__device__ __align__(16) __nv_bfloat16 g_E_bl[MM*DD];
__device__ __align__(16) float g_G[(size_t)NN*MM];
__device__ __align__(16) float g_ET[DD*MM];
__device__ __align__(16) float g_w2T[2*DD*DD];
__device__ __align__(16) float g_W2E[MM*DD];
__device__ __align__(16) float g_esq[MM];
__device__ float g_scale[BB];
__device__ int   g_idx[NN];
__device__ unsigned int g_hist[MM];
__device__ float g_avgp[MM];

__device__ __forceinline__ float tf32_hi(float v) {
    uint32_t b;
    asm("cvt.rna.tf32.f32 %0, %1;" : "=r"(b) : "f"(v));
    return __uint_as_float(b);
}

#define MMA8(d, a0,a1,a2,a3, b0,b1) \
    asm volatile("mma.sync.aligned.m16n8k8.row.col.f32.tf32.tf32.f32 " \
        "{%0,%1,%2,%3}, {%4,%5,%6,%7}, {%8,%9}, {%0,%1,%2,%3};" \
        : "+f"((d)[0]), "+f"((d)[1]), "+f"((d)[2]), "+f"((d)[3]) \
        : "r"(a0), "r"(a1), "r"(a2), "r"(a3), "r"(b0), "r"(b1))

#define MMA16B(d, a, b) \
    asm volatile("mma.sync.aligned.m16n8k16.row.col.f32.bf16.bf16.f32 " \
        "{%0,%1,%2,%3}, {%4,%5,%6,%7}, {%8,%9}, {%0,%1,%2,%3};" \
        : "+f"((d)[0]), "+f"((d)[1]), "+f"((d)[2]), "+f"((d)[3]) \
        : "r"((a)[0]), "r"((a)[1]), "r"((a)[2]), "r"((a)[3]), "r"((b)[0]), "r"((b)[1]))

// ---------------- small utility kernels -------------------------------------
__global__ void k_zero() {
    int i = blockIdx.x*blockDim.x + threadIdx.x;
    if (i < MM) { g_hist[i] = 0u; g_avgp[i] = 0.f; }
}

__global__ void k_transp(const float* __restrict__ src, int rows, int cols, int which) {
    __shared__ float s[32][33];
    float* dst = (which == 0) ? g_ET : g_w2T;
    int c0 = blockIdx.x*32, r0 = blockIdx.y*32;
    int tx = threadIdx.x, ty = threadIdx.y;
    #pragma unroll
    for (int j = 0; j < 4; j++) {
        int r = r0 + ty + j*8, c = c0 + tx;
        s[ty + j*8][tx] = (r < rows && c < cols) ? src[(size_t)r*cols + c] : 0.f;
    }
    __syncthreads();
    #pragma unroll
    for (int j = 0; j < 4; j++) {
        int c = c0 + ty + j*8, r = r0 + tx;
        if (c < cols && r < rows) dst[(size_t)c*rows + r] = s[tx][ty + j*8];
    }
}

__global__ void k_esq(const float* __restrict__ E) {
    int warp = threadIdx.x >> 5, lane = threadIdx.x & 31;
    int m = blockIdx.x*8 + warp;
    const float* row = E + (size_t)m*DD;
    float s = 0.f;
    for (int c = lane; c < DD; c += 32) { float v = row[c]; s += v*v; }
    #pragma unroll
    for (int o = 16; o > 0; o >>= 1) s += __shfl_down_sync(0xffffffffu, s, o);
    if (lane == 0) g_esq[m] = s;
}

__global__ void k_split_eb(const float* __restrict__ E) {
    int i = blockIdx.x*256 + threadIdx.x;
    float v = E[i];
    __nv_bfloat16 h = __float2bfloat16(v);
    g_E_bh[i] = h;
    g_E_bl[i] = __float2bfloat16(v - __bfloat162float(h));
}

__global__ void k_splitw(const float* __restrict__ wctx) {
    int idx = blockIdx.x*256 + threadIdx.x;       // grid 1792
    int o = idx / (DD*CTX);
    int rem = idx - o*(DD*CTX);
    int i = rem / CTX, kk = rem - i*CTX;
    float v = wctx[idx];
    float h = tf32_hi(v);
    int ic = i >> 3, il = i & 7;
    int otile = o >> 4, oloc = o & 15;
    int lane = (oloc & 7)*4 + (il & 3);
    int reg = (oloc >> 3) + 2*(il >> 2);
    int d = ((ic*7 + kk)*16 + otile)*128 + lane*4 + reg;
    g_wch[d] = h;
    g_wcl[d] = tf32_hi(v - h);
}

__global__ void k_splitw1(const float* __restrict__ wf1) {
    int idx = blockIdx.x*256 + threadIdx.x;       // grid 512
    int o = idx >> 9, k = idx & 511;
    float v = wf1[idx];
    float h = tf32_hi(v);
    int ks = k >> 3, il = k & 7;
    int otile = o >> 4, oloc = o & 15;
    int lane = (oloc & 7)*4 + (il & 3);
    int reg = (oloc >> 3) + 2*(il >> 2);
    int d = (ks*16 + otile)*128 + lane*4 + reg;
    g_w1shh[d] = h;
    g_w1shl[d] = tf32_hi(v - h);
}

__global__ void k_shufw2(const float* __restrict__ wf2) {
    int idx = blockIdx.x*256 + threadIdx.x;       // grid 256
    int o = idx >> 8, k = idx & 255;
    int ic = k >> 3, il = k & 7;
    int otile = o >> 4, oloc = o & 15;
    int lane = (oloc & 7)*4 + (il & 3);
    int reg = (oloc >> 3) + 2*(il >> 2);
    float v = wf2[o*2*DD + DD + k];
    float h = tf32_hi(v);
    int d = (ic*16 + otile)*128 + lane*4 + reg;
    g_w2shh[d] = h;
    g_w2shl[d] = tf32_hi(v - h);
}

__global__ void k_scale(const float* __restrict__ x, const int* __restrict__ epo_p) {
    int b = blockIdx.x;
    const float* xb = x + (size_t)b*TT*DD;
    float s = 0.f;
    int tot = (TT-1)*DD;
    for (int i = threadIdx.x; i < tot; i += blockDim.x) { float v = xb[i]; s += v*v; }
    __shared__ float sm[8];
    #pragma unroll
    for (int o = 16; o > 0; o >>= 1) s += __shfl_down_sync(0xffffffffu, s, o);
    if ((threadIdx.x & 31) == 0) sm[threadIdx.x >> 5] = s;
    __syncthreads();
    if (threadIdx.x == 0) {
        float t = 0.f;
        for (int w = 0; w < 8; w++) t += sm[w];
        int iv = epo_p[0];
        float ef = (iv >= 0 && iv < 100000) ? (float)iv : __int_as_float(iv);
        float sc = sqrtf(t / (float)(DD*LL));
        g_scale[b] = 0.5f * sc * exp2f(-ef * 0.1f);
    }
}

// x -> xt2 (hi,lo) [b][d][t]
__global__ void k_xt(const float* __restrict__ x) {
    __shared__ float s[32][33];
    int b = blockIdx.z, t0 = blockIdx.x*32, d0 = blockIdx.y*32;
    int tx = threadIdx.x, ty = threadIdx.y;
    #pragma unroll
    for (int j = 0; j < 4; j++) {
        int t = t0 + ty + j*8;
        s[ty + j*8][tx] = x[((size_t)b*TT + t)*DD + d0 + tx];
    }
    __syncthreads();
    #pragma unroll
    for (int j = 0; j < 4; j++) {
        int d = d0 + ty + j*8;
        float v = s[tx][ty + j*8];
        float h = tf32_hi(v);
        g_xt2[((size_t)b*DD + d)*TT + t0 + tx] = make_float2(h, tf32_hi(v - h));
    }
}

__global__ void k_noisy(const float* __restrict__ x, const float* __restrict__ noise) {
    __shared__ float s[32][33];
    int b = blockIdx.z, l0 = blockIdx.x*32, i0 = blockIdx.y*32;
    int tx = threadIdx.x, ty = threadIdx.y;
    float coef = g_scale[b];
    #pragma unroll
    for (int j = 0; j < 4; j++) {
        int row = ty + j*8;
        int t = l0 + row - CTX;
        float v = (t >= 0 && t < TT-1) ? x[((size_t)b*TT + t)*DD + i0 + tx] : 0.f;
        s[row][tx] = v;
    }
    __syncthreads();
    #pragma unroll
    for (int j = 0; j < 4; j++) {
        int i = i0 + ty + j*8, l = l0 + tx;
        if (l < LL) {
            float v = s[tx][ty + j*8] + coef * noise[((size_t)b*DD + i)*LL + l];
            float h = tf32_hi(v);
            g_noisy2[((size_t)b*DD + i)*LLP + l] = make_float2(h, tf32_hi(v - h));
        }
    }
}

// ---------------- conv (3xTF32, interleaved X, materialized W) ---------------
// stage floats: X2 8x136 f2 = 2176 + WH 3584 + WL 3584 = 9344
#define CV_STG 9344
#define CV_SMEMB (2*CV_STG*4)

__global__ void __launch_bounds__(256, 2) k_conv_tc() {
    extern __shared__ float cs[];
    int tid = threadIdx.x, lane = tid & 31, warp = tid >> 5;
    int warpM = warp >> 2, warpN = warp & 3;
    int t0 = blockIdx.x*128, o0 = blockIdx.y*64, b = blockIdx.z;
    int ot0 = o0 >> 4;

    uint32_t sbase;
    asm("{ .reg .u64 t; cvta.to.shared.u64 t, %1; cvt.u32.u64 %0, t; }" : "=r"(sbase) : "l"(cs));

    auto issue = [&](int ic, int s) {
        const float2* xp = g_noisy2 + ((size_t)(b*DD + ic*8))*LLP + t0;
        uint32_t xd = sbase + (uint32_t)((s*CV_STG)*4);
        for (int idx = tid; idx < 544; idx += 256) {
            int row = idx / 68, q = idx - row*68;
            asm volatile("cp.async.cg.shared.global [%0], [%1], 16;"
                :: "r"(xd + (uint32_t)((row*136 + q*2)*8)), "l"(xp + (size_t)row*LLP + q*2));
        }
        const float* wh = g_wch + ((size_t)(ic*7)*16 + ot0)*128;
        const float* wl = g_wcl + ((size_t)(ic*7)*16 + ot0)*128;
        uint32_t wdh = sbase + (uint32_t)((s*CV_STG + 2176)*4);
        uint32_t wdl = wdh + 3584*4;
        for (int idx = tid; idx < 896; idx += 256) {
            int kk = idx >> 7, q = idx & 127;
            asm volatile("cp.async.cg.shared.global [%0], [%1], 16;"
                :: "r"(wdh + (uint32_t)((kk*512 + q*4)*4)), "l"(wh + kk*2048 + q*4));
            asm volatile("cp.async.cg.shared.global [%0], [%1], 16;"
                :: "r"(wdl + (uint32_t)((kk*512 + q*4)*4)), "l"(wl + kk*2048 + q*4));
        }
        asm volatile("cp.async.commit_group;");
    };

    float c[2][4][4] = {};
    issue(0, 0);
    issue(1, 1);

    for (int ic = 0; ic < 32; ic++) {
        int s = ic & 1;
        if (ic < 31) { asm volatile("cp.async.wait_group 1;"); }
        else         { asm volatile("cp.async.wait_group 0;"); }
        __syncthreads();
        const float2* X2 = (const float2*)(cs + s*CV_STG);
        const float* WH = cs + s*CV_STG + 2176;
        const float* WL = cs + s*CV_STG + 5760;
        int i0v = lane & 3, trow = lane >> 2;

        #pragma unroll
        for (int kk = 0; kk < 7; kk++) {
            uint32_t ah[2][4], al[2][4];
            #pragma unroll
            for (int mf = 0; mf < 2; mf++) {
                float4 vh = *(const float4*)&WH[kk*512 + (warpM*2 + mf)*128 + lane*4];
                float4 vl = *(const float4*)&WL[kk*512 + (warpM*2 + mf)*128 + lane*4];
                ah[mf][0] = __float_as_uint(vh.x); ah[mf][1] = __float_as_uint(vh.y);
                ah[mf][2] = __float_as_uint(vh.z); ah[mf][3] = __float_as_uint(vh.w);
                al[mf][0] = __float_as_uint(vl.x); al[mf][1] = __float_as_uint(vl.y);
                al[mf][2] = __float_as_uint(vl.z); al[mf][3] = __float_as_uint(vl.w);
            }
            uint32_t bh[4][2], bl[4][2];
            #pragma unroll
            for (int nf = 0; nf < 4; nf++) {
                int toff = warpN*32 + nf*8 + trow + kk;
                float2 v0 = X2[i0v*136 + toff];
                float2 v1 = X2[(i0v + 4)*136 + toff];
                bh[nf][0] = __float_as_uint(v0.x); bl[nf][0] = __float_as_uint(v0.y);
                bh[nf][1] = __float_as_uint(v1.x); bl[nf][1] = __float_as_uint(v1.y);
            }
            #pragma unroll
            for (int mf = 0; mf < 2; mf++) {
                #pragma unroll
                for (int nf = 0; nf < 4; nf++) {
                    MMA8(c[mf][nf], ah[mf][0], ah[mf][1], ah[mf][2], ah[mf][3], bh[nf][0], bh[nf][1]);
                    MMA8(c[mf][nf], ah[mf][0], ah[mf][1], ah[mf][2], ah[mf][3], bl[nf][0], bl[nf][1]);
                    MMA8(c[mf][nf], al[mf][0], al[mf][1], al[mf][2], al[mf][3], bh[nf][0], bh[nf][1]);
                }
            }
        }
        __syncthreads();
        if (ic + 2 < 32) issue(ic + 2, s);
    }

    // epilogue: write ctx as interleaved (hi,lo)
    #pragma unroll
    for (int mf = 0; mf < 2; mf++) {
        int r = o0 + warpM*32 + mf*16 + (lane >> 2);
        #pragma unroll
        for (int nf = 0; nf < 4; nf++) {
            int tg = t0 + warpN*32 + nf*8 + (lane & 3)*2;
            float v0 = c[mf][nf][0], v1 = c[mf][nf][1];
            float v2 = c[mf][nf][2], v3 = c[mf][nf][3];
            float h0 = tf32_hi(v0), h1 = tf32_hi(v1), h2 = tf32_hi(v2), h3 = tf32_hi(v3);
            size_t o1 = ((size_t)b*DD + r)*TT + tg;
            size_t o2 = ((size_t)b*DD + r + 8)*TT + tg;
            *(float4*)&g_ctx2[o1] = make_float4(h0, tf32_hi(v0 - h0), h1, tf32_hi(v1 - h1));
            *(float4*)&g_ctx2[o2] = make_float4(h2, tf32_hi(v2 - h2), h3, tf32_hi(v3 - h3));
        }
    }
}

// ---------------- fuse1 on tensor cores (3xTF32, interleaved X) --------------
// stage floats: X2 16x136 f2 = 4352 + WH 1024 + WL 1024 = 6400
#define F1_STG 6400
#define F1_SMEMB (2*F1_STG*4)   /* 51200 */

__global__ void __launch_bounds__(256, 2) k_f1_tc(const float* __restrict__ a1p) {
    extern __shared__ float fs[];
    int tid = threadIdx.x, lane = tid & 31, warp = tid >> 5;
    int warpM = warp >> 2, warpN = warp & 3;
    int t0 = blockIdx.x*128, o0 = blockIdx.y*64, b = blockIdx.z;
    int ot0 = o0 >> 4;

    uint32_t sbase;
    asm("{ .reg .u64 t; cvta.to.shared.u64 t, %1; cvt.u32.u64 %0, t; }" : "=r"(sbase) : "l"(fs));

    auto issue = [&](int cchunk, int s) {
        uint32_t xd = sbase + (uint32_t)((s*F1_STG)*4);
        #pragma unroll
        for (int j = 0; j < 4; j++) {
            int idx = tid + j*256;           // 1024 chunks
            int row = idx >> 6, q = idx & 63;
            int d = cchunk*16 + row;
            const float2* sp = (d < DD) ? (g_xt2 + ((size_t)b*DD + d)*TT + t0)
                                        : (g_ctx2 + ((size_t)b*DD + d - DD)*TT + t0);
            asm volatile("cp.async.cg.shared.global [%0], [%1], 16;"
                :: "r"(xd + (uint32_t)((row*136 + q*2)*8)), "l"(sp + q*2));
        }
        const float* wh = g_w1shh + ((size_t)(cchunk*2)*16 + ot0)*128;
        const float* wl = g_w1shl + ((size_t)(cchunk*2)*16 + ot0)*128;
        uint32_t wdh = sbase + (uint32_t)((s*F1_STG + 4352)*4);
        uint32_t wdl = wdh + 1024*4;
        {
            int sl8 = tid >> 7, q = tid & 127;
            asm volatile("cp.async.cg.shared.global [%0], [%1], 16;"
                :: "r"(wdh + (uint32_t)(tid*16)), "l"(wh + sl8*2048 + q*4));
            asm volatile("cp.async.cg.shared.global [%0], [%1], 16;"
                :: "r"(wdl + (uint32_t)(tid*16)), "l"(wl + sl8*2048 + q*4));
        }
        asm volatile("cp.async.commit_group;");
    };

    float c[2][4][4] = {};
    issue(0, 0);
    issue(1, 1);

    for (int cc = 0; cc < 32; cc++) {
        int s = cc & 1;
        if (cc < 31) { asm volatile("cp.async.wait_group 1;"); }
        else         { asm volatile("cp.async.wait_group 0;"); }
        __syncthreads();
        const float2* X2 = (const float2*)(fs + s*F1_STG);
        const float* WH = fs + s*F1_STG + 4352;
        const float* WL = fs + s*F1_STG + 5376;
        int i0v = lane & 3, trow = lane >> 2;

        #pragma unroll
        for (int sl8 = 0; sl8 < 2; sl8++) {
            uint32_t ah[2][4], al[2][4];
            #pragma unroll
            for (int mf = 0; mf < 2; mf++) {
                float4 vh = *(const float4*)&WH[sl8*512 + (warpM*2 + mf)*128 + lane*4];
                float4 vl = *(const float4*)&WL[sl8*512 + (warpM*2 + mf)*128 + lane*4];
                ah[mf][0] = __float_as_uint(vh.x); ah[mf][1] = __float_as_uint(vh.y);
                ah[mf][2] = __float_as_uint(vh.z); ah[mf][3] = __float_as_uint(vh.w);
                al[mf][0] = __float_as_uint(vl.x); al[mf][1] = __float_as_uint(vl.y);
                al[mf][2] = __float_as_uint(vl.z); al[mf][3] = __float_as_uint(vl.w);
            }
            uint32_t bh[4][2], bl[4][2];
            #pragma unroll
            for (int nf = 0; nf < 4; nf++) {
                int toff = warpN*32 + nf*8 + trow;
                int rbase = sl8*8 + i0v;
                float2 v0 = X2[rbase*136 + toff];
                float2 v1 = X2[(rbase + 4)*136 + toff];
                bh[nf][0] = __float_as_uint(v0.x); bl[nf][0] = __float_as_uint(v0.y);
                bh[nf][1] = __float_as_uint(v1.x); bl[nf][1] = __float_as_uint(v1.y);
            }
            #pragma unroll
            for (int mf = 0; mf < 2; mf++) {
                #pragma unroll
                for (int nf = 0; nf < 4; nf++) {
                    MMA8(c[mf][nf], ah[mf][0], ah[mf][1], ah[mf][2], ah[mf][3], bh[nf][0], bh[nf][1]);
                    MMA8(c[mf][nf], ah[mf][0], ah[mf][1], ah[mf][2], ah[mf][3], bl[nf][0], bl[nf][1]);
                    MMA8(c[mf][nf], al[mf][0], al[mf][1], al[mf][2], al[mf][3], bh[nf][0], bh[nf][1]);
                }
            }
        }
        __syncthreads();
        if (cc + 2 < 32) issue(cc + 2, s);
    }

    // epilogue: prelu -> smem transpose -> write cur exact + bf16 hi/lo
    float a1 = *a1p;
    #pragma unroll
    for (int mf = 0; mf < 2; mf++) {
        int r = warpM*32 + mf*16 + (lane >> 2);
        #pragma unroll
        for (int nf = 0; nf < 4; nf++) {
            int tg = warpN*32 + nf*8 + (lane & 3)*2;
            float v0 = c[mf][nf][0]; v0 = (v0 >= 0.f) ? v0 : a1*v0;
            float v1 = c[mf][nf][1]; v1 = (v1 >= 0.f) ? v1 : a1*v1;
            float v2 = c[mf][nf][2]; v2 = (v2 >= 0.f) ? v2 : a1*v2;
            float v3 = c[mf][nf][3]; v3 = (v3 >= 0.f) ? v3 : a1*v3;
            *(float2*)&fs[r*130 + tg]       = make_float2(v0, v1);
            *(float2*)&fs[(r + 8)*130 + tg] = make_float2(v2, v3);
        }
    }
    __syncthreads();
    int nl = tid >> 1, half = tid & 1;
    size_t n = (size_t)b*TT + t0 + nl;
    float* cp = g_cur + n*DD + o0 + half*32;
    __nv_bfloat16* bhp = g_cur_bh + n*DD + o0 + half*32;
    __nv_bfloat16* blp = g_cur_bl + n*DD + o0 + half*32;
    #pragma unroll
    for (int j = 0; j < 8; j++) {
        float4 v;
        v.x = fs[(half*32 + j*4 + 0)*130 + nl];
        v.y = fs[(half*32 + j*4 + 1)*130 + nl];
        v.z = fs[(half*32 + j*4 + 2)*130 + nl];
        v.w = fs[(half*32 + j*4 + 3)*130 + nl];
        *(float4*)&cp[j*4] = v;
        float vv[4] = {v.x, v.y, v.z, v.w};
        __nv_bfloat16 bh4[4], bl4[4];
        #pragma unroll
        for (int q = 0; q < 4; q++) {
            bh4[q] = __float2bfloat16(vv[q]);
            bl4[q] = __float2bfloat16(vv[q] - __bfloat162float(bh4[q]));
        }
        *(uint2*)&bhp[j*4] = *(uint2*)bh4;
        *(uint2*)&blp[j*4] = *(uint2*)bl4;
    }
}

// ---------------- W2E GEMM (small) -------------------------------------------
__global__ void __launch_bounds__(256) k_gemm_w2e() {
    __shared__ float sA[16][68];
    __shared__ float sB[16][68];
    int i0 = blockIdx.x*64, j0 = blockIdx.y*64;
    int tid = threadIdx.x;
    int tx = tid & 15, ty = tid >> 4;
    int kl = tid >> 4, nl4 = (tid & 15)*4;
    float acc[4][4] = {};
    for (int kc = 0; kc < DD; kc += 16) {
        *(float4*)&sA[kl][nl4] = *(const float4*)(g_ET  + (size_t)(kc + kl)*MM + i0 + nl4);
        *(float4*)&sB[kl][nl4] = *(const float4*)(g_w2T + (size_t)(kc + kl)*DD + j0 + nl4);
        __syncthreads();
        #pragma unroll
        for (int k = 0; k < 16; k++) {
            float4 av = *(const float4*)&sA[k][4*tx];
            float4 bv = *(const float4*)&sB[k][4*ty];
            float ar[4] = {av.x, av.y, av.z, av.w};
            float br[4] = {bv.x, bv.y, bv.z, bv.w};
            #pragma unroll
            for (int a = 0; a < 4; a++)
                #pragma unroll
                for (int cc = 0; cc < 4; cc++)
                    acc[a][cc] += br[a] * ar[cc];
        }
        __syncthreads();
    }
    #pragma unroll
    for (int cc = 0; cc < 4; cc++) {
        int i = i0 + 4*tx + cc;
        float4 v = make_float4(acc[0][cc], acc[1][cc], acc[2][cc], acc[3][cc]);
        *(float4*)&g_W2E[(size_t)i*DD + j0 + 4*ty] = v;
    }
}

// ---------------- dist GEMM via mma.sync bf16 (3xBF16, k16) ------------------
#define DB_ROWW 20
#define DB_ARRW (128*DB_ROWW)
#define DB_STGW (4*DB_ARRW)
#define DB_SMEMB (2*DB_STGW*4)

__global__ void __launch_bounds__(256, 2) k_dist_b() {
    extern __shared__ uint32_t dsm[];
    int tid = threadIdx.x, lane = tid & 31, warp = tid >> 5;
    int warpM = warp >> 2, warpN = warp & 3;
    int n0 = blockIdx.x*128, m0 = blockIdx.y*128;

    uint32_t sbase;
    asm("{ .reg .u64 t; cvta.to.shared.u64 t, %1; cvt.u32.u64 %0, t; }" : "=r"(sbase) : "l"(dsm));

    const __nv_bfloat16* srcs[4] = {
        g_cur_bh + (size_t)n0*DD, g_cur_bl + (size_t)n0*DD,
        g_E_bh   + (size_t)m0*DD, g_E_bl   + (size_t)m0*DD };

    auto issue = [&](int kc, int s) {
        #pragma unroll
        for (int a = 0; a < 4; a++) {
            uint32_t dstb = sbase + (uint32_t)((s*DB_STGW + a*DB_ARRW)*4);
            #pragma unroll
            for (int j = 0; j < 2; j++) {
                int cid = tid + j*256;
                int row = cid >> 2, q = cid & 3;
                uint32_t dst = dstb + (uint32_t)(row*80 + q*16);
                const __nv_bfloat16* src = srcs[a] + (size_t)row*DD + kc + q*8;
                asm volatile("cp.async.cg.shared.global [%0], [%1], 16;"
                             :: "r"(dst), "l"(src));
            }
        }
        asm volatile("cp.async.commit_group;");
    };

    float c[4][4][4] = {};
    issue(0, 0);

    int gr = lane >> 2, lc = lane & 3;
    for (int it = 0; it < 8; it++) {
        int s = it & 1;
        if (it + 1 < 8) issue((it + 1)*32, s ^ 1);
        if (it + 1 < 8) { asm volatile("cp.async.wait_group 1;"); }
        else            { asm volatile("cp.async.wait_group 0;"); }
        __syncthreads();

        const uint32_t* sAh = dsm + s*DB_STGW;
        const uint32_t* sAl = sAh + DB_ARRW;
        const uint32_t* sBh = sAh + 2*DB_ARRW;
        const uint32_t* sBl = sAh + 3*DB_ARRW;

        #pragma unroll
        for (int ks = 0; ks < 2; ks++) {
            int wb = ks*8 + lc;
            uint32_t ah[4][4], al[4][4], bh[4][2], bl[4][2];
            #pragma unroll
            for (int mf = 0; mf < 4; mf++) {
                int r1 = (warpM*64 + mf*16 + gr)*DB_ROWW, r2 = r1 + 8*DB_ROWW;
                ah[mf][0] = sAh[r1 + wb];     ah[mf][1] = sAh[r2 + wb];
                ah[mf][2] = sAh[r1 + wb + 4]; ah[mf][3] = sAh[r2 + wb + 4];
                al[mf][0] = sAl[r1 + wb];     al[mf][1] = sAl[r2 + wb];
                al[mf][2] = sAl[r1 + wb + 4]; al[mf][3] = sAl[r2 + wb + 4];
            }
            #pragma unroll
            for (int nf = 0; nf < 4; nf++) {
                int rn = (warpN*32 + nf*8 + gr)*DB_ROWW;
                bh[nf][0] = sBh[rn + wb]; bh[nf][1] = sBh[rn + wb + 4];
                bl[nf][0] = sBl[rn + wb]; bl[nf][1] = sBl[rn + wb + 4];
            }
            #pragma unroll
            for (int mf = 0; mf < 4; mf++) {
                #pragma unroll
                for (int nf = 0; nf < 4; nf++) {
                    MMA16B(c[mf][nf], ah[mf], bh[nf]);
                    MMA16B(c[mf][nf], ah[mf], bl[nf]);
                    MMA16B(c[mf][nf], al[mf], bh[nf]);
                }
            }
        }
        __syncthreads();
    }

    #pragma unroll
    for (int mf = 0; mf < 4; mf++) {
        int r1 = n0 + warpM*64 + mf*16 + gr;
        #pragma unroll
        for (int nf = 0; nf < 4; nf++) {
            int gc = m0 + warpN*32 + nf*8 + lc*2;
            *(float2*)&g_G[(size_t)r1*MM + gc]       = make_float2(c[mf][nf][0], c[mf][nf][1]);
            *(float2*)&g_G[(size_t)(r1 + 8)*MM + gc] = make_float2(c[mf][nf][2], c[mf][nf][3]);
        }
    }
}

// ---------------- per-row stats with exact top-2 refinement -----------------
__device__ __forceinline__ float gumbel_of(float u) {
    u = fminf(fmaxf(u, 1e-10f), 1.f - 1e-7f);
    return -__logf(-__logf(u));
}

__global__ void __launch_bounds__(256) k_rowstats(const float* __restrict__ gum,
                                                  const float* __restrict__ emb,
                                                  float* __restrict__ out) {
    __shared__ float sAcc[MM];
    int tid = threadIdx.x, wid = tid >> 5, lane = tid & 31;
    for (int i = tid; i < MM; i += 256) sAcc[i] = 0.f;
    __syncthreads();

    float esq_r[8][4];
    #pragma unroll
    for (int ch = 0; ch < 8; ch++) {
        float4 v = *(const float4*)&g_esq[ch*128 + lane*4];
        esq_r[ch][0] = v.x; esq_r[ch][1] = v.y; esq_r[ch][2] = v.z; esq_r[ch][3] = v.w;
    }
    float pAcc[8][4] = {};
    int nbase = blockIdx.x*128 + wid*16;

    for (int r = 0; r < 16; r++) {
        int n = nbase + r;
        const float* Gr = g_G + (size_t)n*MM;
        const float* Ur = gum + (size_t)n*MM;
        float dm[8][4];
        float h1v = -3.4e38f, h2v = -3.4e38f; int h1i = 0x7fffffff, h2i = 0x7fffffff;
        float s1v = -3.4e38f, s2v = -3.4e38f; int s1i = 0x7fffffff, s2i = 0x7fffffff;
        #pragma unroll
        for (int ch = 0; ch < 8; ch++) {
            float4 g4 = *(const float4*)&Gr[ch*128 + lane*4];
            float4 u4 = *(const float4*)&Ur[ch*128 + lane*4];
            float gg[4] = {g4.x, g4.y, g4.z, g4.w};
            float uu[4] = {u4.x, u4.y, u4.z, u4.w};
            #pragma unroll
            for (int j = 0; j < 4; j++) {
                int m = ch*128 + lane*4 + j;
                float d = 2.f*gg[j] - esq_r[ch][j];
                dm[ch][j] = d;
                if (d > h1v || (d == h1v && m < h1i)) { h2v = h1v; h2i = h1i; h1v = d; h1i = m; }
                else if (d > h2v || (d == h2v && m < h2i)) { h2v = d; h2i = m; }
                float sc = d + gumbel_of(uu[j]);
                if (sc > s1v || (sc == s1v && m < s1i)) { s2v = s1v; s2i = s1i; s1v = sc; s1i = m; }
                else if (sc > s2v || (sc == s2v && m < s2i)) { s2v = sc; s2i = m; }
            }
        }
        #pragma unroll
        for (int o = 16; o > 0; o >>= 1) {
            float ov1 = __shfl_xor_sync(0xffffffffu, h1v, o);
            int   oi1 = __shfl_xor_sync(0xffffffffu, h1i, o);
            float ov2 = __shfl_xor_sync(0xffffffffu, h2v, o);
            int   oi2 = __shfl_xor_sync(0xffffffffu, h2i, o);
            if (ov1 > h1v || (ov1 == h1v && oi1 < h1i)) {
                float t1v = h1v; int t1i = h1i;
                h1v = ov1; h1i = oi1;
                if (t1v > ov2 || (t1v == ov2 && t1i < oi2)) { h2v = t1v; h2i = t1i; }
                else { h2v = ov2; h2i = oi2; }
            } else {
                if (ov1 > h2v || (ov1 == h2v && oi1 < h2i)) { h2v = ov1; h2i = oi1; }
            }
            float pv1 = __shfl_xor_sync(0xffffffffu, s1v, o);
            int   pi1 = __shfl_xor_sync(0xffffffffu, s1i, o);
            float pv2 = __shfl_xor_sync(0xffffffffu, s2v, o);
            int   pi2 = __shfl_xor_sync(0xffffffffu, s2i, o);
            if (pv1 > s1v || (pv1 == s1v && pi1 < s1i)) {
                float t1v = s1v; int t1i = s1i;
                s1v = pv1; s1i = pi1;
                if (t1v > pv2 || (t1v == pv2 && t1i < pi2)) { s2v = t1v; s2i = t1i; }
                else { s2v = pv2; s2i = pi2; }
            } else {
                if (pv1 > s2v || (pv1 == s2v && pi1 < s2i)) { s2v = pv1; s2i = pi1; }
            }
        }

        int cands[4] = {h1i, h2i, s1i, s2i};
        float ex[4];
        const float* curp = g_cur + (size_t)n*DD + lane*8;
        #pragma unroll
        for (int t = 0; t < 4; t++) {
            const float* Ep = emb + (size_t)cands[t]*DD + lane*8;
            float s = 0.f;
            #pragma unroll
            for (int j = 0; j < 8; j++) s += curp[j]*Ep[j];
            #pragma unroll
            for (int o = 16; o > 0; o >>= 1) s += __shfl_xor_sync(0xffffffffu, s, o);
            ex[t] = 2.f*s - g_esq[cands[t]];
        }

        float ssum = 0.f;
        #pragma unroll
        for (int ch = 0; ch < 8; ch++)
            #pragma unroll
            for (int j = 0; j < 4; j++) { float e = __expf(dm[ch][j] - h1v); dm[ch][j] = e; ssum += e; }
        #pragma unroll
        for (int o = 16; o > 0; o >>= 1) ssum += __shfl_xor_sync(0xffffffffu, ssum, o);
        float inv = 1.f / ssum;
        #pragma unroll
        for (int ch = 0; ch < 8; ch++)
            #pragma unroll
            for (int j = 0; j < 4; j++) pAcc[ch][j] += dm[ch][j] * inv;

        if (lane == 0) {
            int kH = h1i; float vH = ex[0];
            if (ex[1] > vH || (ex[1] == vH && h2i < kH)) { kH = h2i; vH = ex[1]; }
            atomicAdd(&g_hist[kH], 1u);
            float sc0 = ex[2] + gumbel_of(Ur[s1i]);
            float sc1 = ex[3] + gumbel_of(Ur[s2i]);
            int kS = s1i;
            if (sc1 > sc0 || (sc1 == sc0 && s2i < s1i)) kS = s2i;
            g_idx[n] = kS;
            out[QSIZE + 2 + n] = (float)kS;
        }
    }
    #pragma unroll
    for (int ch = 0; ch < 8; ch++)
        #pragma unroll
        for (int j = 0; j < 4; j++) atomicAdd(&sAcc[ch*128 + lane*4 + j], pAcc[ch][j]);
    __syncthreads();
    for (int i = tid; i < MM; i += 256) atomicAdd(&g_avgp[i], sAcc[i]);
}

__global__ void k_finalize(float* __restrict__ out) {
    __shared__ float s1[MM];
    __shared__ float s2[MM];
    int m = threadIdx.x;
    float hp = (float)g_hist[m] * (1.f/(float)NN);
    float ap = g_avgp[m] * (1.f/(float)NN);
    s1[m] = -hp * log2f(hp + 1e-10f);
    s2[m] = -ap * log2f(ap + 1e-10f);
    __syncthreads();
    for (int s = 512; s > 0; s >>= 1) {
        if (m < s) { s1[m] += s1[m + s]; s2[m] += s2[m + s]; }
        __syncthreads();
    }
    if (m == 0) { out[QSIZE] = s1[0]; out[QSIZE + 1] = s2[0]; }
}

// ---------------- fuse2 (3xTF32, interleaved X, materialized W) --------------
// stage floats: X2 8x136 f2 = 2176 + WH 512 + WL 512 = 3200
#define F2_STG 3200
#define F2_SMEMB (64*130*4)   /* transpose buffer 33280 >= 2*F2_STG*4=25600 */

__global__ void __launch_bounds__(256) k_f2_tc(const float* __restrict__ a2p,
                                               float* __restrict__ out) {
    extern __shared__ float fs[];
    int tid = threadIdx.x, lane = tid & 31, warp = tid >> 5;
    int warpM = warp >> 2, warpN = warp & 3;
    int t0 = blockIdx.x*128, o0 = blockIdx.y*64, b = blockIdx.z;
    int ot0 = o0 >> 4;

    uint32_t sbase;
    asm("{ .reg .u64 t; cvta.to.shared.u64 t, %1; cvt.u32.u64 %0, t; }" : "=r"(sbase) : "l"(fs));

    auto issue = [&](int ic, int s) {
        uint32_t xd = sbase + (uint32_t)((s*F2_STG)*4);
        #pragma unroll
        for (int j = 0; j < 2; j++) {
            int idx = tid + j*256;          // 512 chunks
            int row = idx >> 6, q = idx & 63;
            const float2* sp = g_ctx2 + ((size_t)(b*DD + ic*8 + row))*TT + t0;
            asm volatile("cp.async.cg.shared.global [%0], [%1], 16;"
                :: "r"(xd + (uint32_t)((row*136 + q*2)*8)), "l"(sp + q*2));
        }
        if (tid < 128) {
            const float* wp = g_w2shh + ((size_t)ic*16 + ot0)*128;
            uint32_t wd = sbase + (uint32_t)((s*F2_STG + 2176)*4);
            asm volatile("cp.async.cg.shared.global [%0], [%1], 16;"
                :: "r"(wd + (uint32_t)(tid*16)), "l"(wp + tid*4));
        } else {
            int t2 = tid - 128;
            const float* wp = g_w2shl + ((size_t)ic*16 + ot0)*128;
            uint32_t wd = sbase + (uint32_t)((s*F2_STG + 2688)*4);
            asm volatile("cp.async.cg.shared.global [%0], [%1], 16;"
                :: "r"(wd + (uint32_t)(t2*16)), "l"(wp + t2*4));
        }
        asm volatile("cp.async.commit_group;");
    };

    float c[2][4][4] = {};
    issue(0, 0);
    issue(1, 1);

    for (int ic = 0; ic < 32; ic++) {
        int s = ic & 1;
        if (ic < 31) { asm volatile("cp.async.wait_group 1;"); }
        else         { asm volatile("cp.async.wait_group 0;"); }
        __syncthreads();
        const float2* X2 = (const float2*)(fs + s*F2_STG);
        const float* WH = fs + s*F2_STG + 2176;
        const float* WL = fs + s*F2_STG + 2688;
        int i0v = lane & 3, trow = lane >> 2;

        uint32_t ah[2][4], al[2][4];
        #pragma unroll
        for (int mf = 0; mf < 2; mf++) {
            float4 vh = *(const float4*)&WH[(warpM*2 + mf)*128 + lane*4];
            float4 vl = *(const float4*)&WL[(warpM*2 + mf)*128 + lane*4];
            ah[mf][0] = __float_as_uint(vh.x); ah[mf][1] = __float_as_uint(vh.y);
            ah[mf][2] = __float_as_uint(vh.z); ah[mf][3] = __float_as_uint(vh.w);
            al[mf][0] = __float_as_uint(vl.x); al[mf][1] = __float_as_uint(vl.y);
            al[mf][2] = __float_as_uint(vl.z); al[mf][3] = __float_as_uint(vl.w);
        }
        uint32_t bh[4][2], bl[4][2];
        #pragma unroll
        for (int nf = 0; nf < 4; nf++) {
            int toff = warpN*32 + nf*8 + trow;
            float2 v0 = X2[i0v*136 + toff];
            float2 v1 = X2[(i0v + 4)*136 + toff];
            bh[nf][0] = __float_as_uint(v0.x); bl[nf][0] = __float_as_uint(v0.y);
            bh[nf][1] = __float_as_uint(v1.x); bl[nf][1] = __float_as_uint(v1.y);
        }
        #pragma unroll
        for (int mf = 0; mf < 2; mf++) {
            #pragma unroll
            for (int nf = 0; nf < 4; nf++) {
                MMA8(c[mf][nf], ah[mf][0], ah[mf][1], ah[mf][2], ah[mf][3], bh[nf][0], bh[nf][1]);
                MMA8(c[mf][nf], ah[mf][0], ah[mf][1], ah[mf][2], ah[mf][3], bl[nf][0], bl[nf][1]);
                MMA8(c[mf][nf], al[mf][0], al[mf][1], al[mf][2], al[mf][3], bh[nf][0], bh[nf][1]);
            }
        }
        __syncthreads();
        if (ic + 2 < 32) issue(ic + 2, s);
    }

    #pragma unroll
    for (int mf = 0; mf < 2; mf++) {
        int r = warpM*32 + mf*16 + (lane >> 2);
        #pragma unroll
        for (int nf = 0; nf < 4; nf++) {
            int tg = warpN*32 + nf*8 + (lane & 3)*2;
            *(float2*)&fs[r*130 + tg]       = make_float2(c[mf][nf][0], c[mf][nf][1]);
            *(float2*)&fs[(r + 8)*130 + tg] = make_float2(c[mf][nf][2], c[mf][nf][3]);
        }
    }
    __syncthreads();
    float a2v = *a2p;
    int nl = tid >> 1, half = tid & 1;
    size_t n = (size_t)b*TT + t0 + nl;
    int mi = g_idx[n];
    const float* w2e = g_W2E + (size_t)mi*DD + o0 + half*32;
    float* op = out + n*DD + o0 + half*32;
    #pragma unroll
    for (int j = 0; j < 8; j++) {
        float4 w4 = *(const float4*)&w2e[j*4];
        float4 v;
        float u;
        u = fs[(half*32 + j*4 + 0)*130 + nl] + w4.x; v.x = (u >= 0.f) ? u : a2v*u;
        u = fs[(half*32 + j*4 + 1)*130 + nl] + w4.y; v.y = (u >= 0.f) ? u : a2v*u;
        u = fs[(half*32 + j*4 + 2)*130 + nl] + w4.z; v.z = (u >= 0.f) ? u : a2v*u;
        u = fs[(half*32 + j*4 + 3)*130 + nl] + w4.w; v.w = (u >= 0.f) ? u : a2v*u;
        *(float4*)&op[j*4] = v;
    }
}

// ---------------- launch -----------------------------------------------------
extern "C" void kernel_launch(void* const* d_in, const int* in_sizes, int n_in,
                              void* d_out, int out_size) {
    const float* x     = (const float*)d_in[0];
    const float* noise = (const float*)d_in[1];
    const float* gum   = (const float*)d_in[2];
    const int*   epo   = (const int*)  d_in[3];
    const float* emb   = (const float*)d_in[4];
    const float* wctx  = (const float*)d_in[5];
    const float* wf1   = (const float*)d_in[6];
    const float* a1    = (const float*)d_in[7];
    const float* wf2   = (const float*)d_in[8];
    const float* a2    = (const float*)d_in[9];
    float* out = (float*)d_out;

    cudaFuncSetAttribute(k_conv_tc, cudaFuncAttributeMaxDynamicSharedMemorySize, CV_SMEMB);
    cudaFuncSetAttribute(k_f1_tc, cudaFuncAttributeMaxDynamicSharedMemorySize, F1_SMEMB);
    cudaFuncSetAttribute(k_dist_b, cudaFuncAttributeMaxDynamicSharedMemorySize, DB_SMEMB);
    cudaFuncSetAttribute(k_f2_tc, cudaFuncAttributeMaxDynamicSharedMemorySize, F2_SMEMB);

    dim3 tb32(32, 8);

    k_scale<<<BB, 256>>>(x, epo);                                   // 0
    k_noisy<<<dim3((LL + 31)/32, DD/32, BB), tb32>>>(x, noise);     // 1
    k_splitw<<<DD*DD*CTX/256, 256>>>(wctx);                         // 2
    k_conv_tc<<<dim3(TT/128, 4, BB), 256, CV_SMEMB>>>();            // 3 <- capture
    k_xt<<<dim3(TT/32, DD/32, BB), tb32>>>(x);
    k_splitw1<<<2*DD*DD/256, 256>>>(wf1);
    k_f1_tc<<<dim3(TT/128, DD/64, BB), 256, F1_SMEMB>>>(a1);
    k_transp<<<dim3(DD/32, MM/32), tb32>>>(emb, MM, DD, 0);         // ET
    k_transp<<<dim3(2*DD/32, DD/32), tb32>>>(wf2, DD, 2*DD, 1);     // w2T
    k_esq<<<MM/8, 256>>>(emb);
    k_zero<<<4, 256>>>();
    k_split_eb<<<MM*DD/256, 256>>>(emb);
    k_shufw2<<<DD*DD/256, 256>>>(wf2);
    k_gemm_w2e<<<dim3(MM/64, DD/64), 256>>>();
    k_dist_b<<<dim3(NN/128, MM/128), 256, DB_SMEMB>>>();
    k_rowstats<<<NN/128, 256>>>(gum, emb, out);
    k_finalize<<<1, MM>>>(out);
    k_f2_tc<<<dim3(TT/128, DD/64, BB), 256, F2_SMEMB>>>(a2, out);
}

// round 10
// speedup vs baseline: 1.2398x; 1.0292x over previous
#include <cuda_runtime.h>
#include <cuda_bf16.h>
#include <math.h>
#include <stdint.h>

#define BB 8
#define TT 4096
#define DD 256
#define MM 1024
#define CTX 7
#define LL (TT - 1 + CTX)      /* 4102 */
#define LLP 4104               /* padded stride */
#define NN (BB*TT)             /* 32768 */
#define QSIZE (NN*DD)          /* 8388608 */

// ---------------- scratch ----------------------------------------------------
__device__ __align__(16) float2 g_xt2[BB*DD*TT];        // x^T as (tf32hi, lo)
__device__ __align__(16) float2 g_noisy2[BB*DD*LLP];    // noisy ctx-in (hi, lo)
__device__ __align__(16) float2 g_ctx2[BB*DD*TT];       // conv out (hi, lo)
__device__ __align__(16) float g_wch[DD*DD*CTX];        // w_ctx hi, A-frag shuffled
__device__ __align__(16) float g_wcl[DD*DD*CTX];
__device__ __align__(16) float g_w1shh[2*DD*DD];
__device__ __align__(16) float g_w1shl[2*DD*DD];
__device__ __align__(16) float g_w2shh[DD*DD];
__device__ __align__(16) float g_w2shl[DD*DD];
__device__ __align__(16) float g_cur[(size_t)NN*DD];    // fuse1 out, exact fp32
__device__ __align__(16) __nv_bfloat16 g_cur_bh[(size_t)NN*DD];
__device__ __align__(16) __nv_bfloat16 g_cur_bl[(size_t)NN*DD];
__device__ __align__(16) __nv_bfloat16 g_E_bh[MM*DD];
__device__ __align__(16) __nv_bfloat16 g_E_bl[MM*DD];
__device__ __align__(16) float g_G[(size_t)NN*MM];
__device__ __align__(16) float g_ET[DD*MM];
__device__ __align__(16) float g_w2T[2*DD*DD];
__device__ __align__(16) float g_W2E[MM*DD];
__device__ __align__(16) float g_esq[MM];
__device__ float g_scale[BB];
__device__ int   g_idx[NN];
__device__ unsigned int g_hist[MM];
__device__ float g_avgp[MM];

__device__ __forceinline__ float tf32_hi(float v) {
    uint32_t b;
    asm("cvt.rna.tf32.f32 %0, %1;" : "=r"(b) : "f"(v));
    return __uint_as_float(b);
}

#define MMA8(d, a0,a1,a2,a3, b0,b1) \
    asm volatile("mma.sync.aligned.m16n8k8.row.col.f32.tf32.tf32.f32 " \
        "{%0,%1,%2,%3}, {%4,%5,%6,%7}, {%8,%9}, {%0,%1,%2,%3};" \
        : "+f"((d)[0]), "+f"((d)[1]), "+f"((d)[2]), "+f"((d)[3]) \
        : "r"(a0), "r"(a1), "r"(a2), "r"(a3), "r"(b0), "r"(b1))

#define MMA16B(d, a, b) \
    asm volatile("mma.sync.aligned.m16n8k16.row.col.f32.bf16.bf16.f32 " \
        "{%0,%1,%2,%3}, {%4,%5,%6,%7}, {%8,%9}, {%0,%1,%2,%3};" \
        : "+f"((d)[0]), "+f"((d)[1]), "+f"((d)[2]), "+f"((d)[3]) \
        : "r"((a)[0]), "r"((a)[1]), "r"((a)[2]), "r"((a)[3]), "r"((b)[0]), "r"((b)[1]))

// ---------------- small utility kernels -------------------------------------
__global__ void k_zero() {
    int i = blockIdx.x*blockDim.x + threadIdx.x;
    if (i < MM) { g_hist[i] = 0u; g_avgp[i] = 0.f; }
}

__global__ void k_transp(const float* __restrict__ src, int rows, int cols, int which) {
    __shared__ float s[32][33];
    float* dst = (which == 0) ? g_ET : g_w2T;
    int c0 = blockIdx.x*32, r0 = blockIdx.y*32;
    int tx = threadIdx.x, ty = threadIdx.y;
    #pragma unroll
    for (int j = 0; j < 4; j++) {
        int r = r0 + ty + j*8, c = c0 + tx;
        s[ty + j*8][tx] = (r < rows && c < cols) ? src[(size_t)r*cols + c] : 0.f;
    }
    __syncthreads();
    #pragma unroll
    for (int j = 0; j < 4; j++) {
        int c = c0 + ty + j*8, r = r0 + tx;
        if (c < cols && r < rows) dst[(size_t)c*rows + r] = s[tx][ty + j*8];
    }
}

__global__ void k_esq(const float* __restrict__ E) {
    int warp = threadIdx.x >> 5, lane = threadIdx.x & 31;
    int m = blockIdx.x*8 + warp;
    const float* row = E + (size_t)m*DD;
    float s = 0.f;
    for (int c = lane; c < DD; c += 32) { float v = row[c]; s += v*v; }
    #pragma unroll
    for (int o = 16; o > 0; o >>= 1) s += __shfl_down_sync(0xffffffffu, s, o);
    if (lane == 0) g_esq[m] = s;
}

__global__ void k_split_eb(const float* __restrict__ E) {
    int i = blockIdx.x*256 + threadIdx.x;
    float v = E[i];
    __nv_bfloat16 h = __float2bfloat16(v);
    g_E_bh[i] = h;
    g_E_bl[i] = __float2bfloat16(v - __bfloat162float(h));
}

__global__ void k_splitw(const float* __restrict__ wctx) {
    int idx = blockIdx.x*256 + threadIdx.x;       // grid 1792
    int o = idx / (DD*CTX);
    int rem = idx - o*(DD*CTX);
    int i = rem / CTX, kk = rem - i*CTX;
    float v = wctx[idx];
    float h = tf32_hi(v);
    int ic = i >> 3, il = i & 7;
    int otile = o >> 4, oloc = o & 15;
    int lane = (oloc & 7)*4 + (il & 3);
    int reg = (oloc >> 3) + 2*(il >> 2);
    int d = ((ic*7 + kk)*16 + otile)*128 + lane*4 + reg;
    g_wch[d] = h;
    g_wcl[d] = tf32_hi(v - h);
}

__global__ void k_splitw1(const float* __restrict__ wf1) {
    int idx = blockIdx.x*256 + threadIdx.x;       // grid 512
    int o = idx >> 9, k = idx & 511;
    float v = wf1[idx];
    float h = tf32_hi(v);
    int ks = k >> 3, il = k & 7;
    int otile = o >> 4, oloc = o & 15;
    int lane = (oloc & 7)*4 + (il & 3);
    int reg = (oloc >> 3) + 2*(il >> 2);
    int d = (ks*16 + otile)*128 + lane*4 + reg;
    g_w1shh[d] = h;
    g_w1shl[d] = tf32_hi(v - h);
}

__global__ void k_shufw2(const float* __restrict__ wf2) {
    int idx = blockIdx.x*256 + threadIdx.x;       // grid 256
    int o = idx >> 8, k = idx & 255;
    int ic = k >> 3, il = k & 7;
    int otile = o >> 4, oloc = o & 15;
    int lane = (oloc & 7)*4 + (il & 3);
    int reg = (oloc >> 3) + 2*(il >> 2);
    float v = wf2[o*2*DD + DD + k];
    float h = tf32_hi(v);
    int d = (ic*16 + otile)*128 + lane*4 + reg;
    g_w2shh[d] = h;
    g_w2shl[d] = tf32_hi(v - h);
}

__global__ void k_scale(const float* __restrict__ x, const int* __restrict__ epo_p) {
    int b = blockIdx.x;
    const float* xb = x + (size_t)b*TT*DD;
    float s = 0.f;
    int tot = (TT-1)*DD;
    for (int i = threadIdx.x; i < tot; i += blockDim.x) { float v = xb[i]; s += v*v; }
    __shared__ float sm[8];
    #pragma unroll
    for (int o = 16; o > 0; o >>= 1) s += __shfl_down_sync(0xffffffffu, s, o);
    if ((threadIdx.x & 31) == 0) sm[threadIdx.x >> 5] = s;
    __syncthreads();
    if (threadIdx.x == 0) {
        float t = 0.f;
        for (int w = 0; w < 8; w++) t += sm[w];
        int iv = epo_p[0];
        float ef = (iv >= 0 && iv < 100000) ? (float)iv : __int_as_float(iv);
        float sc = sqrtf(t / (float)(DD*LL));
        g_scale[b] = 0.5f * sc * exp2f(-ef * 0.1f);
    }
}

// x -> xt2 (hi,lo) [b][d][t]
__global__ void k_xt(const float* __restrict__ x) {
    __shared__ float s[32][33];
    int b = blockIdx.z, t0 = blockIdx.x*32, d0 = blockIdx.y*32;
    int tx = threadIdx.x, ty = threadIdx.y;
    #pragma unroll
    for (int j = 0; j < 4; j++) {
        int t = t0 + ty + j*8;
        s[ty + j*8][tx] = x[((size_t)b*TT + t)*DD + d0 + tx];
    }
    __syncthreads();
    #pragma unroll
    for (int j = 0; j < 4; j++) {
        int d = d0 + ty + j*8;
        float v = s[tx][ty + j*8];
        float h = tf32_hi(v);
        g_xt2[((size_t)b*DD + d)*TT + t0 + tx] = make_float2(h, tf32_hi(v - h));
    }
}

__global__ void k_noisy(const float* __restrict__ x, const float* __restrict__ noise) {
    __shared__ float s[32][33];
    int b = blockIdx.z, l0 = blockIdx.x*32, i0 = blockIdx.y*32;
    int tx = threadIdx.x, ty = threadIdx.y;
    float coef = g_scale[b];
    #pragma unroll
    for (int j = 0; j < 4; j++) {
        int row = ty + j*8;
        int t = l0 + row - CTX;
        float v = (t >= 0 && t < TT-1) ? x[((size_t)b*TT + t)*DD + i0 + tx] : 0.f;
        s[row][tx] = v;
    }
    __syncthreads();
    #pragma unroll
    for (int j = 0; j < 4; j++) {
        int i = i0 + ty + j*8, l = l0 + tx;
        if (l < LL) {
            float v = s[tx][ty + j*8] + coef * noise[((size_t)b*DD + i)*LL + l];
            float h = tf32_hi(v);
            g_noisy2[((size_t)b*DD + i)*LLP + l] = make_float2(h, tf32_hi(v - h));
        }
    }
}

// ---------------- conv (3xTF32, interleaved X, materialized W) ---------------
#define CV_STG 9344
#define CV_SMEMB (2*CV_STG*4)

__global__ void __launch_bounds__(256, 2) k_conv_tc() {
    extern __shared__ float cs[];
    int tid = threadIdx.x, lane = tid & 31, warp = tid >> 5;
    int warpM = warp >> 2, warpN = warp & 3;
    int t0 = blockIdx.x*128, o0 = blockIdx.y*64, b = blockIdx.z;
    int ot0 = o0 >> 4;

    uint32_t sbase;
    asm("{ .reg .u64 t; cvta.to.shared.u64 t, %1; cvt.u32.u64 %0, t; }" : "=r"(sbase) : "l"(cs));

    auto issue = [&](int ic, int s) {
        const float2* xp = g_noisy2 + ((size_t)(b*DD + ic*8))*LLP + t0;
        uint32_t xd = sbase + (uint32_t)((s*CV_STG)*4);
        for (int idx = tid; idx < 544; idx += 256) {
            int row = idx / 68, q = idx - row*68;
            asm volatile("cp.async.cg.shared.global [%0], [%1], 16;"
                :: "r"(xd + (uint32_t)((row*136 + q*2)*8)), "l"(xp + (size_t)row*LLP + q*2));
        }
        const float* wh = g_wch + ((size_t)(ic*7)*16 + ot0)*128;
        const float* wl = g_wcl + ((size_t)(ic*7)*16 + ot0)*128;
        uint32_t wdh = sbase + (uint32_t)((s*CV_STG + 2176)*4);
        uint32_t wdl = wdh + 3584*4;
        for (int idx = tid; idx < 896; idx += 256) {
            int kk = idx >> 7, q = idx & 127;
            asm volatile("cp.async.cg.shared.global [%0], [%1], 16;"
                :: "r"(wdh + (uint32_t)((kk*512 + q*4)*4)), "l"(wh + kk*2048 + q*4));
            asm volatile("cp.async.cg.shared.global [%0], [%1], 16;"
                :: "r"(wdl + (uint32_t)((kk*512 + q*4)*4)), "l"(wl + kk*2048 + q*4));
        }
        asm volatile("cp.async.commit_group;");
    };

    float c[2][4][4] = {};
    issue(0, 0);
    issue(1, 1);

    for (int ic = 0; ic < 32; ic++) {
        int s = ic & 1;
        if (ic < 31) { asm volatile("cp.async.wait_group 1;"); }
        else         { asm volatile("cp.async.wait_group 0;"); }
        __syncthreads();
        const float2* X2 = (const float2*)(cs + s*CV_STG);
        const float* WH = cs + s*CV_STG + 2176;
        const float* WL = cs + s*CV_STG + 5760;
        int i0v = lane & 3, trow = lane >> 2;

        #pragma unroll
        for (int kk = 0; kk < 7; kk++) {
            uint32_t ah[2][4], al[2][4];
            #pragma unroll
            for (int mf = 0; mf < 2; mf++) {
                float4 vh = *(const float4*)&WH[kk*512 + (warpM*2 + mf)*128 + lane*4];
                float4 vl = *(const float4*)&WL[kk*512 + (warpM*2 + mf)*128 + lane*4];
                ah[mf][0] = __float_as_uint(vh.x); ah[mf][1] = __float_as_uint(vh.y);
                ah[mf][2] = __float_as_uint(vh.z); ah[mf][3] = __float_as_uint(vh.w);
                al[mf][0] = __float_as_uint(vl.x); al[mf][1] = __float_as_uint(vl.y);
                al[mf][2] = __float_as_uint(vl.z); al[mf][3] = __float_as_uint(vl.w);
            }
            uint32_t bh[4][2], bl[4][2];
            #pragma unroll
            for (int nf = 0; nf < 4; nf++) {
                int toff = warpN*32 + nf*8 + trow + kk;
                float2 v0 = X2[i0v*136 + toff];
                float2 v1 = X2[(i0v + 4)*136 + toff];
                bh[nf][0] = __float_as_uint(v0.x); bl[nf][0] = __float_as_uint(v0.y);
                bh[nf][1] = __float_as_uint(v1.x); bl[nf][1] = __float_as_uint(v1.y);
            }
            #pragma unroll
            for (int mf = 0; mf < 2; mf++) {
                #pragma unroll
                for (int nf = 0; nf < 4; nf++) {
                    MMA8(c[mf][nf], ah[mf][0], ah[mf][1], ah[mf][2], ah[mf][3], bh[nf][0], bh[nf][1]);
                    MMA8(c[mf][nf], ah[mf][0], ah[mf][1], ah[mf][2], ah[mf][3], bl[nf][0], bl[nf][1]);
                    MMA8(c[mf][nf], al[mf][0], al[mf][1], al[mf][2], al[mf][3], bh[nf][0], bh[nf][1]);
                }
            }
        }
        __syncthreads();
        if (ic + 2 < 32) issue(ic + 2, s);
    }

    #pragma unroll
    for (int mf = 0; mf < 2; mf++) {
        int r = o0 + warpM*32 + mf*16 + (lane >> 2);
        #pragma unroll
        for (int nf = 0; nf < 4; nf++) {
            int tg = t0 + warpN*32 + nf*8 + (lane & 3)*2;
            float v0 = c[mf][nf][0], v1 = c[mf][nf][1];
            float v2 = c[mf][nf][2], v3 = c[mf][nf][3];
            float h0 = tf32_hi(v0), h1 = tf32_hi(v1), h2 = tf32_hi(v2), h3 = tf32_hi(v3);
            size_t o1 = ((size_t)b*DD + r)*TT + tg;
            size_t o2 = ((size_t)b*DD + r + 8)*TT + tg;
            *(float4*)&g_ctx2[o1] = make_float4(h0, tf32_hi(v0 - h0), h1, tf32_hi(v1 - h1));
            *(float4*)&g_ctx2[o2] = make_float4(h2, tf32_hi(v2 - h2), h3, tf32_hi(v3 - h3));
        }
    }
}

// ---------------- fuse1 on tensor cores (3xTF32, interleaved X) --------------
#define F1_STG 6400
#define F1_SMEMB (2*F1_STG*4)

__global__ void __launch_bounds__(256, 2) k_f1_tc(const float* __restrict__ a1p) {
    extern __shared__ float fs[];
    int tid = threadIdx.x, lane = tid & 31, warp = tid >> 5;
    int warpM = warp >> 2, warpN = warp & 3;
    int t0 = blockIdx.x*128, o0 = blockIdx.y*64, b = blockIdx.z;
    int ot0 = o0 >> 4;

    uint32_t sbase;
    asm("{ .reg .u64 t; cvta.to.shared.u64 t, %1; cvt.u32.u64 %0, t; }" : "=r"(sbase) : "l"(fs));

    auto issue = [&](int cchunk, int s) {
        uint32_t xd = sbase + (uint32_t)((s*F1_STG)*4);
        #pragma unroll
        for (int j = 0; j < 4; j++) {
            int idx = tid + j*256;
            int row = idx >> 6, q = idx & 63;
            int d = cchunk*16 + row;
            const float2* sp = (d < DD) ? (g_xt2 + ((size_t)b*DD + d)*TT + t0)
                                        : (g_ctx2 + ((size_t)b*DD + d - DD)*TT + t0);
            asm volatile("cp.async.cg.shared.global [%0], [%1], 16;"
                :: "r"(xd + (uint32_t)((row*136 + q*2)*8)), "l"(sp + q*2));
        }
        const float* wh = g_w1shh + ((size_t)(cchunk*2)*16 + ot0)*128;
        const float* wl = g_w1shl + ((size_t)(cchunk*2)*16 + ot0)*128;
        uint32_t wdh = sbase + (uint32_t)((s*F1_STG + 4352)*4);
        uint32_t wdl = wdh + 1024*4;
        {
            int sl8 = tid >> 7, q = tid & 127;
            asm volatile("cp.async.cg.shared.global [%0], [%1], 16;"
                :: "r"(wdh + (uint32_t)(tid*16)), "l"(wh + sl8*2048 + q*4));
            asm volatile("cp.async.cg.shared.global [%0], [%1], 16;"
                :: "r"(wdl + (uint32_t)(tid*16)), "l"(wl + sl8*2048 + q*4));
        }
        asm volatile("cp.async.commit_group;");
    };

    float c[2][4][4] = {};
    issue(0, 0);
    issue(1, 1);

    for (int cc = 0; cc < 32; cc++) {
        int s = cc & 1;
        if (cc < 31) { asm volatile("cp.async.wait_group 1;"); }
        else         { asm volatile("cp.async.wait_group 0;"); }
        __syncthreads();
        const float2* X2 = (const float2*)(fs + s*F1_STG);
        const float* WH = fs + s*F1_STG + 4352;
        const float* WL = fs + s*F1_STG + 5376;
        int i0v = lane & 3, trow = lane >> 2;

        #pragma unroll
        for (int sl8 = 0; sl8 < 2; sl8++) {
            uint32_t ah[2][4], al[2][4];
            #pragma unroll
            for (int mf = 0; mf < 2; mf++) {
                float4 vh = *(const float4*)&WH[sl8*512 + (warpM*2 + mf)*128 + lane*4];
                float4 vl = *(const float4*)&WL[sl8*512 + (warpM*2 + mf)*128 + lane*4];
                ah[mf][0] = __float_as_uint(vh.x); ah[mf][1] = __float_as_uint(vh.y);
                ah[mf][2] = __float_as_uint(vh.z); ah[mf][3] = __float_as_uint(vh.w);
                al[mf][0] = __float_as_uint(vl.x); al[mf][1] = __float_as_uint(vl.y);
                al[mf][2] = __float_as_uint(vl.z); al[mf][3] = __float_as_uint(vl.w);
            }
            uint32_t bh[4][2], bl[4][2];
            #pragma unroll
            for (int nf = 0; nf < 4; nf++) {
                int toff = warpN*32 + nf*8 + trow;
                int rbase = sl8*8 + i0v;
                float2 v0 = X2[rbase*136 + toff];
                float2 v1 = X2[(rbase + 4)*136 + toff];
                bh[nf][0] = __float_as_uint(v0.x); bl[nf][0] = __float_as_uint(v0.y);
                bh[nf][1] = __float_as_uint(v1.x); bl[nf][1] = __float_as_uint(v1.y);
            }
            #pragma unroll
            for (int mf = 0; mf < 2; mf++) {
                #pragma unroll
                for (int nf = 0; nf < 4; nf++) {
                    MMA8(c[mf][nf], ah[mf][0], ah[mf][1], ah[mf][2], ah[mf][3], bh[nf][0], bh[nf][1]);
                    MMA8(c[mf][nf], ah[mf][0], ah[mf][1], ah[mf][2], ah[mf][3], bl[nf][0], bl[nf][1]);
                    MMA8(c[mf][nf], al[mf][0], al[mf][1], al[mf][2], al[mf][3], bh[nf][0], bh[nf][1]);
                }
            }
        }
        __syncthreads();
        if (cc + 2 < 32) issue(cc + 2, s);
    }

    float a1 = *a1p;
    #pragma unroll
    for (int mf = 0; mf < 2; mf++) {
        int r = warpM*32 + mf*16 + (lane >> 2);
        #pragma unroll
        for (int nf = 0; nf < 4; nf++) {
            int tg = warpN*32 + nf*8 + (lane & 3)*2;
            float v0 = c[mf][nf][0]; v0 = (v0 >= 0.f) ? v0 : a1*v0;
            float v1 = c[mf][nf][1]; v1 = (v1 >= 0.f) ? v1 : a1*v1;
            float v2 = c[mf][nf][2]; v2 = (v2 >= 0.f) ? v2 : a1*v2;
            float v3 = c[mf][nf][3]; v3 = (v3 >= 0.f) ? v3 : a1*v3;
            *(float2*)&fs[r*130 + tg]       = make_float2(v0, v1);
            *(float2*)&fs[(r + 8)*130 + tg] = make_float2(v2, v3);
        }
    }
    __syncthreads();
    int nl = tid >> 1, half = tid & 1;
    size_t n = (size_t)b*TT + t0 + nl;
    float* cp = g_cur + n*DD + o0 + half*32;
    __nv_bfloat16* bhp = g_cur_bh + n*DD + o0 + half*32;
    __nv_bfloat16* blp = g_cur_bl + n*DD + o0 + half*32;
    #pragma unroll
    for (int j = 0; j < 8; j++) {
        float4 v;
        v.x = fs[(half*32 + j*4 + 0)*130 + nl];
        v.y = fs[(half*32 + j*4 + 1)*130 + nl];
        v.z = fs[(half*32 + j*4 + 2)*130 + nl];
        v.w = fs[(half*32 + j*4 + 3)*130 + nl];
        *(float4*)&cp[j*4] = v;
        float vv[4] = {v.x, v.y, v.z, v.w};
        __nv_bfloat16 bh4[4], bl4[4];
        #pragma unroll
        for (int q = 0; q < 4; q++) {
            bh4[q] = __float2bfloat16(vv[q]);
            bl4[q] = __float2bfloat16(vv[q] - __bfloat162float(bh4[q]));
        }
        *(uint2*)&bhp[j*4] = *(uint2*)bh4;
        *(uint2*)&blp[j*4] = *(uint2*)bl4;
    }
}

// ---------------- W2E GEMM (small) -------------------------------------------
__global__ void __launch_bounds__(256) k_gemm_w2e() {
    __shared__ float sA[16][68];
    __shared__ float sB[16][68];
    int i0 = blockIdx.x*64, j0 = blockIdx.y*64;
    int tid = threadIdx.x;
    int tx = tid & 15, ty = tid >> 4;
    int kl = tid >> 4, nl4 = (tid & 15)*4;
    float acc[4][4] = {};
    for (int kc = 0; kc < DD; kc += 16) {
        *(float4*)&sA[kl][nl4] = *(const float4*)(g_ET  + (size_t)(kc + kl)*MM + i0 + nl4);
        *(float4*)&sB[kl][nl4] = *(const float4*)(g_w2T + (size_t)(kc + kl)*DD + j0 + nl4);
        __syncthreads();
        #pragma unroll
        for (int k = 0; k < 16; k++) {
            float4 av = *(const float4*)&sA[k][4*tx];
            float4 bv = *(const float4*)&sB[k][4*ty];
            float ar[4] = {av.x, av.y, av.z, av.w};
            float br[4] = {bv.x, bv.y, bv.z, bv.w};
            #pragma unroll
            for (int a = 0; a < 4; a++)
                #pragma unroll
                for (int cc = 0; cc < 4; cc++)
                    acc[a][cc] += br[a] * ar[cc];
        }
        __syncthreads();
    }
    #pragma unroll
    for (int cc = 0; cc < 4; cc++) {
        int i = i0 + 4*tx + cc;
        float4 v = make_float4(acc[0][cc], acc[1][cc], acc[2][cc], acc[3][cc]);
        *(float4*)&g_W2E[(size_t)i*DD + j0 + 4*ty] = v;
    }
}

// ---------------- dist GEMM via mma.sync bf16 (3xBF16, k16) ------------------
#define DB_ROWW 20
#define DB_ARRW (128*DB_ROWW)
#define DB_STGW (4*DB_ARRW)
#define DB_SMEMB (2*DB_STGW*4)

__global__ void __launch_bounds__(256, 2) k_dist_b() {
    extern __shared__ uint32_t dsm[];
    int tid = threadIdx.x, lane = tid & 31, warp = tid >> 5;
    int warpM = warp >> 2, warpN = warp & 3;
    int n0 = blockIdx.x*128, m0 = blockIdx.y*128;

    uint32_t sbase;
    asm("{ .reg .u64 t; cvta.to.shared.u64 t, %1; cvt.u32.u64 %0, t; }" : "=r"(sbase) : "l"(dsm));

    const __nv_bfloat16* srcs[4] = {
        g_cur_bh + (size_t)n0*DD, g_cur_bl + (size_t)n0*DD,
        g_E_bh   + (size_t)m0*DD, g_E_bl   + (size_t)m0*DD };

    auto issue = [&](int kc, int s) {
        #pragma unroll
        for (int a = 0; a < 4; a++) {
            uint32_t dstb = sbase + (uint32_t)((s*DB_STGW + a*DB_ARRW)*4);
            #pragma unroll
            for (int j = 0; j < 2; j++) {
                int cid = tid + j*256;
                int row = cid >> 2, q = cid & 3;
                uint32_t dst = dstb + (uint32_t)(row*80 + q*16);
                const __nv_bfloat16* src = srcs[a] + (size_t)row*DD + kc + q*8;
                asm volatile("cp.async.cg.shared.global [%0], [%1], 16;"
                             :: "r"(dst), "l"(src));
            }
        }
        asm volatile("cp.async.commit_group;");
    };

    float c[4][4][4] = {};
    issue(0, 0);

    int gr = lane >> 2, lc = lane & 3;
    for (int it = 0; it < 8; it++) {
        int s = it & 1;
        if (it + 1 < 8) issue((it + 1)*32, s ^ 1);
        if (it + 1 < 8) { asm volatile("cp.async.wait_group 1;"); }
        else            { asm volatile("cp.async.wait_group 0;"); }
        __syncthreads();

        const uint32_t* sAh = dsm + s*DB_STGW;
        const uint32_t* sAl = sAh + DB_ARRW;
        const uint32_t* sBh = sAh + 2*DB_ARRW;
        const uint32_t* sBl = sAh + 3*DB_ARRW;

        #pragma unroll
        for (int ks = 0; ks < 2; ks++) {
            int wb = ks*8 + lc;
            uint32_t ah[4][4], al[4][4], bh[4][2], bl[4][2];
            #pragma unroll
            for (int mf = 0; mf < 4; mf++) {
                int r1 = (warpM*64 + mf*16 + gr)*DB_ROWW, r2 = r1 + 8*DB_ROWW;
                ah[mf][0] = sAh[r1 + wb];     ah[mf][1] = sAh[r2 + wb];
                ah[mf][2] = sAh[r1 + wb + 4]; ah[mf][3] = sAh[r2 + wb + 4];
                al[mf][0] = sAl[r1 + wb];     al[mf][1] = sAl[r2 + wb];
                al[mf][2] = sAl[r1 + wb + 4]; al[mf][3] = sAl[r2 + wb + 4];
            }
            #pragma unroll
            for (int nf = 0; nf < 4; nf++) {
                int rn = (warpN*32 + nf*8 + gr)*DB_ROWW;
                bh[nf][0] = sBh[rn + wb]; bh[nf][1] = sBh[rn + wb + 4];
                bl[nf][0] = sBl[rn + wb]; bl[nf][1] = sBl[rn + wb + 4];
            }
            #pragma unroll
            for (int mf = 0; mf < 4; mf++) {
                #pragma unroll
                for (int nf = 0; nf < 4; nf++) {
                    MMA16B(c[mf][nf], ah[mf], bh[nf]);
                    MMA16B(c[mf][nf], ah[mf], bl[nf]);
                    MMA16B(c[mf][nf], al[mf], bh[nf]);
                }
            }
        }
        __syncthreads();
    }

    #pragma unroll
    for (int mf = 0; mf < 4; mf++) {
        int r1 = n0 + warpM*64 + mf*16 + gr;
        #pragma unroll
        for (int nf = 0; nf < 4; nf++) {
            int gc = m0 + warpN*32 + nf*8 + lc*2;
            *(float2*)&g_G[(size_t)r1*MM + gc]       = make_float2(c[mf][nf][0], c[mf][nf][1]);
            *(float2*)&g_G[(size_t)(r1 + 8)*MM + gc] = make_float2(c[mf][nf][2], c[mf][nf][3]);
        }
    }
}

// ---------------- per-row stats (8x parallelism: 2048 blocks, 2 rows/warp) ---
__device__ __forceinline__ float gumbel_of(float u) {
    u = fminf(fmaxf(u, 1e-10f), 1.f - 1e-7f);
    return -__logf(-__logf(u));
}

__global__ void __launch_bounds__(256) k_rowstats(const float* __restrict__ gum,
                                                  const float* __restrict__ emb,
                                                  float* __restrict__ out) {
    __shared__ float sAcc[MM];
    int tid = threadIdx.x, wid = tid >> 5, lane = tid & 31;
    for (int i = tid; i < MM; i += 256) sAcc[i] = 0.f;
    __syncthreads();

    float esq_r[8][4];
    #pragma unroll
    for (int ch = 0; ch < 8; ch++) {
        float4 v = *(const float4*)&g_esq[ch*128 + lane*4];
        esq_r[ch][0] = v.x; esq_r[ch][1] = v.y; esq_r[ch][2] = v.z; esq_r[ch][3] = v.w;
    }
    float pAcc[8][4] = {};
    int nbase = blockIdx.x*16 + wid*2;

    #pragma unroll
    for (int r = 0; r < 2; r++) {
        int n = nbase + r;
        const float* Gr = g_G + (size_t)n*MM;
        const float* Ur = gum + (size_t)n*MM;
        float dm[8][4];
        float h1v = -3.4e38f, h2v = -3.4e38f; int h1i = 0x7fffffff, h2i = 0x7fffffff;
        float s1v = -3.4e38f, s2v = -3.4e38f; int s1i = 0x7fffffff, s2i = 0x7fffffff;
        #pragma unroll
        for (int ch = 0; ch < 8; ch++) {
            float4 g4 = *(const float4*)&Gr[ch*128 + lane*4];
            float4 u4 = *(const float4*)&Ur[ch*128 + lane*4];
            float gg[4] = {g4.x, g4.y, g4.z, g4.w};
            float uu[4] = {u4.x, u4.y, u4.z, u4.w};
            #pragma unroll
            for (int j = 0; j < 4; j++) {
                int m = ch*128 + lane*4 + j;
                float d = 2.f*gg[j] - esq_r[ch][j];
                dm[ch][j] = d;
                if (d > h1v || (d == h1v && m < h1i)) { h2v = h1v; h2i = h1i; h1v = d; h1i = m; }
                else if (d > h2v || (d == h2v && m < h2i)) { h2v = d; h2i = m; }
                float sc = d + gumbel_of(uu[j]);
                if (sc > s1v || (sc == s1v && m < s1i)) { s2v = s1v; s2i = s1i; s1v = sc; s1i = m; }
                else if (sc > s2v || (sc == s2v && m < s2i)) { s2v = sc; s2i = m; }
            }
        }
        #pragma unroll
        for (int o = 16; o > 0; o >>= 1) {
            float ov1 = __shfl_xor_sync(0xffffffffu, h1v, o);
            int   oi1 = __shfl_xor_sync(0xffffffffu, h1i, o);
            float ov2 = __shfl_xor_sync(0xffffffffu, h2v, o);
            int   oi2 = __shfl_xor_sync(0xffffffffu, h2i, o);
            if (ov1 > h1v || (ov1 == h1v && oi1 < h1i)) {
                float t1v = h1v; int t1i = h1i;
                h1v = ov1; h1i = oi1;
                if (t1v > ov2 || (t1v == ov2 && t1i < oi2)) { h2v = t1v; h2i = t1i; }
                else { h2v = ov2; h2i = oi2; }
            } else {
                if (ov1 > h2v || (ov1 == h2v && oi1 < h2i)) { h2v = ov1; h2i = oi1; }
            }
            float pv1 = __shfl_xor_sync(0xffffffffu, s1v, o);
            int   pi1 = __shfl_xor_sync(0xffffffffu, s1i, o);
            float pv2 = __shfl_xor_sync(0xffffffffu, s2v, o);
            int   pi2 = __shfl_xor_sync(0xffffffffu, s2i, o);
            if (pv1 > s1v || (pv1 == s1v && pi1 < s1i)) {
                float t1v = s1v; int t1i = s1i;
                s1v = pv1; s1i = pi1;
                if (t1v > pv2 || (t1v == pv2 && t1i < pi2)) { s2v = t1v; s2i = t1i; }
                else { s2v = pv2; s2i = pi2; }
            } else {
                if (pv1 > s2v || (pv1 == s2v && pi1 < s2i)) { s2v = pv1; s2i = pi1; }
            }
        }

        int cands[4] = {h1i, h2i, s1i, s2i};
        float ex[4];
        const float* curp = g_cur + (size_t)n*DD + lane*8;
        #pragma unroll
        for (int t = 0; t < 4; t++) {
            const float* Ep = emb + (size_t)cands[t]*DD + lane*8;
            float s = 0.f;
            #pragma unroll
            for (int j = 0; j < 8; j++) s += curp[j]*Ep[j];
            #pragma unroll
            for (int o = 16; o > 0; o >>= 1) s += __shfl_xor_sync(0xffffffffu, s, o);
            ex[t] = 2.f*s - g_esq[cands[t]];
        }

        float ssum = 0.f;
        #pragma unroll
        for (int ch = 0; ch < 8; ch++)
            #pragma unroll
            for (int j = 0; j < 4; j++) { float e = __expf(dm[ch][j] - h1v); dm[ch][j] = e; ssum += e; }
        #pragma unroll
        for (int o = 16; o > 0; o >>= 1) ssum += __shfl_xor_sync(0xffffffffu, ssum, o);
        float inv = 1.f / ssum;
        #pragma unroll
        for (int ch = 0; ch < 8; ch++)
            #pragma unroll
            for (int j = 0; j < 4; j++) pAcc[ch][j] += dm[ch][j] * inv;

        if (lane == 0) {
            int kH = h1i; float vH = ex[0];
            if (ex[1] > vH || (ex[1] == vH && h2i < kH)) { kH = h2i; vH = ex[1]; }
            atomicAdd(&g_hist[kH], 1u);
            float sc0 = ex[2] + gumbel_of(Ur[s1i]);
            float sc1 = ex[3] + gumbel_of(Ur[s2i]);
            int kS = s1i;
            if (sc1 > sc0 || (sc1 == sc0 && s2i < s1i)) kS = s2i;
            g_idx[n] = kS;
            out[QSIZE + 2 + n] = (float)kS;
        }
    }
    #pragma unroll
    for (int ch = 0; ch < 8; ch++)
        #pragma unroll
        for (int j = 0; j < 4; j++) atomicAdd(&sAcc[ch*128 + lane*4 + j], pAcc[ch][j]);
    __syncthreads();
    for (int i = tid; i < MM; i += 256) atomicAdd(&g_avgp[i], sAcc[i]);
}

__global__ void k_finalize(float* __restrict__ out) {
    __shared__ float s1[MM];
    __shared__ float s2[MM];
    int m = threadIdx.x;
    float hp = (float)g_hist[m] * (1.f/(float)NN);
    float ap = g_avgp[m] * (1.f/(float)NN);
    s1[m] = -hp * log2f(hp + 1e-10f);
    s2[m] = -ap * log2f(ap + 1e-10f);
    __syncthreads();
    for (int s = 512; s > 0; s >>= 1) {
        if (m < s) { s1[m] += s1[m + s]; s2[m] += s2[m + s]; }
        __syncthreads();
    }
    if (m == 0) { out[QSIZE] = s1[0]; out[QSIZE + 1] = s2[0]; }
}

// ---------------- fuse2 (3xTF32, interleaved X, materialized W) --------------
#define F2_STG 3200
#define F2_SMEMB (64*130*4)

__global__ void __launch_bounds__(256) k_f2_tc(const float* __restrict__ a2p,
                                               float* __restrict__ out) {
    extern __shared__ float fs[];
    int tid = threadIdx.x, lane = tid & 31, warp = tid >> 5;
    int warpM = warp >> 2, warpN = warp & 3;
    int t0 = blockIdx.x*128, o0 = blockIdx.y*64, b = blockIdx.z;
    int ot0 = o0 >> 4;

    uint32_t sbase;
    asm("{ .reg .u64 t; cvta.to.shared.u64 t, %1; cvt.u32.u64 %0, t; }" : "=r"(sbase) : "l"(fs));

    auto issue = [&](int ic, int s) {
        uint32_t xd = sbase + (uint32_t)((s*F2_STG)*4);
        #pragma unroll
        for (int j = 0; j < 2; j++) {
            int idx = tid + j*256;
            int row = idx >> 6, q = idx & 63;
            const float2* sp = g_ctx2 + ((size_t)(b*DD + ic*8 + row))*TT + t0;
            asm volatile("cp.async.cg.shared.global [%0], [%1], 16;"
                :: "r"(xd + (uint32_t)((row*136 + q*2)*8)), "l"(sp + q*2));
        }
        if (tid < 128) {
            const float* wp = g_w2shh + ((size_t)ic*16 + ot0)*128;
            uint32_t wd = sbase + (uint32_t)((s*F2_STG + 2176)*4);
            asm volatile("cp.async.cg.shared.global [%0], [%1], 16;"
                :: "r"(wd + (uint32_t)(tid*16)), "l"(wp + tid*4));
        } else {
            int t2 = tid - 128;
            const float* wp = g_w2shl + ((size_t)ic*16 + ot0)*128;
            uint32_t wd = sbase + (uint32_t)((s*F2_STG + 2688)*4);
            asm volatile("cp.async.cg.shared.global [%0], [%1], 16;"
                :: "r"(wd + (uint32_t)(t2*16)), "l"(wp + t2*4));
        }
        asm volatile("cp.async.commit_group;");
    };

    float c[2][4][4] = {};
    issue(0, 0);
    issue(1, 1);

    for (int ic = 0; ic < 32; ic++) {
        int s = ic & 1;
        if (ic < 31) { asm volatile("cp.async.wait_group 1;"); }
        else         { asm volatile("cp.async.wait_group 0;"); }
        __syncthreads();
        const float2* X2 = (const float2*)(fs + s*F2_STG);
        const float* WH = fs + s*F2_STG + 2176;
        const float* WL = fs + s*F2_STG + 2688;
        int i0v = lane & 3, trow = lane >> 2;

        uint32_t ah[2][4], al[2][4];
        #pragma unroll
        for (int mf = 0; mf < 2; mf++) {
            float4 vh = *(const float4*)&WH[(warpM*2 + mf)*128 + lane*4];
            float4 vl = *(const float4*)&WL[(warpM*2 + mf)*128 + lane*4];
            ah[mf][0] = __float_as_uint(vh.x); ah[mf][1] = __float_as_uint(vh.y);
            ah[mf][2] = __float_as_uint(vh.z); ah[mf][3] = __float_as_uint(vh.w);
            al[mf][0] = __float_as_uint(vl.x); al[mf][1] = __float_as_uint(vl.y);
            al[mf][2] = __float_as_uint(vl.z); al[mf][3] = __float_as_uint(vl.w);
        }
        uint32_t bh[4][2], bl[4][2];
        #pragma unroll
        for (int nf = 0; nf < 4; nf++) {
            int toff = warpN*32 + nf*8 + trow;
            float2 v0 = X2[i0v*136 + toff];
            float2 v1 = X2[(i0v + 4)*136 + toff];
            bh[nf][0] = __float_as_uint(v0.x); bl[nf][0] = __float_as_uint(v0.y);
            bh[nf][1] = __float_as_uint(v1.x); bl[nf][1] = __float_as_uint(v1.y);
        }
        #pragma unroll
        for (int mf = 0; mf < 2; mf++) {
            #pragma unroll
            for (int nf = 0; nf < 4; nf++) {
                MMA8(c[mf][nf], ah[mf][0], ah[mf][1], ah[mf][2], ah[mf][3], bh[nf][0], bh[nf][1]);
                MMA8(c[mf][nf], ah[mf][0], ah[mf][1], ah[mf][2], ah[mf][3], bl[nf][0], bl[nf][1]);
                MMA8(c[mf][nf], al[mf][0], al[mf][1], al[mf][2], al[mf][3], bh[nf][0], bh[nf][1]);
            }
        }
        __syncthreads();
        if (ic + 2 < 32) issue(ic + 2, s);
    }

    #pragma unroll
    for (int mf = 0; mf < 2; mf++) {
        int r = warpM*32 + mf*16 + (lane >> 2);
        #pragma unroll
        for (int nf = 0; nf < 4; nf++) {
            int tg = warpN*32 + nf*8 + (lane & 3)*2;
            *(float2*)&fs[r*130 + tg]       = make_float2(c[mf][nf][0], c[mf][nf][1]);
            *(float2*)&fs[(r + 8)*130 + tg] = make_float2(c[mf][nf][2], c[mf][nf][3]);
        }
    }
    __syncthreads();
    float a2v = *a2p;
    int nl = tid >> 1, half = tid & 1;
    size_t n = (size_t)b*TT + t0 + nl;
    int mi = g_idx[n];
    const float* w2e = g_W2E + (size_t)mi*DD + o0 + half*32;
    float* op = out + n*DD + o0 + half*32;
    #pragma unroll
    for (int j = 0; j < 8; j++) {
        float4 w4 = *(const float4*)&w2e[j*4];
        float4 v;
        float u;
        u = fs[(half*32 + j*4 + 0)*130 + nl] + w4.x; v.x = (u >= 0.f) ? u : a2v*u;
        u = fs[(half*32 + j*4 + 1)*130 + nl] + w4.y; v.y = (u >= 0.f) ? u : a2v*u;
        u = fs[(half*32 + j*4 + 2)*130 + nl] + w4.z; v.z = (u >= 0.f) ? u : a2v*u;
        u = fs[(half*32 + j*4 + 3)*130 + nl] + w4.w; v.w = (u >= 0.f) ? u : a2v*u;
        *(float4*)&op[j*4] = v;
    }
}

// ---------------- launch -----------------------------------------------------
extern "C" void kernel_launch(void* const* d_in, const int* in_sizes, int n_in,
                              void* d_out, int out_size) {
    const float* x     = (const float*)d_in[0];
    const float* noise = (const float*)d_in[1];
    const float* gum   = (const float*)d_in[2];
    const int*   epo   = (const int*)  d_in[3];
    const float* emb   = (const float*)d_in[4];
    const float* wctx  = (const float*)d_in[5];
    const float* wf1   = (const float*)d_in[6];
    const float* a1    = (const float*)d_in[7];
    const float* wf2   = (const float*)d_in[8];
    const float* a2    = (const float*)d_in[9];
    float* out = (float*)d_out;

    cudaFuncSetAttribute(k_conv_tc, cudaFuncAttributeMaxDynamicSharedMemorySize, CV_SMEMB);
    cudaFuncSetAttribute(k_f1_tc, cudaFuncAttributeMaxDynamicSharedMemorySize, F1_SMEMB);
    cudaFuncSetAttribute(k_dist_b, cudaFuncAttributeMaxDynamicSharedMemorySize, DB_SMEMB);
    cudaFuncSetAttribute(k_f2_tc, cudaFuncAttributeMaxDynamicSharedMemorySize, F2_SMEMB);

    dim3 tb32(32, 8);

    k_scale<<<BB, 256>>>(x, epo);                                   // 0
    k_noisy<<<dim3((LL + 31)/32, DD/32, BB), tb32>>>(x, noise);     // 1
    k_splitw<<<DD*DD*CTX/256, 256>>>(wctx);                         // 2
    k_conv_tc<<<dim3(TT/128, 4, BB), 256, CV_SMEMB>>>();            // 3 <- capture
    k_xt<<<dim3(TT/32, DD/32, BB), tb32>>>(x);
    k_splitw1<<<2*DD*DD/256, 256>>>(wf1);
    k_f1_tc<<<dim3(TT/128, DD/64, BB), 256, F1_SMEMB>>>(a1);
    k_transp<<<dim3(DD/32, MM/32), tb32>>>(emb, MM, DD, 0);         // ET
    k_transp<<<dim3(2*DD/32, DD/32), tb32>>>(wf2, DD, 2*DD, 1);     // w2T
    k_esq<<<MM/8, 256>>>(emb);
    k_zero<<<4, 256>>>();
    k_split_eb<<<MM*DD/256, 256>>>(emb);
    k_shufw2<<<DD*DD/256, 256>>>(wf2);
    k_gemm_w2e<<<dim3(MM/64, DD/64), 256>>>();
    k_dist_b<<<dim3(NN/128, MM/128), 256, DB_SMEMB>>>();
    k_rowstats<<<NN/16, 256>>>(gum, emb, out);
    k_finalize<<<1, MM>>>(out);
    k_f2_tc<<<dim3(TT/128, DD/64, BB), 256, F2_SMEMB>>>(a2, out);
}